// round 3
// baseline (speedup 1.0000x reference)
#include <cuda_runtime.h>
#include <cuda_bf16.h>
#include <math.h>

// Problem constants
#define BS      2
#define TSEQ    2048
#define DEMBD   1024
#define NHEADS  16
#define DHEAD   64
#define MROWS   (BS * TSEQ)      // 4096
#define KQV_N   (3 * DEMBD)      // 3072

// Scratch (allocation-free rule: __device__ globals)
__device__ float g_kqv[MROWS * KQV_N];   // [4096, 3072]  cols: [K | Q | V]
__device__ float g_att[MROWS * DEMBD];   // [4096, 1024]

// ---------------------------------------------------------------------------
// SGEMM with bias: C[M,N] = A[M,K] @ B[K,N] + bias[N]
// BM=BN=128, BK=8, 256 threads, 8x8 microtile per thread.
// Requires M%128==0, N%128==0, K%8==0 (true for all our shapes).
// ---------------------------------------------------------------------------
__global__ __launch_bounds__(256, 2)
void sgemm_bias_kernel(const float* __restrict__ A, const float* __restrict__ B,
                       const float* __restrict__ bias, float* __restrict__ C,
                       int M, int N, int K) {
    __shared__ float As[8][128];   // [k][m] (transposed)
    __shared__ float Bs[8][128];   // [k][n]

    const int tid  = threadIdx.x;
    const int brow = blockIdx.y;
    const int bcol = blockIdx.x;

    // A tile loader: [128 rows x 8 cols] -> 256 float4s, 1 per thread
    const int aRow = tid >> 1;            // 0..127
    const int aCol = (tid & 1) * 4;       // 0 or 4
    // B tile loader: [8 rows x 128 cols] -> 256 float4s, 1 per thread
    const int bRow = tid >> 5;            // 0..7
    const int bCol = (tid & 31) * 4;      // 0..124

    const float* Ag = A + (size_t)(brow * 128) * K;
    const float* Bg = B + bcol * 128;

    const int tRow = tid >> 4;            // 0..15
    const int tCol = tid & 15;            // 0..15

    float acc[8][8];
#pragma unroll
    for (int i = 0; i < 8; i++)
#pragma unroll
        for (int j = 0; j < 8; j++) acc[i][j] = 0.0f;

    for (int k0 = 0; k0 < K; k0 += 8) {
        float4 av = *(const float4*)(Ag + (size_t)aRow * K + k0 + aCol);
        float4 bv = *(const float4*)(Bg + (size_t)(k0 + bRow) * N + bCol);
        As[aCol + 0][aRow] = av.x;
        As[aCol + 1][aRow] = av.y;
        As[aCol + 2][aRow] = av.z;
        As[aCol + 3][aRow] = av.w;
        *(float4*)&Bs[bRow][bCol] = bv;
        __syncthreads();

#pragma unroll
        for (int k = 0; k < 8; k++) {
            float4 a0 = *(const float4*)&As[k][tRow * 8];
            float4 a1 = *(const float4*)&As[k][tRow * 8 + 4];
            float4 b0 = *(const float4*)&Bs[k][tCol * 8];
            float4 b1 = *(const float4*)&Bs[k][tCol * 8 + 4];
            float ar[8] = {a0.x, a0.y, a0.z, a0.w, a1.x, a1.y, a1.z, a1.w};
            float br[8] = {b0.x, b0.y, b0.z, b0.w, b1.x, b1.y, b1.z, b1.w};
#pragma unroll
            for (int i = 0; i < 8; i++)
#pragma unroll
                for (int j = 0; j < 8; j++)
                    acc[i][j] = fmaf(ar[i], br[j], acc[i][j]);
        }
        __syncthreads();
    }

    // Epilogue: C += bias
    const int colBase = bcol * 128 + tCol * 8;
    float4 bia0 = *(const float4*)(bias + colBase);
    float4 bia1 = *(const float4*)(bias + colBase + 4);
#pragma unroll
    for (int i = 0; i < 8; i++) {
        int row = brow * 128 + tRow * 8 + i;
        float4 c0, c1;
        c0.x = acc[i][0] + bia0.x; c0.y = acc[i][1] + bia0.y;
        c0.z = acc[i][2] + bia0.z; c0.w = acc[i][3] + bia0.w;
        c1.x = acc[i][4] + bia1.x; c1.y = acc[i][5] + bia1.y;
        c1.z = acc[i][6] + bia1.z; c1.w = acc[i][7] + bia1.w;
        *(float4*)(C + (size_t)row * N + colBase)     = c0;
        *(float4*)(C + (size_t)row * N + colBase + 4) = c1;
    }
}

// ---------------------------------------------------------------------------
// Causal flash attention.
// Grid: (TSEQ/64, NHEADS, BS), 256 threads.
// Q tile 64 rows, key tiles of 64. Online softmax, fp32.
// kqv layout per row (3072): [K(0:1024) | Q(1024:2048) | V(2048:3072)],
// head h occupies cols h*64 .. h*64+63 of each chunk.
// Smem: Qs[64][64] row-major; KT[64][64] d-major (reused as P[row][key]);
// Vs[64][64] key-major. 48KB exactly.
// Thread (tRow 0..15, tCol 0..15): rows r_i = tRow + 16*i (i<4),
// cols c_j = tCol*4 + j (j<4). Row stats shared by the 16 threads of a
// tRow group via width-16 butterfly shuffles (lanes (tRow%2)*16 + tCol).
// ---------------------------------------------------------------------------
__global__ __launch_bounds__(256, 2)
void attn_kernel(const float* __restrict__ kqv, float* __restrict__ out) {
    __shared__ float Qs[64 * 64];
    __shared__ float KT[64 * 64];   // [d][key]; later reused as P[row][key]
    __shared__ float Vs[64 * 64];   // [key][d]

    const int tid = threadIdx.x;
    const int qt  = blockIdx.x;
    const int h   = blockIdx.y;
    const int b   = blockIdx.z;
    const int tRow = tid >> 4;
    const int tCol = tid & 15;

    const int qrow0 = b * TSEQ + qt * 64;   // global kqv row of first query

    // Load Q tile (coalesced float4)
#pragma unroll
    for (int p = 0; p < 4; p++) {
        int idx = p * 256 + tid;
        int r = idx >> 4, c4 = (idx & 15) << 2;
        *(float4*)&Qs[r * 64 + c4] =
            *(const float4*)(kqv + (size_t)(qrow0 + r) * KQV_N + DEMBD + h * DHEAD + c4);
    }

    float m_i[4], l_i[4], acc[4][4];
#pragma unroll
    for (int i = 0; i < 4; i++) {
        m_i[i] = -INFINITY; l_i[i] = 0.0f;
#pragma unroll
        for (int j = 0; j < 4; j++) acc[i][j] = 0.0f;
    }

    const float scale = 0.125f;   // 1/sqrt(64)

    for (int kt = 0; kt <= qt; kt++) {
        const int krow0 = b * TSEQ + kt * 64;
        __syncthreads();   // previous iter's KT/Vs reads done before overwrite

        // Load K tile transposed into KT[d][key] (conflict-free stores)
        {
            int key = tid & 63;
            int dg  = (tid >> 6) * 16;
#pragma unroll
            for (int p = 0; p < 4; p++) {
                int d0 = dg + p * 4;
                float4 kv = *(const float4*)(kqv + (size_t)(krow0 + key) * KQV_N + h * DHEAD + d0);
                KT[(d0 + 0) * 64 + key] = kv.x;
                KT[(d0 + 1) * 64 + key] = kv.y;
                KT[(d0 + 2) * 64 + key] = kv.z;
                KT[(d0 + 3) * 64 + key] = kv.w;
            }
        }
        // Load V tile (coalesced)
#pragma unroll
        for (int p = 0; p < 4; p++) {
            int idx = p * 256 + tid;
            int r = idx >> 4, c4 = (idx & 15) << 2;
            *(float4*)&Vs[r * 64 + c4] =
                *(const float4*)(kqv + (size_t)(krow0 + r) * KQV_N + 2 * DEMBD + h * DHEAD + c4);
        }
        __syncthreads();

        // S = Q @ K^T
        float s[4][4];
#pragma unroll
        for (int i = 0; i < 4; i++)
#pragma unroll
            for (int j = 0; j < 4; j++) s[i][j] = 0.0f;
#pragma unroll 8
        for (int kk = 0; kk < 64; kk++) {
            float q[4];
#pragma unroll
            for (int i = 0; i < 4; i++) q[i] = Qs[(tRow + 16 * i) * 64 + kk];
            float4 kv = *(const float4*)&KT[kk * 64 + tCol * 4];
#pragma unroll
            for (int i = 0; i < 4; i++) {
                s[i][0] = fmaf(q[i], kv.x, s[i][0]);
                s[i][1] = fmaf(q[i], kv.y, s[i][1]);
                s[i][2] = fmaf(q[i], kv.z, s[i][2]);
                s[i][3] = fmaf(q[i], kv.w, s[i][3]);
            }
        }

        // scale + causal mask (only the diagonal tile needs masking)
        if (kt == qt) {
#pragma unroll
            for (int i = 0; i < 4; i++) {
                int rowIdx = tRow + 16 * i;
#pragma unroll
                for (int j = 0; j < 4; j++) {
                    int keyIdx = tCol * 4 + j;
                    s[i][j] = (keyIdx > rowIdx) ? -INFINITY : s[i][j] * scale;
                }
            }
        } else {
#pragma unroll
            for (int i = 0; i < 4; i++)
#pragma unroll
                for (int j = 0; j < 4; j++) s[i][j] *= scale;
        }

        // Online softmax update
        float p[4][4];
#pragma unroll
        for (int i = 0; i < 4; i++) {
            float rm = fmaxf(fmaxf(s[i][0], s[i][1]), fmaxf(s[i][2], s[i][3]));
#pragma unroll
            for (int off = 8; off >= 1; off >>= 1)
                rm = fmaxf(rm, __shfl_xor_sync(0xffffffffu, rm, off));
            float mnew = fmaxf(m_i[i], rm);
            float corr = __expf(m_i[i] - mnew);   // exp(-inf)=0 on first tile
            m_i[i] = mnew;
            float rs = 0.0f;
#pragma unroll
            for (int j = 0; j < 4; j++) {
                p[i][j] = __expf(s[i][j] - mnew);
                rs += p[i][j];
            }
#pragma unroll
            for (int off = 8; off >= 1; off >>= 1)
                rs += __shfl_xor_sync(0xffffffffu, rs, off);
            l_i[i] = l_i[i] * corr + rs;
#pragma unroll
            for (int j = 0; j < 4; j++) acc[i][j] *= corr;
        }

        // Write P into the KT buffer (all S reads of KT are done after sync)
        __syncthreads();
#pragma unroll
        for (int i = 0; i < 4; i++) {
            float4 pv = make_float4(p[i][0], p[i][1], p[i][2], p[i][3]);
            *(float4*)&KT[(tRow + 16 * i) * 64 + tCol * 4] = pv;
        }
        __syncthreads();

        // acc += P @ V
#pragma unroll 8
        for (int kk = 0; kk < 64; kk++) {
            float pr[4];
#pragma unroll
            for (int i = 0; i < 4; i++) pr[i] = KT[(tRow + 16 * i) * 64 + kk];
            float4 vv = *(const float4*)&Vs[kk * 64 + tCol * 4];
#pragma unroll
            for (int i = 0; i < 4; i++) {
                acc[i][0] = fmaf(pr[i], vv.x, acc[i][0]);
                acc[i][1] = fmaf(pr[i], vv.y, acc[i][1]);
                acc[i][2] = fmaf(pr[i], vv.z, acc[i][2]);
                acc[i][3] = fmaf(pr[i], vv.w, acc[i][3]);
            }
        }
    }

    // Epilogue: out[b, t, h*64 + d] = acc / l
#pragma unroll
    for (int i = 0; i < 4; i++) {
        int row = qrow0 + tRow + 16 * i;
        float inv = 1.0f / l_i[i];
        float4 o = make_float4(acc[i][0] * inv, acc[i][1] * inv,
                               acc[i][2] * inv, acc[i][3] * inv);
        *(float4*)(out + (size_t)row * DEMBD + h * DHEAD + tCol * 4) = o;
    }
}

// ---------------------------------------------------------------------------
extern "C" void kernel_launch(void* const* d_in, const int* in_sizes, int n_in,
                              void* d_out, int out_size) {
    const float* x  = (const float*)d_in[0];
    const float* W1 = (const float*)d_in[1];
    const float* b1 = (const float*)d_in[2];
    const float* W2 = (const float*)d_in[3];
    const float* b2 = (const float*)d_in[4];
    float* out = (float*)d_out;

    float* kqv = nullptr;
    float* att = nullptr;
    cudaGetSymbolAddress((void**)&kqv, g_kqv);
    cudaGetSymbolAddress((void**)&att, g_att);

    // 1) kqv = x @ W1 + b1   [4096,1024]@[1024,3072]
    {
        dim3 grid(KQV_N / 128, MROWS / 128);
        sgemm_bias_kernel<<<grid, 256>>>(x, W1, b1, kqv, MROWS, KQV_N, DEMBD);
    }
    // 2) causal multi-head attention
    {
        dim3 grid(TSEQ / 64, NHEADS, BS);
        attn_kernel<<<grid, 256>>>(kqv, att);
    }
    // 3) out = att @ W2 + b2  [4096,1024]@[1024,1024]
    {
        dim3 grid(DEMBD / 128, MROWS / 128);
        sgemm_bias_kernel<<<grid, 256>>>(att, W2, b2, out, MROWS, DEMBD, DEMBD);
    }
}

// round 5
// speedup vs baseline: 1.4527x; 1.4527x over previous
#include <cuda_runtime.h>
#include <cuda_bf16.h>
#include <math.h>
#include <stdint.h>

// Problem constants
#define BS      2
#define TSEQ    2048
#define DEMBD   1024
#define NHEADS  16
#define DHEAD   64
#define MROWS   (BS * TSEQ)      // 4096
#define KQV_N   (3 * DEMBD)      // 3072

// ---------------------------------------------------------------------------
// Scratch (__device__ globals; allocation-free rule)
// ---------------------------------------------------------------------------
__device__ float g_kqv[MROWS * KQV_N];   // [4096, 3072]  cols: [K | Q | V]
__device__ float g_att[MROWS * DEMBD];   // [4096, 1024]

__device__ __nv_bfloat16 g_A1hi[MROWS * DEMBD];
__device__ __nv_bfloat16 g_A1lo[MROWS * DEMBD];
__device__ __nv_bfloat16 g_A2hi[MROWS * DEMBD];
__device__ __nv_bfloat16 g_A2lo[MROWS * DEMBD];
__device__ __nv_bfloat16 g_W1Thi[KQV_N * DEMBD];   // [3072][1024]  (W1^T, K-contig)
__device__ __nv_bfloat16 g_W1Tlo[KQV_N * DEMBD];
__device__ __nv_bfloat16 g_W2Thi[DEMBD * DEMBD];   // [1024][1024]
__device__ __nv_bfloat16 g_W2Tlo[DEMBD * DEMBD];

// ---------------------------------------------------------------------------
// PTX helpers (baseline ISA only — no sm_103a-specific features)
// ---------------------------------------------------------------------------
__device__ __forceinline__ uint32_t smem_u32(const void* p) {
    uint32_t a;
    asm("{ .reg .u64 t; cvta.to.shared.u64 t, %1; cvt.u32.u64 %0, t; }" : "=r"(a) : "l"(p));
    return a;
}
__device__ __forceinline__ void cp16(uint32_t dst, const void* src) {
    asm volatile("cp.async.cg.shared.global [%0], [%1], 16;"
                 :: "r"(dst), "l"(__cvta_generic_to_global(src)));
}
__device__ __forceinline__ void cp_commit() { asm volatile("cp.async.commit_group;" ::: "memory"); }

#define LDSM4(r, addr) \
    asm volatile("ldmatrix.sync.aligned.m8n8.x4.shared.b16 {%0,%1,%2,%3}, [%4];" \
        : "=r"((r)[0]), "=r"((r)[1]), "=r"((r)[2]), "=r"((r)[3]) : "r"(addr))

#define MMA_BF16(d, a, b0, b1) \
    asm volatile("mma.sync.aligned.m16n8k16.row.col.f32.bf16.bf16.f32 " \
        "{%0,%1,%2,%3}, {%4,%5,%6,%7}, {%8,%9}, {%0,%1,%2,%3};" \
        : "+f"((d)[0]), "+f"((d)[1]), "+f"((d)[2]), "+f"((d)[3]) \
        : "r"((a)[0]), "r"((a)[1]), "r"((a)[2]), "r"((a)[3]), "r"(b0), "r"(b1))

// ---------------------------------------------------------------------------
// fp32 -> bf16 hi/lo split (elementwise, float4)
// ---------------------------------------------------------------------------
__global__ void split_f32(const float* __restrict__ in, __nv_bfloat16* __restrict__ hi,
                          __nv_bfloat16* __restrict__ lo, int n4) {
    int i = blockIdx.x * blockDim.x + threadIdx.x;
    if (i >= n4) return;
    float4 v = ((const float4*)in)[i];
    __nv_bfloat16 h0 = __float2bfloat16(v.x), h1 = __float2bfloat16(v.y);
    __nv_bfloat16 h2 = __float2bfloat16(v.z), h3 = __float2bfloat16(v.w);
    __nv_bfloat16 l0 = __float2bfloat16(v.x - __bfloat162float(h0));
    __nv_bfloat16 l1 = __float2bfloat16(v.y - __bfloat162float(h1));
    __nv_bfloat16 l2 = __float2bfloat16(v.z - __bfloat162float(h2));
    __nv_bfloat16 l3 = __float2bfloat16(v.w - __bfloat162float(h3));
    ((__nv_bfloat162*)hi)[i * 2 + 0] = __nv_bfloat162(h0, h1);
    ((__nv_bfloat162*)hi)[i * 2 + 1] = __nv_bfloat162(h2, h3);
    ((__nv_bfloat162*)lo)[i * 2 + 0] = __nv_bfloat162(l0, l1);
    ((__nv_bfloat162*)lo)[i * 2 + 1] = __nv_bfloat162(l2, l3);
}

// ---------------------------------------------------------------------------
// W[K][N] fp32 -> W^T[N][K] bf16 hi/lo (tiled transpose)
// ---------------------------------------------------------------------------
__global__ void transpose_split(const float* __restrict__ W, __nv_bfloat16* __restrict__ hiT,
                                __nv_bfloat16* __restrict__ loT, int K, int N) {
    __shared__ float t[32][33];
    int n = blockIdx.x * 32 + threadIdx.x;
    int k0 = blockIdx.y * 32;
#pragma unroll
    for (int i = 0; i < 32; i += 8)
        t[threadIdx.y + i][threadIdx.x] = W[(size_t)(k0 + threadIdx.y + i) * N + n];
    __syncthreads();
    int kk = k0 + threadIdx.x;
#pragma unroll
    for (int i = 0; i < 32; i += 8) {
        int nn = blockIdx.x * 32 + threadIdx.y + i;
        float v = t[threadIdx.x][threadIdx.y + i];
        __nv_bfloat16 h = __float2bfloat16(v);
        __nv_bfloat16 l = __float2bfloat16(v - __bfloat162float(h));
        hiT[(size_t)nn * K + kk] = h;
        loT[(size_t)nn * K + kk] = l;
    }
}

// ---------------------------------------------------------------------------
// bf16 hi/lo tensor-core GEMM (mma.sync.m16n8k16):
//   C[M,N] = A[M,K] x B^T[N,K] + bias[N], fp32 accumulate
// CTA: 128x128 tile, 256 threads (8 warps, 2x4 grid, warp tile 64x32).
// BK=32 K-slabs, double-buffered cp.async (wait_group 1 pipelining).
// Smem rows padded to 40 halves (80 B) for conflict-free ldmatrix.
// ---------------------------------------------------------------------------
#define BK        32
#define LDS_ROW   40                       // 32 data + 8 pad halves
#define TILE_H    (128 * LDS_ROW)          // halves per 128xBK tile
#define TILE_B    (TILE_H * 2)             // 10240 bytes
#define STAGE_B   (4 * TILE_B)             // Ah, Al, Bh, Bl
#define GEMM_SMEM (2 * STAGE_B)            // 81920 bytes

// one 128xBK tile: 128 rows x 4 chunks of 16B; 512 chunks / 256 thr = 2 each
__device__ __forceinline__ void load_tile(uint32_t tb, const __nv_bfloat16* sp, int K, int tid) {
#pragma unroll
    for (int i = 0; i < 2; i++) {
        int chunk = tid + i * 256;
        int row = chunk >> 2, cb = chunk & 3;
        cp16(tb + (uint32_t)row * (LDS_ROW * 2) + (uint32_t)cb * 16,
             sp + (size_t)row * K + cb * 8);
    }
}

__global__ __launch_bounds__(256)
void gemm_bf16_mma(const __nv_bfloat16* __restrict__ Ah, const __nv_bfloat16* __restrict__ Al,
                   const __nv_bfloat16* __restrict__ Bh, const __nv_bfloat16* __restrict__ Bl,
                   const float* __restrict__ bias, float* __restrict__ C,
                   int M, int N, int K) {
    extern __shared__ char smem[];
    const uint32_t sbase = smem_u32(smem);

    const int tid  = threadIdx.x;
    const int wid  = tid >> 5;
    const int lane = tid & 31;
    const int m0 = blockIdx.y * 128;
    const int n0 = blockIdx.x * 128;
    const int wm = (wid & 1) * 64;         // warp M offset in tile
    const int wn = (wid >> 1) * 32;        // warp N offset in tile
    const int NSLAB = K / BK;

    const __nv_bfloat16* Ah0 = Ah + (size_t)m0 * K;
    const __nv_bfloat16* Al0 = Al + (size_t)m0 * K;
    const __nv_bfloat16* Bh0 = Bh + (size_t)n0 * K;
    const __nv_bfloat16* Bl0 = Bl + (size_t)n0 * K;

    // Per-lane ldmatrix base offsets (in halves, within a tile)
    const int aOff = (wm + (lane & 15)) * LDS_ROW + (lane >> 4) * 8;
    const int bOff = (wn + (lane & 7) + ((lane >> 4) << 3)) * LDS_ROW + (((lane >> 3) & 1) << 3);

    float acc[4][4][4];
#pragma unroll
    for (int mb = 0; mb < 4; mb++)
#pragma unroll
        for (int nb = 0; nb < 4; nb++)
#pragma unroll
            for (int r = 0; r < 4; r++) acc[mb][nb][r] = 0.0f;

    // Prologue: slab 0 -> stage 0
    {
        const uint32_t st = sbase;
        load_tile(st + 0 * TILE_B, Ah0, K, tid);
        load_tile(st + 1 * TILE_B, Al0, K, tid);
        load_tile(st + 2 * TILE_B, Bh0, K, tid);
        load_tile(st + 3 * TILE_B, Bl0, K, tid);
        cp_commit();
    }

    for (int s = 0; s < NSLAB; s++) {
        if (s + 1 < NSLAB) {
            const uint32_t st = sbase + ((s + 1) & 1) * STAGE_B;
            const int k0 = (s + 1) * BK;
            load_tile(st + 0 * TILE_B, Ah0 + k0, K, tid);
            load_tile(st + 1 * TILE_B, Al0 + k0, K, tid);
            load_tile(st + 2 * TILE_B, Bh0 + k0, K, tid);
            load_tile(st + 3 * TILE_B, Bl0 + k0, K, tid);
            cp_commit();
            asm volatile("cp.async.wait_group 1;" ::: "memory");
        } else {
            asm volatile("cp.async.wait_group 0;" ::: "memory");
        }
        __syncthreads();

        const uint32_t st = sbase + (s & 1) * STAGE_B;
        const uint32_t ahb = st + 0 * TILE_B + (uint32_t)aOff * 2;
        const uint32_t alb = st + 1 * TILE_B + (uint32_t)aOff * 2;
        const uint32_t bhb = st + 2 * TILE_B + (uint32_t)bOff * 2;
        const uint32_t blb = st + 3 * TILE_B + (uint32_t)bOff * 2;

#pragma unroll
        for (int kk = 0; kk < BK; kk += 16) {
            uint32_t ah[4][4], al[4][4], bh[2][4], bl[2][4];
#pragma unroll
            for (int mb = 0; mb < 4; mb++) {
                LDSM4(ah[mb], ahb + (mb * 16 * LDS_ROW + kk) * 2);
                LDSM4(al[mb], alb + (mb * 16 * LDS_ROW + kk) * 2);
            }
#pragma unroll
            for (int g = 0; g < 2; g++) {
                LDSM4(bh[g], bhb + (g * 16 * LDS_ROW + kk) * 2);
                LDSM4(bl[g], blb + (g * 16 * LDS_ROW + kk) * 2);
            }
#pragma unroll
            for (int mb = 0; mb < 4; mb++)
#pragma unroll
                for (int nb = 0; nb < 4; nb++) {
                    const int g = nb >> 1, h2 = (nb & 1) * 2;
                    MMA_BF16(acc[mb][nb], ah[mb], bh[g][h2], bh[g][h2 + 1]);
                    MMA_BF16(acc[mb][nb], ah[mb], bl[g][h2], bl[g][h2 + 1]);
                    MMA_BF16(acc[mb][nb], al[mb], bh[g][h2], bh[g][h2 + 1]);
                }
        }
        __syncthreads();
    }

    // Epilogue: direct fp32 stores + bias
    const int rBase = m0 + wm + (lane >> 2);
    const int cBase = n0 + wn + (lane & 3) * 2;
#pragma unroll
    for (int mb = 0; mb < 4; mb++) {
#pragma unroll
        for (int nb = 0; nb < 4; nb++) {
            const int col = cBase + nb * 8;
            const float bx = __ldg(bias + col);
            const float by = __ldg(bias + col + 1);
            float* p0 = C + (size_t)(rBase + mb * 16) * N + col;
            float* p1 = C + (size_t)(rBase + mb * 16 + 8) * N + col;
            float2 v0 = make_float2(acc[mb][nb][0] + bx, acc[mb][nb][1] + by);
            float2 v1 = make_float2(acc[mb][nb][2] + bx, acc[mb][nb][3] + by);
            *(float2*)p0 = v0;
            *(float2*)p1 = v1;
        }
    }
}

// ---------------------------------------------------------------------------
// Causal flash attention (fp32 SIMT — unchanged from R3)
// ---------------------------------------------------------------------------
__global__ __launch_bounds__(256, 2)
void attn_kernel(const float* __restrict__ kqv, float* __restrict__ out) {
    __shared__ float Qs[64 * 64];
    __shared__ float KT[64 * 64];
    __shared__ float Vs[64 * 64];

    const int tid = threadIdx.x;
    const int qt  = blockIdx.x;
    const int h   = blockIdx.y;
    const int b   = blockIdx.z;
    const int tRow = tid >> 4;
    const int tCol = tid & 15;

    const int qrow0 = b * TSEQ + qt * 64;

#pragma unroll
    for (int p = 0; p < 4; p++) {
        int idx = p * 256 + tid;
        int r = idx >> 4, c4 = (idx & 15) << 2;
        *(float4*)&Qs[r * 64 + c4] =
            *(const float4*)(kqv + (size_t)(qrow0 + r) * KQV_N + DEMBD + h * DHEAD + c4);
    }

    float m_i[4], l_i[4], acc[4][4];
#pragma unroll
    for (int i = 0; i < 4; i++) {
        m_i[i] = -INFINITY; l_i[i] = 0.0f;
#pragma unroll
        for (int j = 0; j < 4; j++) acc[i][j] = 0.0f;
    }

    const float scale = 0.125f;

    for (int kt = 0; kt <= qt; kt++) {
        const int krow0 = b * TSEQ + kt * 64;
        __syncthreads();

        {
            int key = tid & 63;
            int dg  = (tid >> 6) * 16;
#pragma unroll
            for (int p = 0; p < 4; p++) {
                int d0 = dg + p * 4;
                float4 kv = *(const float4*)(kqv + (size_t)(krow0 + key) * KQV_N + h * DHEAD + d0);
                KT[(d0 + 0) * 64 + key] = kv.x;
                KT[(d0 + 1) * 64 + key] = kv.y;
                KT[(d0 + 2) * 64 + key] = kv.z;
                KT[(d0 + 3) * 64 + key] = kv.w;
            }
        }
#pragma unroll
        for (int p = 0; p < 4; p++) {
            int idx = p * 256 + tid;
            int r = idx >> 4, c4 = (idx & 15) << 2;
            *(float4*)&Vs[r * 64 + c4] =
                *(const float4*)(kqv + (size_t)(krow0 + r) * KQV_N + 2 * DEMBD + h * DHEAD + c4);
        }
        __syncthreads();

        float s[4][4];
#pragma unroll
        for (int i = 0; i < 4; i++)
#pragma unroll
            for (int j = 0; j < 4; j++) s[i][j] = 0.0f;
#pragma unroll 8
        for (int kk = 0; kk < 64; kk++) {
            float q[4];
#pragma unroll
            for (int i = 0; i < 4; i++) q[i] = Qs[(tRow + 16 * i) * 64 + kk];
            float4 kv = *(const float4*)&KT[kk * 64 + tCol * 4];
#pragma unroll
            for (int i = 0; i < 4; i++) {
                s[i][0] = fmaf(q[i], kv.x, s[i][0]);
                s[i][1] = fmaf(q[i], kv.y, s[i][1]);
                s[i][2] = fmaf(q[i], kv.z, s[i][2]);
                s[i][3] = fmaf(q[i], kv.w, s[i][3]);
            }
        }

        if (kt == qt) {
#pragma unroll
            for (int i = 0; i < 4; i++) {
                int rowIdx = tRow + 16 * i;
#pragma unroll
                for (int j = 0; j < 4; j++) {
                    int keyIdx = tCol * 4 + j;
                    s[i][j] = (keyIdx > rowIdx) ? -INFINITY : s[i][j] * scale;
                }
            }
        } else {
#pragma unroll
            for (int i = 0; i < 4; i++)
#pragma unroll
                for (int j = 0; j < 4; j++) s[i][j] *= scale;
        }

        float p[4][4];
#pragma unroll
        for (int i = 0; i < 4; i++) {
            float rm = fmaxf(fmaxf(s[i][0], s[i][1]), fmaxf(s[i][2], s[i][3]));
#pragma unroll
            for (int off = 8; off >= 1; off >>= 1)
                rm = fmaxf(rm, __shfl_xor_sync(0xffffffffu, rm, off));
            float mnew = fmaxf(m_i[i], rm);
            float corr = __expf(m_i[i] - mnew);
            m_i[i] = mnew;
            float rs = 0.0f;
#pragma unroll
            for (int j = 0; j < 4; j++) {
                p[i][j] = __expf(s[i][j] - mnew);
                rs += p[i][j];
            }
#pragma unroll
            for (int off = 8; off >= 1; off >>= 1)
                rs += __shfl_xor_sync(0xffffffffu, rs, off);
            l_i[i] = l_i[i] * corr + rs;
#pragma unroll
            for (int j = 0; j < 4; j++) acc[i][j] *= corr;
        }

        __syncthreads();
#pragma unroll
        for (int i = 0; i < 4; i++) {
            float4 pv = make_float4(p[i][0], p[i][1], p[i][2], p[i][3]);
            *(float4*)&KT[(tRow + 16 * i) * 64 + tCol * 4] = pv;
        }
        __syncthreads();

#pragma unroll 8
        for (int kk = 0; kk < 64; kk++) {
            float pr[4];
#pragma unroll
            for (int i = 0; i < 4; i++) pr[i] = KT[(tRow + 16 * i) * 64 + kk];
            float4 vv = *(const float4*)&Vs[kk * 64 + tCol * 4];
#pragma unroll
            for (int i = 0; i < 4; i++) {
                acc[i][0] = fmaf(pr[i], vv.x, acc[i][0]);
                acc[i][1] = fmaf(pr[i], vv.y, acc[i][1]);
                acc[i][2] = fmaf(pr[i], vv.z, acc[i][2]);
                acc[i][3] = fmaf(pr[i], vv.w, acc[i][3]);
            }
        }
    }

#pragma unroll
    for (int i = 0; i < 4; i++) {
        int row = qrow0 + tRow + 16 * i;
        float inv = 1.0f / l_i[i];
        float4 o = make_float4(acc[i][0] * inv, acc[i][1] * inv,
                               acc[i][2] * inv, acc[i][3] * inv);
        *(float4*)(out + (size_t)row * DEMBD + h * DHEAD + tCol * 4) = o;
    }
}

// ---------------------------------------------------------------------------
extern "C" void kernel_launch(void* const* d_in, const int* in_sizes, int n_in,
                              void* d_out, int out_size) {
    const float* x  = (const float*)d_in[0];
    const float* W1 = (const float*)d_in[1];
    const float* b1 = (const float*)d_in[2];
    const float* W2 = (const float*)d_in[3];
    const float* b2 = (const float*)d_in[4];
    float* out = (float*)d_out;

    float *kqv, *att;
    __nv_bfloat16 *A1h, *A1l, *A2h, *A2l, *W1h, *W1l, *W2h, *W2l;
    cudaGetSymbolAddress((void**)&kqv, g_kqv);
    cudaGetSymbolAddress((void**)&att, g_att);
    cudaGetSymbolAddress((void**)&A1h, g_A1hi);
    cudaGetSymbolAddress((void**)&A1l, g_A1lo);
    cudaGetSymbolAddress((void**)&A2h, g_A2hi);
    cudaGetSymbolAddress((void**)&A2l, g_A2lo);
    cudaGetSymbolAddress((void**)&W1h, g_W1Thi);
    cudaGetSymbolAddress((void**)&W1l, g_W1Tlo);
    cudaGetSymbolAddress((void**)&W2h, g_W2Thi);
    cudaGetSymbolAddress((void**)&W2l, g_W2Tlo);

    cudaFuncSetAttribute(gemm_bf16_mma, cudaFuncAttributeMaxDynamicSharedMemorySize, GEMM_SMEM);

    // 0) input conversions
    {
        int n4 = MROWS * DEMBD / 4;
        split_f32<<<(n4 + 255) / 256, 256>>>(x, A1h, A1l, n4);
        transpose_split<<<dim3(KQV_N / 32, DEMBD / 32), dim3(32, 8)>>>(W1, W1h, W1l, DEMBD, KQV_N);
        transpose_split<<<dim3(DEMBD / 32, DEMBD / 32), dim3(32, 8)>>>(W2, W2h, W2l, DEMBD, DEMBD);
    }
    // 1) kqv = x @ W1 + b1  (tensor cores)
    gemm_bf16_mma<<<dim3(KQV_N / 128, MROWS / 128), 256, GEMM_SMEM>>>(
        A1h, A1l, W1h, W1l, b1, kqv, MROWS, KQV_N, DEMBD);
    // 2) causal multi-head attention (fp32)
    attn_kernel<<<dim3(TSEQ / 64, NHEADS, BS), 256>>>(kqv, att);
    // 3) out = att @ W2 + b2  (tensor cores)
    {
        int n4 = MROWS * DEMBD / 4;
        split_f32<<<(n4 + 255) / 256, 256>>>(att, A2h, A2l, n4);
    }
    gemm_bf16_mma<<<dim3(DEMBD / 128, MROWS / 128), 256, GEMM_SMEM>>>(
        A2h, A2l, W2h, W2l, b2, out, MROWS, DEMBD, DEMBD);
}

// round 6
// speedup vs baseline: 2.3702x; 1.6316x over previous
#include <cuda_runtime.h>
#include <cuda_bf16.h>
#include <math.h>
#include <stdint.h>

// Problem constants
#define BS      2
#define TSEQ    2048
#define DEMBD   1024
#define NHEADS  16
#define DHEAD   64
#define MROWS   (BS * TSEQ)      // 4096
#define KQV_N   (3 * DEMBD)      // 3072
#define BH      (BS * NHEADS)    // 32

// ---------------------------------------------------------------------------
// Scratch (__device__ globals; allocation-free rule)
// ---------------------------------------------------------------------------
__device__ float g_kqv[MROWS * KQV_N];   // [4096, 3072]  cols: [K | Q | V]

__device__ __nv_bfloat16 g_A1hi[MROWS * DEMBD];
__device__ __nv_bfloat16 g_A1lo[MROWS * DEMBD];
__device__ __nv_bfloat16 g_A2hi[MROWS * DEMBD];   // written by attention
__device__ __nv_bfloat16 g_A2lo[MROWS * DEMBD];
__device__ __nv_bfloat16 g_W1Thi[KQV_N * DEMBD];
__device__ __nv_bfloat16 g_W1Tlo[KQV_N * DEMBD];
__device__ __nv_bfloat16 g_W2Thi[DEMBD * DEMBD];
__device__ __nv_bfloat16 g_W2Tlo[DEMBD * DEMBD];

// Attention operands, per-head layouts (bf16 hi/lo)
__device__ __nv_bfloat16 g_Qhi[BH * TSEQ * DHEAD];  // [bh][t][d], pre-scaled
__device__ __nv_bfloat16 g_Qlo[BH * TSEQ * DHEAD];
__device__ __nv_bfloat16 g_Khi[BH * TSEQ * DHEAD];  // [bh][t][d]
__device__ __nv_bfloat16 g_Klo[BH * TSEQ * DHEAD];
__device__ __nv_bfloat16 g_Vthi[BH * DHEAD * TSEQ]; // [bh][d][t]  (transposed)
__device__ __nv_bfloat16 g_Vtlo[BH * DHEAD * TSEQ];

// ---------------------------------------------------------------------------
// PTX helpers (baseline ISA only)
// ---------------------------------------------------------------------------
__device__ __forceinline__ uint32_t smem_u32(const void* p) {
    uint32_t a;
    asm("{ .reg .u64 t; cvta.to.shared.u64 t, %1; cvt.u32.u64 %0, t; }" : "=r"(a) : "l"(p));
    return a;
}
__device__ __forceinline__ void cp16(uint32_t dst, const void* src) {
    asm volatile("cp.async.cg.shared.global [%0], [%1], 16;"
                 :: "r"(dst), "l"(__cvta_generic_to_global(src)));
}
__device__ __forceinline__ void cp_commit() { asm volatile("cp.async.commit_group;" ::: "memory"); }

#define LDSM4(r, addr) \
    asm volatile("ldmatrix.sync.aligned.m8n8.x4.shared.b16 {%0,%1,%2,%3}, [%4];" \
        : "=r"((r)[0]), "=r"((r)[1]), "=r"((r)[2]), "=r"((r)[3]) : "r"(addr))

#define MMA_BF16(d, a, b0, b1) \
    asm volatile("mma.sync.aligned.m16n8k16.row.col.f32.bf16.bf16.f32 " \
        "{%0,%1,%2,%3}, {%4,%5,%6,%7}, {%8,%9}, {%0,%1,%2,%3};" \
        : "+f"((d)[0]), "+f"((d)[1]), "+f"((d)[2]), "+f"((d)[3]) \
        : "r"((a)[0]), "r"((a)[1]), "r"((a)[2]), "r"((a)[3]), "r"(b0), "r"(b1))

// pack two fp32 into bf16x2: low half <- lo, high half <- hi
__device__ __forceinline__ uint32_t packbf2(float lo, float hi) {
    uint32_t r;
    asm("cvt.rn.bf16x2.f32 %0, %1, %2;" : "=r"(r) : "f"(hi), "f"(lo));
    return r;
}
// residual (lo-part) pack given the hi-pack
__device__ __forceinline__ uint32_t packlo2(float lo, float hi, uint32_t hp) {
    __nv_bfloat162 hv = *reinterpret_cast<__nv_bfloat162*>(&hp);
    return packbf2(lo - __bfloat162float(hv.x), hi - __bfloat162float(hv.y));
}

// ---------------------------------------------------------------------------
// fp32 -> bf16 hi/lo split (elementwise, float4)  [x -> A1]
// ---------------------------------------------------------------------------
__global__ void split_f32(const float* __restrict__ in, __nv_bfloat16* __restrict__ hi,
                          __nv_bfloat16* __restrict__ lo, int n4) {
    int i = blockIdx.x * blockDim.x + threadIdx.x;
    if (i >= n4) return;
    float4 v = ((const float4*)in)[i];
    uint32_t h0 = packbf2(v.x, v.y), h1 = packbf2(v.z, v.w);
    uint32_t l0 = packlo2(v.x, v.y, h0), l1 = packlo2(v.z, v.w, h1);
    ((uint32_t*)hi)[i * 2 + 0] = h0;
    ((uint32_t*)hi)[i * 2 + 1] = h1;
    ((uint32_t*)lo)[i * 2 + 0] = l0;
    ((uint32_t*)lo)[i * 2 + 1] = l1;
}

// ---------------------------------------------------------------------------
// W[K][N] fp32 -> W^T[N][K] bf16 hi/lo (tiled transpose)
// ---------------------------------------------------------------------------
__global__ void transpose_split(const float* __restrict__ W, __nv_bfloat16* __restrict__ hiT,
                                __nv_bfloat16* __restrict__ loT, int K, int N) {
    __shared__ float t[32][33];
    int n = blockIdx.x * 32 + threadIdx.x;
    int k0 = blockIdx.y * 32;
#pragma unroll
    for (int i = 0; i < 32; i += 8)
        t[threadIdx.y + i][threadIdx.x] = W[(size_t)(k0 + threadIdx.y + i) * N + n];
    __syncthreads();
    int kk = k0 + threadIdx.x;
#pragma unroll
    for (int i = 0; i < 32; i += 8) {
        int nn = blockIdx.x * 32 + threadIdx.y + i;
        float v = t[threadIdx.x][threadIdx.y + i];
        __nv_bfloat16 h = __float2bfloat16(v);
        __nv_bfloat16 l = __float2bfloat16(v - __bfloat162float(h));
        hiT[(size_t)nn * K + kk] = h;
        loT[(size_t)nn * K + kk] = l;
    }
}

// ---------------------------------------------------------------------------
// kqv -> per-head Q (scaled) and K, bf16 hi/lo, layout [bh][t][64]
// ---------------------------------------------------------------------------
__global__ void qk_convert(const float* __restrict__ kqv,
                           __nv_bfloat16* __restrict__ Qh, __nv_bfloat16* __restrict__ Ql,
                           __nv_bfloat16* __restrict__ Kh, __nv_bfloat16* __restrict__ Kl) {
    int idx = blockIdx.x * 256 + threadIdx.x;       // 4096*256 total
    int row = idx >> 8;                             // 0..4095 (b*T + t)
    int c4  = idx & 255;
    int d = (c4 & 15) * 4;
    int h = c4 >> 4;
    int b = row >> 11, t = row & 2047;
    size_t src = (size_t)row * KQV_N;
    float4 q = *(const float4*)(kqv + src + DEMBD + h * DHEAD + d);
    float4 k = *(const float4*)(kqv + src + h * DHEAD + d);
    q.x *= 0.125f; q.y *= 0.125f; q.z *= 0.125f; q.w *= 0.125f;
    size_t dst = ((size_t)(b * NHEADS + h) * TSEQ + t) * DHEAD + d;
    uint32_t qh0 = packbf2(q.x, q.y), qh1 = packbf2(q.z, q.w);
    uint32_t ql0 = packlo2(q.x, q.y, qh0), ql1 = packlo2(q.z, q.w, qh1);
    uint32_t kh0 = packbf2(k.x, k.y), kh1 = packbf2(k.z, k.w);
    uint32_t kl0 = packlo2(k.x, k.y, kh0), kl1 = packlo2(k.z, k.w, kh1);
    *(uint32_t*)(Qh + dst) = qh0; *(uint32_t*)(Qh + dst + 2) = qh1;
    *(uint32_t*)(Ql + dst) = ql0; *(uint32_t*)(Ql + dst + 2) = ql1;
    *(uint32_t*)(Kh + dst) = kh0; *(uint32_t*)(Kh + dst + 2) = kh1;
    *(uint32_t*)(Kl + dst) = kl0; *(uint32_t*)(Kl + dst + 2) = kl1;
}

// ---------------------------------------------------------------------------
// kqv V part -> transposed per-head [bh][d][t], bf16 hi/lo
// ---------------------------------------------------------------------------
__global__ void v_convert(const float* __restrict__ kqv,
                          __nv_bfloat16* __restrict__ Vh, __nv_bfloat16* __restrict__ Vl) {
    __shared__ float tile[32][33];
    int bh = blockIdx.z;
    int b = bh >> 4, h = bh & 15;
    int t0 = blockIdx.x * 32, d0 = blockIdx.y * 32;
    int tx = threadIdx.x, ty = threadIdx.y;   // (32, 8)
#pragma unroll
    for (int i = 0; i < 4; i++)
        tile[ty + i * 8][tx] =
            kqv[(size_t)(b * TSEQ + t0 + ty + i * 8) * KQV_N + 2 * DEMBD + h * DHEAD + d0 + tx];
    __syncthreads();
#pragma unroll
    for (int i = 0; i < 4; i++) {
        float v = tile[tx][ty + i * 8];          // (t = t0+tx, d = d0+ty+8i)
        __nv_bfloat16 hh = __float2bfloat16(v);
        __nv_bfloat16 ll = __float2bfloat16(v - __bfloat162float(hh));
        size_t dst = ((size_t)bh * DHEAD + d0 + ty + i * 8) * TSEQ + t0 + tx;
        Vh[dst] = hh;
        Vl[dst] = ll;
    }
}

// ---------------------------------------------------------------------------
// bf16 hi/lo tensor-core GEMM (unchanged from R5)
// ---------------------------------------------------------------------------
#define BK        32
#define LDS_ROW   40
#define TILE_H    (128 * LDS_ROW)
#define TILE_B    (TILE_H * 2)
#define STAGE_B   (4 * TILE_B)
#define GEMM_SMEM (2 * STAGE_B)

__device__ __forceinline__ void load_tile(uint32_t tb, const __nv_bfloat16* sp, int K, int tid) {
#pragma unroll
    for (int i = 0; i < 2; i++) {
        int chunk = tid + i * 256;
        int row = chunk >> 2, cb = chunk & 3;
        cp16(tb + (uint32_t)row * (LDS_ROW * 2) + (uint32_t)cb * 16,
             sp + (size_t)row * K + cb * 8);
    }
}

__global__ __launch_bounds__(256)
void gemm_bf16_mma(const __nv_bfloat16* __restrict__ Ah, const __nv_bfloat16* __restrict__ Al,
                   const __nv_bfloat16* __restrict__ Bh, const __nv_bfloat16* __restrict__ Bl,
                   const float* __restrict__ bias, float* __restrict__ C,
                   int M, int N, int K) {
    extern __shared__ char smem[];
    const uint32_t sbase = smem_u32(smem);

    const int tid  = threadIdx.x;
    const int wid  = tid >> 5;
    const int lane = tid & 31;
    const int m0 = blockIdx.y * 128;
    const int n0 = blockIdx.x * 128;
    const int wm = (wid & 1) * 64;
    const int wn = (wid >> 1) * 32;
    const int NSLAB = K / BK;

    const __nv_bfloat16* Ah0 = Ah + (size_t)m0 * K;
    const __nv_bfloat16* Al0 = Al + (size_t)m0 * K;
    const __nv_bfloat16* Bh0 = Bh + (size_t)n0 * K;
    const __nv_bfloat16* Bl0 = Bl + (size_t)n0 * K;

    const int aOff = (wm + (lane & 15)) * LDS_ROW + (lane >> 4) * 8;
    const int bOff = (wn + (lane & 7) + ((lane >> 4) << 3)) * LDS_ROW + (((lane >> 3) & 1) << 3);

    float acc[4][4][4];
#pragma unroll
    for (int mb = 0; mb < 4; mb++)
#pragma unroll
        for (int nb = 0; nb < 4; nb++)
#pragma unroll
            for (int r = 0; r < 4; r++) acc[mb][nb][r] = 0.0f;

    {
        const uint32_t st = sbase;
        load_tile(st + 0 * TILE_B, Ah0, K, tid);
        load_tile(st + 1 * TILE_B, Al0, K, tid);
        load_tile(st + 2 * TILE_B, Bh0, K, tid);
        load_tile(st + 3 * TILE_B, Bl0, K, tid);
        cp_commit();
    }

    for (int s = 0; s < NSLAB; s++) {
        if (s + 1 < NSLAB) {
            const uint32_t st = sbase + ((s + 1) & 1) * STAGE_B;
            const int k0 = (s + 1) * BK;
            load_tile(st + 0 * TILE_B, Ah0 + k0, K, tid);
            load_tile(st + 1 * TILE_B, Al0 + k0, K, tid);
            load_tile(st + 2 * TILE_B, Bh0 + k0, K, tid);
            load_tile(st + 3 * TILE_B, Bl0 + k0, K, tid);
            cp_commit();
            asm volatile("cp.async.wait_group 1;" ::: "memory");
        } else {
            asm volatile("cp.async.wait_group 0;" ::: "memory");
        }
        __syncthreads();

        const uint32_t st = sbase + (s & 1) * STAGE_B;
        const uint32_t ahb = st + 0 * TILE_B + (uint32_t)aOff * 2;
        const uint32_t alb = st + 1 * TILE_B + (uint32_t)aOff * 2;
        const uint32_t bhb = st + 2 * TILE_B + (uint32_t)bOff * 2;
        const uint32_t blb = st + 3 * TILE_B + (uint32_t)bOff * 2;

#pragma unroll
        for (int kk = 0; kk < BK; kk += 16) {
            uint32_t ah[4][4], al[4][4], bh[2][4], bl[2][4];
#pragma unroll
            for (int mb = 0; mb < 4; mb++) {
                LDSM4(ah[mb], ahb + (mb * 16 * LDS_ROW + kk) * 2);
                LDSM4(al[mb], alb + (mb * 16 * LDS_ROW + kk) * 2);
            }
#pragma unroll
            for (int g = 0; g < 2; g++) {
                LDSM4(bh[g], bhb + (g * 16 * LDS_ROW + kk) * 2);
                LDSM4(bl[g], blb + (g * 16 * LDS_ROW + kk) * 2);
            }
#pragma unroll
            for (int mb = 0; mb < 4; mb++)
#pragma unroll
                for (int nb = 0; nb < 4; nb++) {
                    const int g = nb >> 1, h2 = (nb & 1) * 2;
                    MMA_BF16(acc[mb][nb], ah[mb], bh[g][h2], bh[g][h2 + 1]);
                    MMA_BF16(acc[mb][nb], ah[mb], bl[g][h2], bl[g][h2 + 1]);
                    MMA_BF16(acc[mb][nb], al[mb], bh[g][h2], bh[g][h2 + 1]);
                }
        }
        __syncthreads();
    }

    const int rBase = m0 + wm + (lane >> 2);
    const int cBase = n0 + wn + (lane & 3) * 2;
#pragma unroll
    for (int mb = 0; mb < 4; mb++) {
#pragma unroll
        for (int nb = 0; nb < 4; nb++) {
            const int col = cBase + nb * 8;
            const float bx = __ldg(bias + col);
            const float by = __ldg(bias + col + 1);
            float* p0 = C + (size_t)(rBase + mb * 16) * N + col;
            float* p1 = C + (size_t)(rBase + mb * 16 + 8) * N + col;
            *(float2*)p0 = make_float2(acc[mb][nb][0] + bx, acc[mb][nb][1] + by);
            *(float2*)p1 = make_float2(acc[mb][nb][2] + bx, acc[mb][nb][3] + by);
        }
    }
}

// ---------------------------------------------------------------------------
// Tensor-core causal flash attention (bf16 hi/lo, fp32 softmax).
// Grid (16, NHEADS, BS), 256 threads. CTA = 128 queries; key tiles of 64.
// Warp w owns q-rows w*16..w*16+15 and the full 64-key width.
// Output written directly as bf16 hi/lo (input of GEMM2).
// ---------------------------------------------------------------------------
#define AT_ROW    72                      // 64 + 8 pad halves
#define AT_TILE_B (64 * AT_ROW * 2)       // 9216 B
#define AT_STAGE  (4 * AT_TILE_B)         // Khi,Klo,Vhi,Vlo = 36864 B
#define ATTN_SMEM (2 * AT_STAGE)          // 73728 B

__global__ __launch_bounds__(256)
void attn_tc(const __nv_bfloat16* __restrict__ Qh, const __nv_bfloat16* __restrict__ Ql,
             const __nv_bfloat16* __restrict__ Kh, const __nv_bfloat16* __restrict__ Kl,
             const __nv_bfloat16* __restrict__ Vh, const __nv_bfloat16* __restrict__ Vl,
             __nv_bfloat16* __restrict__ Oh, __nv_bfloat16* __restrict__ Ol) {
    extern __shared__ char smem[];
    const uint32_t sbase = smem_u32(smem);

    const int tid  = threadIdx.x;
    const int wid  = tid >> 5;
    const int lane = tid & 31;
    const int qt = (gridDim.x - 1) - blockIdx.x;       // heavy tiles first
    const int h  = blockIdx.y;
    const int b  = blockIdx.z;
    const int bh = b * NHEADS + h;
    const int nkt = 2 * qt + 2;

    const __nv_bfloat16* Qhp = Qh + ((size_t)bh * TSEQ + qt * 128) * DHEAD;
    const __nv_bfloat16* Qlp = Ql + ((size_t)bh * TSEQ + qt * 128) * DHEAD;
    const __nv_bfloat16* Khp = Kh + (size_t)bh * TSEQ * DHEAD;
    const __nv_bfloat16* Klp = Kl + (size_t)bh * TSEQ * DHEAD;
    const __nv_bfloat16* Vhp = Vh + (size_t)bh * DHEAD * TSEQ;
    const __nv_bfloat16* Vlp = Vl + (size_t)bh * DHEAD * TSEQ;

    // ---- stage Q (128x64) into smem, extract A fragments, then free smem ----
#pragma unroll
    for (int i = 0; i < 4; i++) {
        int chunk = tid + i * 256;           // 1024 chunks
        int row = chunk >> 3, cb = chunk & 7;
        cp16(sbase + (uint32_t)row * (AT_ROW * 2) + cb * 16, Qhp + (size_t)row * DHEAD + cb * 8);
        cp16(sbase + 2 * AT_TILE_B + (uint32_t)row * (AT_ROW * 2) + cb * 16,
             Qlp + (size_t)row * DHEAD + cb * 8);
    }
    cp_commit();
    asm volatile("cp.async.wait_group 0;" ::: "memory");
    __syncthreads();

    uint32_t qhi[4][4], qlo[4][4];
    {
        const int aOff = (wid * 16 + (lane & 15)) * AT_ROW + (lane >> 4) * 8;
#pragma unroll
        for (int kb = 0; kb < 4; kb++) {
            LDSM4(qhi[kb], sbase + (uint32_t)(aOff + kb * 16) * 2);
            LDSM4(qlo[kb], sbase + 2 * AT_TILE_B + (uint32_t)(aOff + kb * 16) * 2);
        }
    }
    __syncthreads();

    // B-operand ldmatrix base (n-index over 64, k-contig rows of AT_ROW halves)
    const int bOff = ((lane & 7) + ((lane >> 4) << 3)) * AT_ROW + (((lane >> 3) & 1) << 3);

    float o[8][4];
#pragma unroll
    for (int nb = 0; nb < 8; nb++)
#pragma unroll
        for (int r = 0; r < 4; r++) o[nb][r] = 0.0f;
    float m0 = -INFINITY, m1 = -INFINITY, l0 = 0.0f, l1 = 0.0f;

    const int qrow_lo = qt * 128 + wid * 16;           // warp's lowest q row
    const int r0g = qrow_lo + (lane >> 2);
    const int r1g = r0g + 8;

    // ---- prologue: key tile 0 -> stage 0 ----
    {
        const uint32_t st = sbase;
#pragma unroll
        for (int i = 0; i < 8; i++) {
            int chunk = tid + i * 256;                 // 2048 chunks
            int tile = chunk >> 9, within = chunk & 511;
            int row = within >> 3, cb = within & 7;
            uint32_t dst = st + tile * AT_TILE_B + (uint32_t)row * (AT_ROW * 2) + cb * 16;
            if (tile == 0)      cp16(dst, Khp + (size_t)row * DHEAD + cb * 8);
            else if (tile == 1) cp16(dst, Klp + (size_t)row * DHEAD + cb * 8);
            else if (tile == 2) cp16(dst, Vhp + (size_t)row * TSEQ + cb * 8);
            else                cp16(dst, Vlp + (size_t)row * TSEQ + cb * 8);
        }
        cp_commit();
    }

    for (int kt = 0; kt < nkt; kt++) {
        if (kt + 1 < nkt) {
            const uint32_t st = sbase + ((kt + 1) & 1) * AT_STAGE;
            const int koff = (kt + 1) * 64;
#pragma unroll
            for (int i = 0; i < 8; i++) {
                int chunk = tid + i * 256;
                int tile = chunk >> 9, within = chunk & 511;
                int row = within >> 3, cb = within & 7;
                uint32_t dst = st + tile * AT_TILE_B + (uint32_t)row * (AT_ROW * 2) + cb * 16;
                if (tile == 0)      cp16(dst, Khp + (size_t)(koff + row) * DHEAD + cb * 8);
                else if (tile == 1) cp16(dst, Klp + (size_t)(koff + row) * DHEAD + cb * 8);
                else if (tile == 2) cp16(dst, Vhp + (size_t)row * TSEQ + koff + cb * 8);
                else                cp16(dst, Vlp + (size_t)row * TSEQ + koff + cb * 8);
            }
            cp_commit();
            asm volatile("cp.async.wait_group 1;" ::: "memory");
        } else {
            asm volatile("cp.async.wait_group 0;" ::: "memory");
        }
        __syncthreads();

        // skip tiles entirely above the diagonal for this warp
        if (kt * 64 <= qrow_lo + 15) {
            const uint32_t st = sbase + (kt & 1) * AT_STAGE;
            const uint32_t khb = st + 0 * AT_TILE_B + (uint32_t)bOff * 2;
            const uint32_t klb = st + 1 * AT_TILE_B + (uint32_t)bOff * 2;
            const uint32_t vhb = st + 2 * AT_TILE_B + (uint32_t)bOff * 2;
            const uint32_t vlb = st + 3 * AT_TILE_B + (uint32_t)bOff * 2;

            // ---- S = Q K^T (hi/lo split) ----
            float s[8][4];
#pragma unroll
            for (int nb = 0; nb < 8; nb++)
#pragma unroll
                for (int r = 0; r < 4; r++) s[nb][r] = 0.0f;

#pragma unroll
            for (int kb = 0; kb < 4; kb++) {
                uint32_t kh[4][4], kl[4][4];
#pragma unroll
                for (int g = 0; g < 4; g++) {
                    LDSM4(kh[g], khb + (uint32_t)(g * 16 * AT_ROW + kb * 16) * 2);
                    LDSM4(kl[g], klb + (uint32_t)(g * 16 * AT_ROW + kb * 16) * 2);
                }
#pragma unroll
                for (int g = 0; g < 4; g++)
#pragma unroll
                    for (int half = 0; half < 2; half++) {
                        const int nb = 2 * g + half, h2 = half * 2;
                        MMA_BF16(s[nb], qhi[kb], kh[g][h2], kh[g][h2 + 1]);
                        MMA_BF16(s[nb], qhi[kb], kl[g][h2], kl[g][h2 + 1]);
                        MMA_BF16(s[nb], qlo[kb], kh[g][h2], kh[g][h2 + 1]);
                    }
            }

            // ---- causal mask (only needed near diagonal) ----
            if (kt * 64 + 63 > qrow_lo) {
#pragma unroll
                for (int nb = 0; nb < 8; nb++) {
                    int c = kt * 64 + nb * 8 + (lane & 3) * 2;
                    if (c > r0g)     s[nb][0] = -INFINITY;
                    if (c + 1 > r0g) s[nb][1] = -INFINITY;
                    if (c > r1g)     s[nb][2] = -INFINITY;
                    if (c + 1 > r1g) s[nb][3] = -INFINITY;
                }
            }

            // ---- online softmax ----
            float mx0 = -INFINITY, mx1 = -INFINITY;
#pragma unroll
            for (int nb = 0; nb < 8; nb++) {
                mx0 = fmaxf(mx0, fmaxf(s[nb][0], s[nb][1]));
                mx1 = fmaxf(mx1, fmaxf(s[nb][2], s[nb][3]));
            }
            mx0 = fmaxf(mx0, __shfl_xor_sync(0xffffffffu, mx0, 1));
            mx0 = fmaxf(mx0, __shfl_xor_sync(0xffffffffu, mx0, 2));
            mx1 = fmaxf(mx1, __shfl_xor_sync(0xffffffffu, mx1, 1));
            mx1 = fmaxf(mx1, __shfl_xor_sync(0xffffffffu, mx1, 2));

            float mn0 = fmaxf(m0, mx0), mn1 = fmaxf(m1, mx1);
            float c0 = __expf(m0 - mn0), c1 = __expf(m1 - mn1);
            m0 = mn0; m1 = mn1;

            float rs0 = 0.0f, rs1 = 0.0f;
#pragma unroll
            for (int nb = 0; nb < 8; nb++) {
                s[nb][0] = __expf(s[nb][0] - m0); rs0 += s[nb][0];
                s[nb][1] = __expf(s[nb][1] - m0); rs0 += s[nb][1];
                s[nb][2] = __expf(s[nb][2] - m1); rs1 += s[nb][2];
                s[nb][3] = __expf(s[nb][3] - m1); rs1 += s[nb][3];
            }
            rs0 += __shfl_xor_sync(0xffffffffu, rs0, 1);
            rs0 += __shfl_xor_sync(0xffffffffu, rs0, 2);
            rs1 += __shfl_xor_sync(0xffffffffu, rs1, 1);
            rs1 += __shfl_xor_sync(0xffffffffu, rs1, 2);
            l0 = l0 * c0 + rs0;
            l1 = l1 * c1 + rs1;
#pragma unroll
            for (int nb = 0; nb < 8; nb++) {
                o[nb][0] *= c0; o[nb][1] *= c0;
                o[nb][2] *= c1; o[nb][3] *= c1;
            }

            // ---- O += P V  (P converted in-register to A fragments) ----
#pragma unroll
            for (int kbp = 0; kbp < 4; kbp++) {
                uint32_t phi[4], plo[4];
                const int e = 2 * kbp;
                phi[0] = packbf2(s[e][0], s[e][1]);
                phi[1] = packbf2(s[e][2], s[e][3]);
                phi[2] = packbf2(s[e + 1][0], s[e + 1][1]);
                phi[3] = packbf2(s[e + 1][2], s[e + 1][3]);
                plo[0] = packlo2(s[e][0], s[e][1], phi[0]);
                plo[1] = packlo2(s[e][2], s[e][3], phi[1]);
                plo[2] = packlo2(s[e + 1][0], s[e + 1][1], phi[2]);
                plo[3] = packlo2(s[e + 1][2], s[e + 1][3], phi[3]);

                uint32_t vh[4][4], vl[4][4];
#pragma unroll
                for (int g = 0; g < 4; g++) {
                    LDSM4(vh[g], vhb + (uint32_t)(g * 16 * AT_ROW + kbp * 16) * 2);
                    LDSM4(vl[g], vlb + (uint32_t)(g * 16 * AT_ROW + kbp * 16) * 2);
                }
#pragma unroll
                for (int g = 0; g < 4; g++)
#pragma unroll
                    for (int half = 0; half < 2; half++) {
                        const int nbd = 2 * g + half, h2 = half * 2;
                        MMA_BF16(o[nbd], phi, vh[g][h2], vh[g][h2 + 1]);
                        MMA_BF16(o[nbd], plo, vh[g][h2], vh[g][h2 + 1]);
                        MMA_BF16(o[nbd], phi, vl[g][h2], vl[g][h2 + 1]);
                    }
            }
        }
        __syncthreads();
    }

    // ---- epilogue: normalize, split hi/lo, store bf16 pairs ----
    const float inv0 = 1.0f / l0, inv1 = 1.0f / l1;
    const size_t grow0 = (size_t)b * TSEQ + r0g;       // r0g is a t index
    const size_t grow1 = grow0 + 8;
    const int colb = h * DHEAD + (lane & 3) * 2;
#pragma unroll
    for (int nbd = 0; nbd < 8; nbd++) {
        const int col = colb + nbd * 8;
        float f00 = o[nbd][0] * inv0, f01 = o[nbd][1] * inv0;
        float f10 = o[nbd][2] * inv1, f11 = o[nbd][3] * inv1;
        uint32_t h0 = packbf2(f00, f01), l0p = packlo2(f00, f01, h0);
        uint32_t h1 = packbf2(f10, f11), l1p = packlo2(f10, f11, h1);
        *(uint32_t*)(Oh + grow0 * DEMBD + col) = h0;
        *(uint32_t*)(Ol + grow0 * DEMBD + col) = l0p;
        *(uint32_t*)(Oh + grow1 * DEMBD + col) = h1;
        *(uint32_t*)(Ol + grow1 * DEMBD + col) = l1p;
    }
}

// ---------------------------------------------------------------------------
extern "C" void kernel_launch(void* const* d_in, const int* in_sizes, int n_in,
                              void* d_out, int out_size) {
    const float* x  = (const float*)d_in[0];
    const float* W1 = (const float*)d_in[1];
    const float* b1 = (const float*)d_in[2];
    const float* W2 = (const float*)d_in[3];
    const float* b2 = (const float*)d_in[4];
    float* out = (float*)d_out;

    float* kqv;
    __nv_bfloat16 *A1h, *A1l, *A2h, *A2l, *W1h, *W1l, *W2h, *W2l;
    __nv_bfloat16 *Qh, *Ql, *Kh, *Kl, *Vh, *Vl;
    cudaGetSymbolAddress((void**)&kqv, g_kqv);
    cudaGetSymbolAddress((void**)&A1h, g_A1hi);
    cudaGetSymbolAddress((void**)&A1l, g_A1lo);
    cudaGetSymbolAddress((void**)&A2h, g_A2hi);
    cudaGetSymbolAddress((void**)&A2l, g_A2lo);
    cudaGetSymbolAddress((void**)&W1h, g_W1Thi);
    cudaGetSymbolAddress((void**)&W1l, g_W1Tlo);
    cudaGetSymbolAddress((void**)&W2h, g_W2Thi);
    cudaGetSymbolAddress((void**)&W2l, g_W2Tlo);
    cudaGetSymbolAddress((void**)&Qh, g_Qhi);
    cudaGetSymbolAddress((void**)&Ql, g_Qlo);
    cudaGetSymbolAddress((void**)&Kh, g_Khi);
    cudaGetSymbolAddress((void**)&Kl, g_Klo);
    cudaGetSymbolAddress((void**)&Vh, g_Vthi);
    cudaGetSymbolAddress((void**)&Vl, g_Vtlo);

    cudaFuncSetAttribute(gemm_bf16_mma, cudaFuncAttributeMaxDynamicSharedMemorySize, GEMM_SMEM);
    cudaFuncSetAttribute(attn_tc, cudaFuncAttributeMaxDynamicSharedMemorySize, ATTN_SMEM);

    // 0) input conversions
    {
        int n4 = MROWS * DEMBD / 4;
        split_f32<<<(n4 + 255) / 256, 256>>>(x, A1h, A1l, n4);
        transpose_split<<<dim3(KQV_N / 32, DEMBD / 32), dim3(32, 8)>>>(W1, W1h, W1l, DEMBD, KQV_N);
        transpose_split<<<dim3(DEMBD / 32, DEMBD / 32), dim3(32, 8)>>>(W2, W2h, W2l, DEMBD, DEMBD);
    }
    // 1) kqv = x @ W1 + b1  (tensor cores)
    gemm_bf16_mma<<<dim3(KQV_N / 128, MROWS / 128), 256, GEMM_SMEM>>>(
        A1h, A1l, W1h, W1l, b1, kqv, MROWS, KQV_N, DEMBD);
    // 2a) kqv -> per-head bf16 hi/lo operands
    qk_convert<<<4096, 256>>>(kqv, Qh, Ql, Kh, Kl);
    v_convert<<<dim3(TSEQ / 32, DHEAD / 32, BH), dim3(32, 8)>>>(kqv, Vh, Vl);
    // 2b) causal attention (tensor cores), writes A2 hi/lo directly
    attn_tc<<<dim3(TSEQ / 128, NHEADS, BS), 256, ATTN_SMEM>>>(
        Qh, Ql, Kh, Kl, Vh, Vl, A2h, A2l);
    // 3) out = att @ W2 + b2  (tensor cores)
    gemm_bf16_mma<<<dim3(DEMBD / 128, MROWS / 128), 256, GEMM_SMEM>>>(
        A2h, A2l, W2h, W2l, b2, out, MROWS, DEMBD, DEMBD);
}

// round 7
// speedup vs baseline: 2.6046x; 1.0989x over previous
#include <cuda_runtime.h>
#include <cuda_bf16.h>
#include <math.h>
#include <stdint.h>

// Problem constants
#define BS      2
#define TSEQ    2048
#define DEMBD   1024
#define NHEADS  16
#define DHEAD   64
#define MROWS   (BS * TSEQ)      // 4096
#define KQV_N   (3 * DEMBD)      // 3072
#define BH      (BS * NHEADS)    // 32

// ---------------------------------------------------------------------------
// Scratch (__device__ globals; allocation-free rule)
// ---------------------------------------------------------------------------
__device__ float g_kqv[MROWS * KQV_N];   // [4096, 3072]  cols: [K | Q | V]

__device__ __nv_bfloat16 g_A1hi[MROWS * DEMBD];
__device__ __nv_bfloat16 g_A1lo[MROWS * DEMBD];
__device__ __nv_bfloat16 g_A2hi[MROWS * DEMBD];   // written by attention
__device__ __nv_bfloat16 g_A2lo[MROWS * DEMBD];
__device__ __nv_bfloat16 g_W1Thi[KQV_N * DEMBD];
__device__ __nv_bfloat16 g_W1Tlo[KQV_N * DEMBD];
__device__ __nv_bfloat16 g_W2Thi[DEMBD * DEMBD];
__device__ __nv_bfloat16 g_W2Tlo[DEMBD * DEMBD];

// Attention operands, per-head layouts (bf16 hi/lo)
__device__ __nv_bfloat16 g_Qhi[BH * TSEQ * DHEAD];  // [bh][t][d], pre-scaled
__device__ __nv_bfloat16 g_Qlo[BH * TSEQ * DHEAD];
__device__ __nv_bfloat16 g_Khi[BH * TSEQ * DHEAD];  // [bh][t][d]
__device__ __nv_bfloat16 g_Klo[BH * TSEQ * DHEAD];
__device__ __nv_bfloat16 g_Vthi[BH * DHEAD * TSEQ]; // [bh][d][t]  (transposed)
__device__ __nv_bfloat16 g_Vtlo[BH * DHEAD * TSEQ];

// ---------------------------------------------------------------------------
// PTX helpers (baseline ISA only)
// ---------------------------------------------------------------------------
__device__ __forceinline__ uint32_t smem_u32(const void* p) {
    uint32_t a;
    asm("{ .reg .u64 t; cvta.to.shared.u64 t, %1; cvt.u32.u64 %0, t; }" : "=r"(a) : "l"(p));
    return a;
}
__device__ __forceinline__ void cp16(uint32_t dst, const void* src) {
    asm volatile("cp.async.cg.shared.global [%0], [%1], 16;"
                 :: "r"(dst), "l"(__cvta_generic_to_global(src)));
}
__device__ __forceinline__ void cp_commit() { asm volatile("cp.async.commit_group;" ::: "memory"); }

#define LDSM4(r, addr) \
    asm volatile("ldmatrix.sync.aligned.m8n8.x4.shared.b16 {%0,%1,%2,%3}, [%4];" \
        : "=r"((r)[0]), "=r"((r)[1]), "=r"((r)[2]), "=r"((r)[3]) : "r"(addr))

#define MMA_BF16(d, a, b0, b1) \
    asm volatile("mma.sync.aligned.m16n8k16.row.col.f32.bf16.bf16.f32 " \
        "{%0,%1,%2,%3}, {%4,%5,%6,%7}, {%8,%9}, {%0,%1,%2,%3};" \
        : "+f"((d)[0]), "+f"((d)[1]), "+f"((d)[2]), "+f"((d)[3]) \
        : "r"((a)[0]), "r"((a)[1]), "r"((a)[2]), "r"((a)[3]), "r"(b0), "r"(b1))

// pack two fp32 into bf16x2: low half <- lo, high half <- hi
__device__ __forceinline__ uint32_t packbf2(float lo, float hi) {
    uint32_t r;
    asm("cvt.rn.bf16x2.f32 %0, %1, %2;" : "=r"(r) : "f"(hi), "f"(lo));
    return r;
}
// residual (lo-part) pack given the hi-pack
__device__ __forceinline__ uint32_t packlo2(float lo, float hi, uint32_t hp) {
    __nv_bfloat162 hv = *reinterpret_cast<__nv_bfloat162*>(&hp);
    return packbf2(lo - __bfloat162float(hv.x), hi - __bfloat162float(hv.y));
}

// ---------------------------------------------------------------------------
// fp32 -> bf16 hi/lo split (elementwise, float4)  [x -> A1]
// ---------------------------------------------------------------------------
__global__ void split_f32(const float* __restrict__ in, __nv_bfloat16* __restrict__ hi,
                          __nv_bfloat16* __restrict__ lo, int n4) {
    int i = blockIdx.x * blockDim.x + threadIdx.x;
    if (i >= n4) return;
    float4 v = ((const float4*)in)[i];
    uint32_t h0 = packbf2(v.x, v.y), h1 = packbf2(v.z, v.w);
    uint32_t l0 = packlo2(v.x, v.y, h0), l1 = packlo2(v.z, v.w, h1);
    ((uint32_t*)hi)[i * 2 + 0] = h0;
    ((uint32_t*)hi)[i * 2 + 1] = h1;
    ((uint32_t*)lo)[i * 2 + 0] = l0;
    ((uint32_t*)lo)[i * 2 + 1] = l1;
}

// ---------------------------------------------------------------------------
// W[K][N] fp32 -> W^T[N][K] bf16 hi/lo (tiled transpose)
// ---------------------------------------------------------------------------
__global__ void transpose_split(const float* __restrict__ W, __nv_bfloat16* __restrict__ hiT,
                                __nv_bfloat16* __restrict__ loT, int K, int N) {
    __shared__ float t[32][33];
    int n = blockIdx.x * 32 + threadIdx.x;
    int k0 = blockIdx.y * 32;
#pragma unroll
    for (int i = 0; i < 32; i += 8)
        t[threadIdx.y + i][threadIdx.x] = W[(size_t)(k0 + threadIdx.y + i) * N + n];
    __syncthreads();
    int kk = k0 + threadIdx.x;
#pragma unroll
    for (int i = 0; i < 32; i += 8) {
        int nn = blockIdx.x * 32 + threadIdx.y + i;
        float v = t[threadIdx.x][threadIdx.y + i];
        __nv_bfloat16 h = __float2bfloat16(v);
        __nv_bfloat16 l = __float2bfloat16(v - __bfloat162float(h));
        hiT[(size_t)nn * K + kk] = h;
        loT[(size_t)nn * K + kk] = l;
    }
}

// ---------------------------------------------------------------------------
// kqv -> per-head Q (scaled) and K, bf16 hi/lo, layout [bh][t][64]
// ---------------------------------------------------------------------------
__global__ void qk_convert(const float* __restrict__ kqv,
                           __nv_bfloat16* __restrict__ Qh, __nv_bfloat16* __restrict__ Ql,
                           __nv_bfloat16* __restrict__ Kh, __nv_bfloat16* __restrict__ Kl) {
    int idx = blockIdx.x * 256 + threadIdx.x;       // 4096*256 total
    int row = idx >> 8;                             // 0..4095 (b*T + t)
    int c4  = idx & 255;
    int d = (c4 & 15) * 4;
    int h = c4 >> 4;
    int b = row >> 11, t = row & 2047;
    size_t src = (size_t)row * KQV_N;
    float4 q = *(const float4*)(kqv + src + DEMBD + h * DHEAD + d);
    float4 k = *(const float4*)(kqv + src + h * DHEAD + d);
    q.x *= 0.125f; q.y *= 0.125f; q.z *= 0.125f; q.w *= 0.125f;
    size_t dst = ((size_t)(b * NHEADS + h) * TSEQ + t) * DHEAD + d;
    uint32_t qh0 = packbf2(q.x, q.y), qh1 = packbf2(q.z, q.w);
    uint32_t ql0 = packlo2(q.x, q.y, qh0), ql1 = packlo2(q.z, q.w, qh1);
    uint32_t kh0 = packbf2(k.x, k.y), kh1 = packbf2(k.z, k.w);
    uint32_t kl0 = packlo2(k.x, k.y, kh0), kl1 = packlo2(k.z, k.w, kh1);
    *(uint32_t*)(Qh + dst) = qh0; *(uint32_t*)(Qh + dst + 2) = qh1;
    *(uint32_t*)(Ql + dst) = ql0; *(uint32_t*)(Ql + dst + 2) = ql1;
    *(uint32_t*)(Kh + dst) = kh0; *(uint32_t*)(Kh + dst + 2) = kh1;
    *(uint32_t*)(Kl + dst) = kl0; *(uint32_t*)(Kl + dst + 2) = kl1;
}

// ---------------------------------------------------------------------------
// kqv V part -> transposed per-head [bh][d][t], bf16 hi/lo
// ---------------------------------------------------------------------------
__global__ void v_convert(const float* __restrict__ kqv,
                          __nv_bfloat16* __restrict__ Vh, __nv_bfloat16* __restrict__ Vl) {
    __shared__ float tile[32][33];
    int bh = blockIdx.z;
    int b = bh >> 4, h = bh & 15;
    int t0 = blockIdx.x * 32, d0 = blockIdx.y * 32;
    int tx = threadIdx.x, ty = threadIdx.y;   // (32, 8)
#pragma unroll
    for (int i = 0; i < 4; i++)
        tile[ty + i * 8][tx] =
            kqv[(size_t)(b * TSEQ + t0 + ty + i * 8) * KQV_N + 2 * DEMBD + h * DHEAD + d0 + tx];
    __syncthreads();
#pragma unroll
    for (int i = 0; i < 4; i++) {
        float v = tile[tx][ty + i * 8];          // (t = t0+tx, d = d0+ty+8i)
        __nv_bfloat16 hh = __float2bfloat16(v);
        __nv_bfloat16 ll = __float2bfloat16(v - __bfloat162float(hh));
        size_t dst = ((size_t)bh * DHEAD + d0 + ty + i * 8) * TSEQ + t0 + tx;
        Vh[dst] = hh;
        Vl[dst] = ll;
    }
}

// ---------------------------------------------------------------------------
// bf16 hi/lo tensor-core GEMM. R7: 2 CTAs/SM (reg cap 128) + low-pressure
// inner loop (B frags hoisted per k-step, A frags streamed per m-block).
// ---------------------------------------------------------------------------
#define BK        32
#define LDS_ROW   40
#define TILE_H    (128 * LDS_ROW)
#define TILE_B    (TILE_H * 2)
#define STAGE_B   (4 * TILE_B)
#define GEMM_SMEM (2 * STAGE_B)            // 81920 B -> 2 CTAs fit in 228KB

__device__ __forceinline__ void load_tile(uint32_t tb, const __nv_bfloat16* sp, int K, int tid) {
#pragma unroll
    for (int i = 0; i < 2; i++) {
        int chunk = tid + i * 256;
        int row = chunk >> 2, cb = chunk & 3;
        cp16(tb + (uint32_t)row * (LDS_ROW * 2) + (uint32_t)cb * 16,
             sp + (size_t)row * K + cb * 8);
    }
}

__global__ __launch_bounds__(256, 2)
void gemm_bf16_mma(const __nv_bfloat16* __restrict__ Ah, const __nv_bfloat16* __restrict__ Al,
                   const __nv_bfloat16* __restrict__ Bh, const __nv_bfloat16* __restrict__ Bl,
                   const float* __restrict__ bias, float* __restrict__ C,
                   int M, int N, int K) {
    extern __shared__ char smem[];
    const uint32_t sbase = smem_u32(smem);

    const int tid  = threadIdx.x;
    const int wid  = tid >> 5;
    const int lane = tid & 31;
    const int m0 = blockIdx.y * 128;
    const int n0 = blockIdx.x * 128;
    const int wm = (wid & 1) * 64;
    const int wn = (wid >> 1) * 32;
    const int NSLAB = K / BK;

    const __nv_bfloat16* Ah0 = Ah + (size_t)m0 * K;
    const __nv_bfloat16* Al0 = Al + (size_t)m0 * K;
    const __nv_bfloat16* Bh0 = Bh + (size_t)n0 * K;
    const __nv_bfloat16* Bl0 = Bl + (size_t)n0 * K;

    const int aOff = (wm + (lane & 15)) * LDS_ROW + (lane >> 4) * 8;
    const int bOff = (wn + (lane & 7) + ((lane >> 4) << 3)) * LDS_ROW + (((lane >> 3) & 1) << 3);

    float acc[4][4][4];
#pragma unroll
    for (int mb = 0; mb < 4; mb++)
#pragma unroll
        for (int nb = 0; nb < 4; nb++)
#pragma unroll
            for (int r = 0; r < 4; r++) acc[mb][nb][r] = 0.0f;

    {
        const uint32_t st = sbase;
        load_tile(st + 0 * TILE_B, Ah0, K, tid);
        load_tile(st + 1 * TILE_B, Al0, K, tid);
        load_tile(st + 2 * TILE_B, Bh0, K, tid);
        load_tile(st + 3 * TILE_B, Bl0, K, tid);
        cp_commit();
    }

    for (int s = 0; s < NSLAB; s++) {
        if (s + 1 < NSLAB) {
            const uint32_t st = sbase + ((s + 1) & 1) * STAGE_B;
            const int k0 = (s + 1) * BK;
            load_tile(st + 0 * TILE_B, Ah0 + k0, K, tid);
            load_tile(st + 1 * TILE_B, Al0 + k0, K, tid);
            load_tile(st + 2 * TILE_B, Bh0 + k0, K, tid);
            load_tile(st + 3 * TILE_B, Bl0 + k0, K, tid);
            cp_commit();
            asm volatile("cp.async.wait_group 1;" ::: "memory");
        } else {
            asm volatile("cp.async.wait_group 0;" ::: "memory");
        }
        __syncthreads();

        const uint32_t st = sbase + (s & 1) * STAGE_B;
        const uint32_t ahb = st + 0 * TILE_B + (uint32_t)aOff * 2;
        const uint32_t alb = st + 1 * TILE_B + (uint32_t)aOff * 2;
        const uint32_t bhb = st + 2 * TILE_B + (uint32_t)bOff * 2;
        const uint32_t blb = st + 3 * TILE_B + (uint32_t)bOff * 2;

#pragma unroll
        for (int kk = 0; kk < BK; kk += 16) {
            // Hoist B fragments (16 regs), stream A per m-block (8 regs live).
            uint32_t bh[2][4], bl[2][4];
#pragma unroll
            for (int g = 0; g < 2; g++) {
                LDSM4(bh[g], bhb + (g * 16 * LDS_ROW + kk) * 2);
                LDSM4(bl[g], blb + (g * 16 * LDS_ROW + kk) * 2);
            }
#pragma unroll
            for (int mb = 0; mb < 4; mb++) {
                uint32_t ah[4], al[4];
                LDSM4(ah, ahb + (mb * 16 * LDS_ROW + kk) * 2);
                LDSM4(al, alb + (mb * 16 * LDS_ROW + kk) * 2);
#pragma unroll
                for (int nb = 0; nb < 4; nb++) {
                    const int g = nb >> 1, h2 = (nb & 1) * 2;
                    MMA_BF16(acc[mb][nb], ah, bh[g][h2], bh[g][h2 + 1]);
                    MMA_BF16(acc[mb][nb], ah, bl[g][h2], bl[g][h2 + 1]);
                    MMA_BF16(acc[mb][nb], al, bh[g][h2], bh[g][h2 + 1]);
                }
            }
        }
        __syncthreads();
    }

    const int rBase = m0 + wm + (lane >> 2);
    const int cBase = n0 + wn + (lane & 3) * 2;
#pragma unroll
    for (int mb = 0; mb < 4; mb++) {
#pragma unroll
        for (int nb = 0; nb < 4; nb++) {
            const int col = cBase + nb * 8;
            const float bx = __ldg(bias + col);
            const float by = __ldg(bias + col + 1);
            float* p0 = C + (size_t)(rBase + mb * 16) * N + col;
            float* p1 = C + (size_t)(rBase + mb * 16 + 8) * N + col;
            *(float2*)p0 = make_float2(acc[mb][nb][0] + bx, acc[mb][nb][1] + by);
            *(float2*)p1 = make_float2(acc[mb][nb][2] + bx, acc[mb][nb][3] + by);
        }
    }
}

// ---------------------------------------------------------------------------
// Tensor-core causal flash attention (bf16 hi/lo, fp32 softmax) — R6 version.
// ---------------------------------------------------------------------------
#define AT_ROW    72                      // 64 + 8 pad halves
#define AT_TILE_B (64 * AT_ROW * 2)       // 9216 B
#define AT_STAGE  (4 * AT_TILE_B)         // Khi,Klo,Vhi,Vlo = 36864 B
#define ATTN_SMEM (2 * AT_STAGE)          // 73728 B

__global__ __launch_bounds__(256)
void attn_tc(const __nv_bfloat16* __restrict__ Qh, const __nv_bfloat16* __restrict__ Ql,
             const __nv_bfloat16* __restrict__ Kh, const __nv_bfloat16* __restrict__ Kl,
             const __nv_bfloat16* __restrict__ Vh, const __nv_bfloat16* __restrict__ Vl,
             __nv_bfloat16* __restrict__ Oh, __nv_bfloat16* __restrict__ Ol) {
    extern __shared__ char smem[];
    const uint32_t sbase = smem_u32(smem);

    const int tid  = threadIdx.x;
    const int wid  = tid >> 5;
    const int lane = tid & 31;
    const int qt = (gridDim.x - 1) - blockIdx.x;       // heavy tiles first
    const int h  = blockIdx.y;
    const int b  = blockIdx.z;
    const int bh = b * NHEADS + h;
    const int nkt = 2 * qt + 2;

    const __nv_bfloat16* Qhp = Qh + ((size_t)bh * TSEQ + qt * 128) * DHEAD;
    const __nv_bfloat16* Qlp = Ql + ((size_t)bh * TSEQ + qt * 128) * DHEAD;
    const __nv_bfloat16* Khp = Kh + (size_t)bh * TSEQ * DHEAD;
    const __nv_bfloat16* Klp = Kl + (size_t)bh * TSEQ * DHEAD;
    const __nv_bfloat16* Vhp = Vh + (size_t)bh * DHEAD * TSEQ;
    const __nv_bfloat16* Vlp = Vl + (size_t)bh * DHEAD * TSEQ;

    // ---- stage Q (128x64) into smem, extract A fragments, then free smem ----
#pragma unroll
    for (int i = 0; i < 4; i++) {
        int chunk = tid + i * 256;           // 1024 chunks
        int row = chunk >> 3, cb = chunk & 7;
        cp16(sbase + (uint32_t)row * (AT_ROW * 2) + cb * 16, Qhp + (size_t)row * DHEAD + cb * 8);
        cp16(sbase + 2 * AT_TILE_B + (uint32_t)row * (AT_ROW * 2) + cb * 16,
             Qlp + (size_t)row * DHEAD + cb * 8);
    }
    cp_commit();
    asm volatile("cp.async.wait_group 0;" ::: "memory");
    __syncthreads();

    uint32_t qhi[4][4], qlo[4][4];
    {
        const int aOff = (wid * 16 + (lane & 15)) * AT_ROW + (lane >> 4) * 8;
#pragma unroll
        for (int kb = 0; kb < 4; kb++) {
            LDSM4(qhi[kb], sbase + (uint32_t)(aOff + kb * 16) * 2);
            LDSM4(qlo[kb], sbase + 2 * AT_TILE_B + (uint32_t)(aOff + kb * 16) * 2);
        }
    }
    __syncthreads();

    const int bOff = ((lane & 7) + ((lane >> 4) << 3)) * AT_ROW + (((lane >> 3) & 1) << 3);

    float o[8][4];
#pragma unroll
    for (int nb = 0; nb < 8; nb++)
#pragma unroll
        for (int r = 0; r < 4; r++) o[nb][r] = 0.0f;
    float m0 = -INFINITY, m1 = -INFINITY, l0 = 0.0f, l1 = 0.0f;

    const int qrow_lo = qt * 128 + wid * 16;
    const int r0g = qrow_lo + (lane >> 2);
    const int r1g = r0g + 8;

    // ---- prologue: key tile 0 -> stage 0 ----
    {
        const uint32_t st = sbase;
#pragma unroll
        for (int i = 0; i < 8; i++) {
            int chunk = tid + i * 256;
            int tile = chunk >> 9, within = chunk & 511;
            int row = within >> 3, cb = within & 7;
            uint32_t dst = st + tile * AT_TILE_B + (uint32_t)row * (AT_ROW * 2) + cb * 16;
            if (tile == 0)      cp16(dst, Khp + (size_t)row * DHEAD + cb * 8);
            else if (tile == 1) cp16(dst, Klp + (size_t)row * DHEAD + cb * 8);
            else if (tile == 2) cp16(dst, Vhp + (size_t)row * TSEQ + cb * 8);
            else                cp16(dst, Vlp + (size_t)row * TSEQ + cb * 8);
        }
        cp_commit();
    }

    for (int kt = 0; kt < nkt; kt++) {
        if (kt + 1 < nkt) {
            const uint32_t st = sbase + ((kt + 1) & 1) * AT_STAGE;
            const int koff = (kt + 1) * 64;
#pragma unroll
            for (int i = 0; i < 8; i++) {
                int chunk = tid + i * 256;
                int tile = chunk >> 9, within = chunk & 511;
                int row = within >> 3, cb = within & 7;
                uint32_t dst = st + tile * AT_TILE_B + (uint32_t)row * (AT_ROW * 2) + cb * 16;
                if (tile == 0)      cp16(dst, Khp + (size_t)(koff + row) * DHEAD + cb * 8);
                else if (tile == 1) cp16(dst, Klp + (size_t)(koff + row) * DHEAD + cb * 8);
                else if (tile == 2) cp16(dst, Vhp + (size_t)row * TSEQ + koff + cb * 8);
                else                cp16(dst, Vlp + (size_t)row * TSEQ + koff + cb * 8);
            }
            cp_commit();
            asm volatile("cp.async.wait_group 1;" ::: "memory");
        } else {
            asm volatile("cp.async.wait_group 0;" ::: "memory");
        }
        __syncthreads();

        if (kt * 64 <= qrow_lo + 15) {
            const uint32_t st = sbase + (kt & 1) * AT_STAGE;
            const uint32_t khb = st + 0 * AT_TILE_B + (uint32_t)bOff * 2;
            const uint32_t klb = st + 1 * AT_TILE_B + (uint32_t)bOff * 2;
            const uint32_t vhb = st + 2 * AT_TILE_B + (uint32_t)bOff * 2;
            const uint32_t vlb = st + 3 * AT_TILE_B + (uint32_t)bOff * 2;

            float s[8][4];
#pragma unroll
            for (int nb = 0; nb < 8; nb++)
#pragma unroll
                for (int r = 0; r < 4; r++) s[nb][r] = 0.0f;

#pragma unroll
            for (int kb = 0; kb < 4; kb++) {
                uint32_t kh[4][4], kl[4][4];
#pragma unroll
                for (int g = 0; g < 4; g++) {
                    LDSM4(kh[g], khb + (uint32_t)(g * 16 * AT_ROW + kb * 16) * 2);
                    LDSM4(kl[g], klb + (uint32_t)(g * 16 * AT_ROW + kb * 16) * 2);
                }
#pragma unroll
                for (int g = 0; g < 4; g++)
#pragma unroll
                    for (int half = 0; half < 2; half++) {
                        const int nb = 2 * g + half, h2 = half * 2;
                        MMA_BF16(s[nb], qhi[kb], kh[g][h2], kh[g][h2 + 1]);
                        MMA_BF16(s[nb], qhi[kb], kl[g][h2], kl[g][h2 + 1]);
                        MMA_BF16(s[nb], qlo[kb], kh[g][h2], kh[g][h2 + 1]);
                    }
            }

            if (kt * 64 + 63 > qrow_lo) {
#pragma unroll
                for (int nb = 0; nb < 8; nb++) {
                    int c = kt * 64 + nb * 8 + (lane & 3) * 2;
                    if (c > r0g)     s[nb][0] = -INFINITY;
                    if (c + 1 > r0g) s[nb][1] = -INFINITY;
                    if (c > r1g)     s[nb][2] = -INFINITY;
                    if (c + 1 > r1g) s[nb][3] = -INFINITY;
                }
            }

            float mx0 = -INFINITY, mx1 = -INFINITY;
#pragma unroll
            for (int nb = 0; nb < 8; nb++) {
                mx0 = fmaxf(mx0, fmaxf(s[nb][0], s[nb][1]));
                mx1 = fmaxf(mx1, fmaxf(s[nb][2], s[nb][3]));
            }
            mx0 = fmaxf(mx0, __shfl_xor_sync(0xffffffffu, mx0, 1));
            mx0 = fmaxf(mx0, __shfl_xor_sync(0xffffffffu, mx0, 2));
            mx1 = fmaxf(mx1, __shfl_xor_sync(0xffffffffu, mx1, 1));
            mx1 = fmaxf(mx1, __shfl_xor_sync(0xffffffffu, mx1, 2));

            float mn0 = fmaxf(m0, mx0), mn1 = fmaxf(m1, mx1);
            float c0 = __expf(m0 - mn0), c1 = __expf(m1 - mn1);
            m0 = mn0; m1 = mn1;

            float rs0 = 0.0f, rs1 = 0.0f;
#pragma unroll
            for (int nb = 0; nb < 8; nb++) {
                s[nb][0] = __expf(s[nb][0] - m0); rs0 += s[nb][0];
                s[nb][1] = __expf(s[nb][1] - m0); rs0 += s[nb][1];
                s[nb][2] = __expf(s[nb][2] - m1); rs1 += s[nb][2];
                s[nb][3] = __expf(s[nb][3] - m1); rs1 += s[nb][3];
            }
            rs0 += __shfl_xor_sync(0xffffffffu, rs0, 1);
            rs0 += __shfl_xor_sync(0xffffffffu, rs0, 2);
            rs1 += __shfl_xor_sync(0xffffffffu, rs1, 1);
            rs1 += __shfl_xor_sync(0xffffffffu, rs1, 2);
            l0 = l0 * c0 + rs0;
            l1 = l1 * c1 + rs1;
#pragma unroll
            for (int nb = 0; nb < 8; nb++) {
                o[nb][0] *= c0; o[nb][1] *= c0;
                o[nb][2] *= c1; o[nb][3] *= c1;
            }

#pragma unroll
            for (int kbp = 0; kbp < 4; kbp++) {
                uint32_t phi[4], plo[4];
                const int e = 2 * kbp;
                phi[0] = packbf2(s[e][0], s[e][1]);
                phi[1] = packbf2(s[e][2], s[e][3]);
                phi[2] = packbf2(s[e + 1][0], s[e + 1][1]);
                phi[3] = packbf2(s[e + 1][2], s[e + 1][3]);
                plo[0] = packlo2(s[e][0], s[e][1], phi[0]);
                plo[1] = packlo2(s[e][2], s[e][3], phi[1]);
                plo[2] = packlo2(s[e + 1][0], s[e + 1][1], phi[2]);
                plo[3] = packlo2(s[e + 1][2], s[e + 1][3], phi[3]);

                uint32_t vh[4][4], vl[4][4];
#pragma unroll
                for (int g = 0; g < 4; g++) {
                    LDSM4(vh[g], vhb + (uint32_t)(g * 16 * AT_ROW + kbp * 16) * 2);
                    LDSM4(vl[g], vlb + (uint32_t)(g * 16 * AT_ROW + kbp * 16) * 2);
                }
#pragma unroll
                for (int g = 0; g < 4; g++)
#pragma unroll
                    for (int half = 0; half < 2; half++) {
                        const int nbd = 2 * g + half, h2 = half * 2;
                        MMA_BF16(o[nbd], phi, vh[g][h2], vh[g][h2 + 1]);
                        MMA_BF16(o[nbd], plo, vh[g][h2], vh[g][h2 + 1]);
                        MMA_BF16(o[nbd], phi, vl[g][h2], vl[g][h2 + 1]);
                    }
            }
        }
        __syncthreads();
    }

    const float inv0 = 1.0f / l0, inv1 = 1.0f / l1;
    const size_t grow0 = (size_t)b * TSEQ + r0g;
    const size_t grow1 = grow0 + 8;
    const int colb = h * DHEAD + (lane & 3) * 2;
#pragma unroll
    for (int nbd = 0; nbd < 8; nbd++) {
        const int col = colb + nbd * 8;
        float f00 = o[nbd][0] * inv0, f01 = o[nbd][1] * inv0;
        float f10 = o[nbd][2] * inv1, f11 = o[nbd][3] * inv1;
        uint32_t h0 = packbf2(f00, f01), l0p = packlo2(f00, f01, h0);
        uint32_t h1 = packbf2(f10, f11), l1p = packlo2(f10, f11, h1);
        *(uint32_t*)(Oh + grow0 * DEMBD + col) = h0;
        *(uint32_t*)(Ol + grow0 * DEMBD + col) = l0p;
        *(uint32_t*)(Oh + grow1 * DEMBD + col) = h1;
        *(uint32_t*)(Ol + grow1 * DEMBD + col) = l1p;
    }
}

// ---------------------------------------------------------------------------
extern "C" void kernel_launch(void* const* d_in, const int* in_sizes, int n_in,
                              void* d_out, int out_size) {
    const float* x  = (const float*)d_in[0];
    const float* W1 = (const float*)d_in[1];
    const float* b1 = (const float*)d_in[2];
    const float* W2 = (const float*)d_in[3];
    const float* b2 = (const float*)d_in[4];
    float* out = (float*)d_out;

    float* kqv;
    __nv_bfloat16 *A1h, *A1l, *A2h, *A2l, *W1h, *W1l, *W2h, *W2l;
    __nv_bfloat16 *Qh, *Ql, *Kh, *Kl, *Vh, *Vl;
    cudaGetSymbolAddress((void**)&kqv, g_kqv);
    cudaGetSymbolAddress((void**)&A1h, g_A1hi);
    cudaGetSymbolAddress((void**)&A1l, g_A1lo);
    cudaGetSymbolAddress((void**)&A2h, g_A2hi);
    cudaGetSymbolAddress((void**)&A2l, g_A2lo);
    cudaGetSymbolAddress((void**)&W1h, g_W1Thi);
    cudaGetSymbolAddress((void**)&W1l, g_W1Tlo);
    cudaGetSymbolAddress((void**)&W2h, g_W2Thi);
    cudaGetSymbolAddress((void**)&W2l, g_W2Tlo);
    cudaGetSymbolAddress((void**)&Qh, g_Qhi);
    cudaGetSymbolAddress((void**)&Ql, g_Qlo);
    cudaGetSymbolAddress((void**)&Kh, g_Khi);
    cudaGetSymbolAddress((void**)&Kl, g_Klo);
    cudaGetSymbolAddress((void**)&Vh, g_Vthi);
    cudaGetSymbolAddress((void**)&Vl, g_Vtlo);

    cudaFuncSetAttribute(gemm_bf16_mma, cudaFuncAttributeMaxDynamicSharedMemorySize, GEMM_SMEM);
    cudaFuncSetAttribute(attn_tc, cudaFuncAttributeMaxDynamicSharedMemorySize, ATTN_SMEM);

    // 0) input conversions
    {
        int n4 = MROWS * DEMBD / 4;
        split_f32<<<(n4 + 255) / 256, 256>>>(x, A1h, A1l, n4);
        transpose_split<<<dim3(KQV_N / 32, DEMBD / 32), dim3(32, 8)>>>(W1, W1h, W1l, DEMBD, KQV_N);
        transpose_split<<<dim3(DEMBD / 32, DEMBD / 32), dim3(32, 8)>>>(W2, W2h, W2l, DEMBD, DEMBD);
    }
    // 1) kqv = x @ W1 + b1  (tensor cores)
    gemm_bf16_mma<<<dim3(KQV_N / 128, MROWS / 128), 256, GEMM_SMEM>>>(
        A1h, A1l, W1h, W1l, b1, kqv, MROWS, KQV_N, DEMBD);
    // 2a) kqv -> per-head bf16 hi/lo operands
    qk_convert<<<4096, 256>>>(kqv, Qh, Ql, Kh, Kl);
    v_convert<<<dim3(TSEQ / 32, DHEAD / 32, BH), dim3(32, 8)>>>(kqv, Vh, Vl);
    // 2b) causal attention (tensor cores), writes A2 hi/lo directly
    attn_tc<<<dim3(TSEQ / 128, NHEADS, BS), 256, ATTN_SMEM>>>(
        Qh, Ql, Kh, Kl, Vh, Vl, A2h, A2l);
    // 3) out = att @ W2 + b2  (tensor cores)
    gemm_bf16_mma<<<dim3(DEMBD / 128, MROWS / 128), 256, GEMM_SMEM>>>(
        A2h, A2l, W2h, W2l, b2, out, MROWS, DEMBD, DEMBD);
}

// round 8
// speedup vs baseline: 2.6532x; 1.0187x over previous
#include <cuda_runtime.h>
#include <cuda_bf16.h>
#include <math.h>
#include <stdint.h>

// Problem constants
#define BS      2
#define TSEQ    2048
#define DEMBD   1024
#define NHEADS  16
#define DHEAD   64
#define MROWS   (BS * TSEQ)      // 4096
#define KQV_N   (3 * DEMBD)      // 3072
#define BH      (BS * NHEADS)    // 32

// ---------------------------------------------------------------------------
// Scratch (__device__ globals; allocation-free rule)
// ---------------------------------------------------------------------------
__device__ __nv_bfloat16 g_A1hi[MROWS * DEMBD];
__device__ __nv_bfloat16 g_A1lo[MROWS * DEMBD];
__device__ __nv_bfloat16 g_A2hi[MROWS * DEMBD];   // written by attention
__device__ __nv_bfloat16 g_A2lo[MROWS * DEMBD];
__device__ __nv_bfloat16 g_W1Thi[KQV_N * DEMBD];
__device__ __nv_bfloat16 g_W1Tlo[KQV_N * DEMBD];
__device__ __nv_bfloat16 g_W2Thi[DEMBD * DEMBD];
__device__ __nv_bfloat16 g_W2Tlo[DEMBD * DEMBD];

// Attention operands, per-head layouts (bf16 hi/lo) — written by GEMM1 epilogue
__device__ __nv_bfloat16 g_Qhi[BH * TSEQ * DHEAD];  // [bh][t][d], pre-scaled
__device__ __nv_bfloat16 g_Qlo[BH * TSEQ * DHEAD];
__device__ __nv_bfloat16 g_Khi[BH * TSEQ * DHEAD];  // [bh][t][d]
__device__ __nv_bfloat16 g_Klo[BH * TSEQ * DHEAD];
__device__ __nv_bfloat16 g_Vthi[BH * DHEAD * TSEQ]; // [bh][d][t]  (transposed)
__device__ __nv_bfloat16 g_Vtlo[BH * DHEAD * TSEQ];

// ---------------------------------------------------------------------------
// PTX helpers (baseline ISA only)
// ---------------------------------------------------------------------------
__device__ __forceinline__ uint32_t smem_u32(const void* p) {
    uint32_t a;
    asm("{ .reg .u64 t; cvta.to.shared.u64 t, %1; cvt.u32.u64 %0, t; }" : "=r"(a) : "l"(p));
    return a;
}
__device__ __forceinline__ void cp16(uint32_t dst, const void* src) {
    asm volatile("cp.async.cg.shared.global [%0], [%1], 16;"
                 :: "r"(dst), "l"(__cvta_generic_to_global(src)));
}
__device__ __forceinline__ void cp_commit() { asm volatile("cp.async.commit_group;" ::: "memory"); }

#define LDSM4(r, addr) \
    asm volatile("ldmatrix.sync.aligned.m8n8.x4.shared.b16 {%0,%1,%2,%3}, [%4];" \
        : "=r"((r)[0]), "=r"((r)[1]), "=r"((r)[2]), "=r"((r)[3]) : "r"(addr))

#define MMA_BF16(d, a, b0, b1) \
    asm volatile("mma.sync.aligned.m16n8k16.row.col.f32.bf16.bf16.f32 " \
        "{%0,%1,%2,%3}, {%4,%5,%6,%7}, {%8,%9}, {%0,%1,%2,%3};" \
        : "+f"((d)[0]), "+f"((d)[1]), "+f"((d)[2]), "+f"((d)[3]) \
        : "r"((a)[0]), "r"((a)[1]), "r"((a)[2]), "r"((a)[3]), "r"(b0), "r"(b1))

// pack two fp32 into bf16x2: low half <- lo, high half <- hi
__device__ __forceinline__ uint32_t packbf2(float lo, float hi) {
    uint32_t r;
    asm("cvt.rn.bf16x2.f32 %0, %1, %2;" : "=r"(r) : "f"(hi), "f"(lo));
    return r;
}
// residual (lo-part) pack given the hi-pack
__device__ __forceinline__ uint32_t packlo2(float lo, float hi, uint32_t hp) {
    __nv_bfloat162 hv = *reinterpret_cast<__nv_bfloat162*>(&hp);
    return packbf2(lo - __bfloat162float(hv.x), hi - __bfloat162float(hv.y));
}

// ---------------------------------------------------------------------------
// fp32 -> bf16 hi/lo split (elementwise, float4)  [x -> A1]
// ---------------------------------------------------------------------------
__global__ void split_f32(const float* __restrict__ in, __nv_bfloat16* __restrict__ hi,
                          __nv_bfloat16* __restrict__ lo, int n4) {
    int i = blockIdx.x * blockDim.x + threadIdx.x;
    if (i >= n4) return;
    float4 v = ((const float4*)in)[i];
    uint32_t h0 = packbf2(v.x, v.y), h1 = packbf2(v.z, v.w);
    uint32_t l0 = packlo2(v.x, v.y, h0), l1 = packlo2(v.z, v.w, h1);
    ((uint32_t*)hi)[i * 2 + 0] = h0;
    ((uint32_t*)hi)[i * 2 + 1] = h1;
    ((uint32_t*)lo)[i * 2 + 0] = l0;
    ((uint32_t*)lo)[i * 2 + 1] = l1;
}

// ---------------------------------------------------------------------------
// W[K][N] fp32 -> W^T[N][K] bf16 hi/lo (tiled transpose)
// ---------------------------------------------------------------------------
__global__ void transpose_split(const float* __restrict__ W, __nv_bfloat16* __restrict__ hiT,
                                __nv_bfloat16* __restrict__ loT, int K, int N) {
    __shared__ float t[32][33];
    int n = blockIdx.x * 32 + threadIdx.x;
    int k0 = blockIdx.y * 32;
#pragma unroll
    for (int i = 0; i < 32; i += 8)
        t[threadIdx.y + i][threadIdx.x] = W[(size_t)(k0 + threadIdx.y + i) * N + n];
    __syncthreads();
    int kk = k0 + threadIdx.x;
#pragma unroll
    for (int i = 0; i < 32; i += 8) {
        int nn = blockIdx.x * 32 + threadIdx.y + i;
        float v = t[threadIdx.x][threadIdx.y + i];
        __nv_bfloat16 h = __float2bfloat16(v);
        __nv_bfloat16 l = __float2bfloat16(v - __bfloat162float(h));
        hiT[(size_t)nn * K + kk] = h;
        loT[(size_t)nn * K + kk] = l;
    }
}

// ---------------------------------------------------------------------------
// Shared GEMM tiling constants
// ---------------------------------------------------------------------------
#define BK        32
#define LDS_ROW   40
#define TILE_H    (128 * LDS_ROW)
#define TILE_B    (TILE_H * 2)
#define STAGE_B   (4 * TILE_B)
#define GEMM_SMEM (2 * STAGE_B)            // 81920 B -> 2 CTAs/SM

__device__ __forceinline__ void load_tile(uint32_t tb, const __nv_bfloat16* sp, int K, int tid) {
#pragma unroll
    for (int i = 0; i < 2; i++) {
        int chunk = tid + i * 256;
        int row = chunk >> 2, cb = chunk & 3;
        cp16(tb + (uint32_t)row * (LDS_ROW * 2) + (uint32_t)cb * 16,
             sp + (size_t)row * K + cb * 8);
    }
}

// Mainloop shared by both GEMM kernels: accumulates the 128x128 tile.
__device__ __forceinline__ void gemm_mainloop(
    uint32_t sbase, const __nv_bfloat16* Ah0, const __nv_bfloat16* Al0,
    const __nv_bfloat16* Bh0, const __nv_bfloat16* Bl0, int K, int tid,
    int aOff, int bOff, float acc[4][4][4]) {

    const int NSLAB = K / BK;
    {
        const uint32_t st = sbase;
        load_tile(st + 0 * TILE_B, Ah0, K, tid);
        load_tile(st + 1 * TILE_B, Al0, K, tid);
        load_tile(st + 2 * TILE_B, Bh0, K, tid);
        load_tile(st + 3 * TILE_B, Bl0, K, tid);
        cp_commit();
    }

    for (int s = 0; s < NSLAB; s++) {
        if (s + 1 < NSLAB) {
            const uint32_t st = sbase + ((s + 1) & 1) * STAGE_B;
            const int k0 = (s + 1) * BK;
            load_tile(st + 0 * TILE_B, Ah0 + k0, K, tid);
            load_tile(st + 1 * TILE_B, Al0 + k0, K, tid);
            load_tile(st + 2 * TILE_B, Bh0 + k0, K, tid);
            load_tile(st + 3 * TILE_B, Bl0 + k0, K, tid);
            cp_commit();
            asm volatile("cp.async.wait_group 1;" ::: "memory");
        } else {
            asm volatile("cp.async.wait_group 0;" ::: "memory");
        }
        __syncthreads();

        const uint32_t st = sbase + (s & 1) * STAGE_B;
        const uint32_t ahb = st + 0 * TILE_B + (uint32_t)aOff * 2;
        const uint32_t alb = st + 1 * TILE_B + (uint32_t)aOff * 2;
        const uint32_t bhb = st + 2 * TILE_B + (uint32_t)bOff * 2;
        const uint32_t blb = st + 3 * TILE_B + (uint32_t)bOff * 2;

#pragma unroll
        for (int kk = 0; kk < BK; kk += 16) {
            uint32_t bh[2][4], bl[2][4];
#pragma unroll
            for (int g = 0; g < 2; g++) {
                LDSM4(bh[g], bhb + (g * 16 * LDS_ROW + kk) * 2);
                LDSM4(bl[g], blb + (g * 16 * LDS_ROW + kk) * 2);
            }
#pragma unroll
            for (int mb = 0; mb < 4; mb++) {
                uint32_t ah[4], al[4];
                LDSM4(ah, ahb + (mb * 16 * LDS_ROW + kk) * 2);
                LDSM4(al, alb + (mb * 16 * LDS_ROW + kk) * 2);
#pragma unroll
                for (int nb = 0; nb < 4; nb++) {
                    const int g = nb >> 1, h2 = (nb & 1) * 2;
                    MMA_BF16(acc[mb][nb], ah, bh[g][h2], bh[g][h2 + 1]);
                    MMA_BF16(acc[mb][nb], ah, bl[g][h2], bl[g][h2 + 1]);
                    MMA_BF16(acc[mb][nb], al, bh[g][h2], bh[g][h2 + 1]);
                }
            }
        }
        __syncthreads();
    }
}

// ---------------------------------------------------------------------------
// GEMM2: generic fp32-output GEMM + bias (att @ W2 + b2 -> out)
// ---------------------------------------------------------------------------
__global__ __launch_bounds__(256, 2)
void gemm_bf16_mma(const __nv_bfloat16* __restrict__ Ah, const __nv_bfloat16* __restrict__ Al,
                   const __nv_bfloat16* __restrict__ Bh, const __nv_bfloat16* __restrict__ Bl,
                   const float* __restrict__ bias, float* __restrict__ C,
                   int M, int N, int K) {
    extern __shared__ char smem[];
    const uint32_t sbase = smem_u32(smem);

    const int tid  = threadIdx.x;
    const int wid  = tid >> 5;
    const int lane = tid & 31;
    const int m0 = blockIdx.y * 128;
    const int n0 = blockIdx.x * 128;
    const int wm = (wid & 1) * 64;
    const int wn = (wid >> 1) * 32;

    const int aOff = (wm + (lane & 15)) * LDS_ROW + (lane >> 4) * 8;
    const int bOff = (wn + (lane & 7) + ((lane >> 4) << 3)) * LDS_ROW + (((lane >> 3) & 1) << 3);

    float acc[4][4][4];
#pragma unroll
    for (int mb = 0; mb < 4; mb++)
#pragma unroll
        for (int nb = 0; nb < 4; nb++)
#pragma unroll
            for (int r = 0; r < 4; r++) acc[mb][nb][r] = 0.0f;

    gemm_mainloop(sbase, Ah + (size_t)m0 * K, Al + (size_t)m0 * K,
                  Bh + (size_t)n0 * K, Bl + (size_t)n0 * K, K, tid, aOff, bOff, acc);

    const int rBase = m0 + wm + (lane >> 2);
    const int cBase = n0 + wn + (lane & 3) * 2;
#pragma unroll
    for (int mb = 0; mb < 4; mb++) {
#pragma unroll
        for (int nb = 0; nb < 4; nb++) {
            const int col = cBase + nb * 8;
            const float bx = __ldg(bias + col);
            const float by = __ldg(bias + col + 1);
            float* p0 = C + (size_t)(rBase + mb * 16) * N + col;
            float* p1 = C + (size_t)(rBase + mb * 16 + 8) * N + col;
            *(float2*)p0 = make_float2(acc[mb][nb][0] + bx, acc[mb][nb][1] + by);
            *(float2*)p1 = make_float2(acc[mb][nb][2] + bx, acc[mb][nb][3] + by);
        }
    }
}

// ---------------------------------------------------------------------------
// GEMM1 with fused QKV epilogue: x @ W1 + b1, written directly as per-head
// bf16 hi/lo attention operands (Q scaled; V transposed via smem staging).
// Each CTA's 128 columns sit entirely inside one of the K/Q/V thirds.
// ---------------------------------------------------------------------------
#define VP 132   // fp32 smem pitch for V transpose staging (128 + 4 pad)

__global__ __launch_bounds__(256, 2)
void gemm1_qkv(const __nv_bfloat16* __restrict__ Ah, const __nv_bfloat16* __restrict__ Al,
               const __nv_bfloat16* __restrict__ Bh, const __nv_bfloat16* __restrict__ Bl,
               const float* __restrict__ bias,
               __nv_bfloat16* __restrict__ Qh, __nv_bfloat16* __restrict__ Ql,
               __nv_bfloat16* __restrict__ Kh, __nv_bfloat16* __restrict__ Kl,
               __nv_bfloat16* __restrict__ Vh, __nv_bfloat16* __restrict__ Vl) {
    extern __shared__ char smem[];
    const uint32_t sbase = smem_u32(smem);
    const int K = DEMBD;

    const int tid  = threadIdx.x;
    const int wid  = tid >> 5;
    const int lane = tid & 31;
    const int m0 = blockIdx.y * 128;
    const int n0 = blockIdx.x * 128;
    const int wm = (wid & 1) * 64;
    const int wn = (wid >> 1) * 32;

    const int aOff = (wm + (lane & 15)) * LDS_ROW + (lane >> 4) * 8;
    const int bOff = (wn + (lane & 7) + ((lane >> 4) << 3)) * LDS_ROW + (((lane >> 3) & 1) << 3);

    float acc[4][4][4];
#pragma unroll
    for (int mb = 0; mb < 4; mb++)
#pragma unroll
        for (int nb = 0; nb < 4; nb++)
#pragma unroll
            for (int r = 0; r < 4; r++) acc[mb][nb][r] = 0.0f;

    gemm_mainloop(sbase, Ah + (size_t)m0 * K, Al + (size_t)m0 * K,
                  Bh + (size_t)n0 * K, Bl + (size_t)n0 * K, K, tid, aOff, bOff, acc);

    const int part = n0 >> 10;              // 0 = K, 1 = Q, 2 = V
    const int b    = m0 >> 11;              // batch
    const int t0   = m0 & 2047;             // t of tile row 0
    const int cp0  = n0 & 1023;             // col offset within part

    if (part < 2) {
        // ---- K / Q: direct per-head [bh][t][64] bf16 hi/lo stores ----
        __nv_bfloat16* Dh = (part == 0) ? Kh : Qh;
        __nv_bfloat16* Dl = (part == 0) ? Kl : Ql;
        const float qscale = (part == 1) ? 0.125f : 1.0f;
        const int rLoc = wm + (lane >> 2);
        const int cLoc = wn + (lane & 3) * 2;
#pragma unroll
        for (int mb = 0; mb < 4; mb++) {
#pragma unroll
            for (int nb = 0; nb < 4; nb++) {
                const int c = cLoc + nb * 8;              // 0..127 local
                const int cpart = cp0 + c;                // 0..1023 within part
                const int h = cpart >> 6, d = cpart & 63;
                const float bx = __ldg(bias + n0 + c);
                const float by = __ldg(bias + n0 + c + 1);
                float f0 = (acc[mb][nb][0] + bx) * qscale;
                float f1 = (acc[mb][nb][1] + by) * qscale;
                float f2 = (acc[mb][nb][2] + bx) * qscale;
                float f3 = (acc[mb][nb][3] + by) * qscale;
                const size_t base =
                    ((size_t)(b * NHEADS + h) * TSEQ);
                const int tA = t0 + rLoc + mb * 16;
                const int tB = tA + 8;
                uint32_t h0 = packbf2(f0, f1), l0 = packlo2(f0, f1, h0);
                uint32_t h1 = packbf2(f2, f3), l1 = packlo2(f2, f3, h1);
                *(uint32_t*)(Dh + (base + tA) * DHEAD + d) = h0;
                *(uint32_t*)(Dl + (base + tA) * DHEAD + d) = l0;
                *(uint32_t*)(Dh + (base + tB) * DHEAD + d) = h1;
                *(uint32_t*)(Dl + (base + tB) * DHEAD + d) = l1;
            }
        }
    } else {
        // ---- V: stage (bias-added fp32) into smem as [col][row], then write
        //      transposed per-head [bh][d][t] bf16 hi/lo, coalesced over t ----
        float* sv = (float*)smem;
        const int rLoc = wm + (lane >> 2);
        const int cLoc = wn + (lane & 3) * 2;
#pragma unroll
        for (int mb = 0; mb < 4; mb++) {
#pragma unroll
            for (int nb = 0; nb < 4; nb++) {
                const int c = cLoc + nb * 8;
                const float bx = __ldg(bias + n0 + c);
                const float by = __ldg(bias + n0 + c + 1);
                const int rA = rLoc + mb * 16, rB = rA + 8;
                sv[(c + 0) * VP + rA] = acc[mb][nb][0] + bx;
                sv[(c + 1) * VP + rA] = acc[mb][nb][1] + by;
                sv[(c + 0) * VP + rB] = acc[mb][nb][2] + bx;
                sv[(c + 1) * VP + rB] = acc[mb][nb][3] + by;
            }
        }
        __syncthreads();
#pragma unroll
        for (int i = 0; i < 16; i++) {
            const int c = (tid >> 5) + i * 8;            // 0..127 local col
            const int cpart = cp0 + c;
            const int h = cpart >> 6, d = cpart & 63;
            float4 v = *(float4*)&sv[c * VP + lane * 4];
            uint32_t hA = packbf2(v.x, v.y), lA = packlo2(v.x, v.y, hA);
            uint32_t hB = packbf2(v.z, v.w), lB = packlo2(v.z, v.w, hB);
            const size_t dst =
                ((size_t)(b * NHEADS + h) * DHEAD + d) * TSEQ + t0 + lane * 4;
            *(uint2*)(Vh + dst) = make_uint2(hA, hB);
            *(uint2*)(Vl + dst) = make_uint2(lA, lB);
        }
    }
}

// ---------------------------------------------------------------------------
// Tensor-core causal flash attention (bf16 hi/lo, fp32 softmax) — unchanged.
// ---------------------------------------------------------------------------
#define AT_ROW    72                      // 64 + 8 pad halves
#define AT_TILE_B (64 * AT_ROW * 2)       // 9216 B
#define AT_STAGE  (4 * AT_TILE_B)         // Khi,Klo,Vhi,Vlo = 36864 B
#define ATTN_SMEM (2 * AT_STAGE)          // 73728 B

__global__ __launch_bounds__(256)
void attn_tc(const __nv_bfloat16* __restrict__ Qh, const __nv_bfloat16* __restrict__ Ql,
             const __nv_bfloat16* __restrict__ Kh, const __nv_bfloat16* __restrict__ Kl,
             const __nv_bfloat16* __restrict__ Vh, const __nv_bfloat16* __restrict__ Vl,
             __nv_bfloat16* __restrict__ Oh, __nv_bfloat16* __restrict__ Ol) {
    extern __shared__ char smem[];
    const uint32_t sbase = smem_u32(smem);

    const int tid  = threadIdx.x;
    const int wid  = tid >> 5;
    const int lane = tid & 31;
    const int qt = (gridDim.x - 1) - blockIdx.x;       // heavy tiles first
    const int h  = blockIdx.y;
    const int b  = blockIdx.z;
    const int bh = b * NHEADS + h;
    const int nkt = 2 * qt + 2;

    const __nv_bfloat16* Qhp = Qh + ((size_t)bh * TSEQ + qt * 128) * DHEAD;
    const __nv_bfloat16* Qlp = Ql + ((size_t)bh * TSEQ + qt * 128) * DHEAD;
    const __nv_bfloat16* Khp = Kh + (size_t)bh * TSEQ * DHEAD;
    const __nv_bfloat16* Klp = Kl + (size_t)bh * TSEQ * DHEAD;
    const __nv_bfloat16* Vhp = Vh + (size_t)bh * DHEAD * TSEQ;
    const __nv_bfloat16* Vlp = Vl + (size_t)bh * DHEAD * TSEQ;

#pragma unroll
    for (int i = 0; i < 4; i++) {
        int chunk = tid + i * 256;
        int row = chunk >> 3, cb = chunk & 7;
        cp16(sbase + (uint32_t)row * (AT_ROW * 2) + cb * 16, Qhp + (size_t)row * DHEAD + cb * 8);
        cp16(sbase + 2 * AT_TILE_B + (uint32_t)row * (AT_ROW * 2) + cb * 16,
             Qlp + (size_t)row * DHEAD + cb * 8);
    }
    cp_commit();
    asm volatile("cp.async.wait_group 0;" ::: "memory");
    __syncthreads();

    uint32_t qhi[4][4], qlo[4][4];
    {
        const int aOff = (wid * 16 + (lane & 15)) * AT_ROW + (lane >> 4) * 8;
#pragma unroll
        for (int kb = 0; kb < 4; kb++) {
            LDSM4(qhi[kb], sbase + (uint32_t)(aOff + kb * 16) * 2);
            LDSM4(qlo[kb], sbase + 2 * AT_TILE_B + (uint32_t)(aOff + kb * 16) * 2);
        }
    }
    __syncthreads();

    const int bOff = ((lane & 7) + ((lane >> 4) << 3)) * AT_ROW + (((lane >> 3) & 1) << 3);

    float o[8][4];
#pragma unroll
    for (int nb = 0; nb < 8; nb++)
#pragma unroll
        for (int r = 0; r < 4; r++) o[nb][r] = 0.0f;
    float m0 = -INFINITY, m1 = -INFINITY, l0 = 0.0f, l1 = 0.0f;

    const int qrow_lo = qt * 128 + wid * 16;
    const int r0g = qrow_lo + (lane >> 2);
    const int r1g = r0g + 8;

    {
        const uint32_t st = sbase;
#pragma unroll
        for (int i = 0; i < 8; i++) {
            int chunk = tid + i * 256;
            int tile = chunk >> 9, within = chunk & 511;
            int row = within >> 3, cb = within & 7;
            uint32_t dst = st + tile * AT_TILE_B + (uint32_t)row * (AT_ROW * 2) + cb * 16;
            if (tile == 0)      cp16(dst, Khp + (size_t)row * DHEAD + cb * 8);
            else if (tile == 1) cp16(dst, Klp + (size_t)row * DHEAD + cb * 8);
            else if (tile == 2) cp16(dst, Vhp + (size_t)row * TSEQ + cb * 8);
            else                cp16(dst, Vlp + (size_t)row * TSEQ + cb * 8);
        }
        cp_commit();
    }

    for (int kt = 0; kt < nkt; kt++) {
        if (kt + 1 < nkt) {
            const uint32_t st = sbase + ((kt + 1) & 1) * AT_STAGE;
            const int koff = (kt + 1) * 64;
#pragma unroll
            for (int i = 0; i < 8; i++) {
                int chunk = tid + i * 256;
                int tile = chunk >> 9, within = chunk & 511;
                int row = within >> 3, cb = within & 7;
                uint32_t dst = st + tile * AT_TILE_B + (uint32_t)row * (AT_ROW * 2) + cb * 16;
                if (tile == 0)      cp16(dst, Khp + (size_t)(koff + row) * DHEAD + cb * 8);
                else if (tile == 1) cp16(dst, Klp + (size_t)(koff + row) * DHEAD + cb * 8);
                else if (tile == 2) cp16(dst, Vhp + (size_t)row * TSEQ + koff + cb * 8);
                else                cp16(dst, Vlp + (size_t)row * TSEQ + koff + cb * 8);
            }
            cp_commit();
            asm volatile("cp.async.wait_group 1;" ::: "memory");
        } else {
            asm volatile("cp.async.wait_group 0;" ::: "memory");
        }
        __syncthreads();

        if (kt * 64 <= qrow_lo + 15) {
            const uint32_t st = sbase + (kt & 1) * AT_STAGE;
            const uint32_t khb = st + 0 * AT_TILE_B + (uint32_t)bOff * 2;
            const uint32_t klb = st + 1 * AT_TILE_B + (uint32_t)bOff * 2;
            const uint32_t vhb = st + 2 * AT_TILE_B + (uint32_t)bOff * 2;
            const uint32_t vlb = st + 3 * AT_TILE_B + (uint32_t)bOff * 2;

            float s[8][4];
#pragma unroll
            for (int nb = 0; nb < 8; nb++)
#pragma unroll
                for (int r = 0; r < 4; r++) s[nb][r] = 0.0f;

#pragma unroll
            for (int kb = 0; kb < 4; kb++) {
                uint32_t kh[4][4], kl[4][4];
#pragma unroll
                for (int g = 0; g < 4; g++) {
                    LDSM4(kh[g], khb + (uint32_t)(g * 16 * AT_ROW + kb * 16) * 2);
                    LDSM4(kl[g], klb + (uint32_t)(g * 16 * AT_ROW + kb * 16) * 2);
                }
#pragma unroll
                for (int g = 0; g < 4; g++)
#pragma unroll
                    for (int half = 0; half < 2; half++) {
                        const int nb = 2 * g + half, h2 = half * 2;
                        MMA_BF16(s[nb], qhi[kb], kh[g][h2], kh[g][h2 + 1]);
                        MMA_BF16(s[nb], qhi[kb], kl[g][h2], kl[g][h2 + 1]);
                        MMA_BF16(s[nb], qlo[kb], kh[g][h2], kh[g][h2 + 1]);
                    }
            }

            if (kt * 64 + 63 > qrow_lo) {
#pragma unroll
                for (int nb = 0; nb < 8; nb++) {
                    int c = kt * 64 + nb * 8 + (lane & 3) * 2;
                    if (c > r0g)     s[nb][0] = -INFINITY;
                    if (c + 1 > r0g) s[nb][1] = -INFINITY;
                    if (c > r1g)     s[nb][2] = -INFINITY;
                    if (c + 1 > r1g) s[nb][3] = -INFINITY;
                }
            }

            float mx0 = -INFINITY, mx1 = -INFINITY;
#pragma unroll
            for (int nb = 0; nb < 8; nb++) {
                mx0 = fmaxf(mx0, fmaxf(s[nb][0], s[nb][1]));
                mx1 = fmaxf(mx1, fmaxf(s[nb][2], s[nb][3]));
            }
            mx0 = fmaxf(mx0, __shfl_xor_sync(0xffffffffu, mx0, 1));
            mx0 = fmaxf(mx0, __shfl_xor_sync(0xffffffffu, mx0, 2));
            mx1 = fmaxf(mx1, __shfl_xor_sync(0xffffffffu, mx1, 1));
            mx1 = fmaxf(mx1, __shfl_xor_sync(0xffffffffu, mx1, 2));

            float mn0 = fmaxf(m0, mx0), mn1 = fmaxf(m1, mx1);
            float c0 = __expf(m0 - mn0), c1 = __expf(m1 - mn1);
            m0 = mn0; m1 = mn1;

            float rs0 = 0.0f, rs1 = 0.0f;
#pragma unroll
            for (int nb = 0; nb < 8; nb++) {
                s[nb][0] = __expf(s[nb][0] - m0); rs0 += s[nb][0];
                s[nb][1] = __expf(s[nb][1] - m0); rs0 += s[nb][1];
                s[nb][2] = __expf(s[nb][2] - m1); rs1 += s[nb][2];
                s[nb][3] = __expf(s[nb][3] - m1); rs1 += s[nb][3];
            }
            rs0 += __shfl_xor_sync(0xffffffffu, rs0, 1);
            rs0 += __shfl_xor_sync(0xffffffffu, rs0, 2);
            rs1 += __shfl_xor_sync(0xffffffffu, rs1, 1);
            rs1 += __shfl_xor_sync(0xffffffffu, rs1, 2);
            l0 = l0 * c0 + rs0;
            l1 = l1 * c1 + rs1;
#pragma unroll
            for (int nb = 0; nb < 8; nb++) {
                o[nb][0] *= c0; o[nb][1] *= c0;
                o[nb][2] *= c1; o[nb][3] *= c1;
            }

#pragma unroll
            for (int kbp = 0; kbp < 4; kbp++) {
                uint32_t phi[4], plo[4];
                const int e = 2 * kbp;
                phi[0] = packbf2(s[e][0], s[e][1]);
                phi[1] = packbf2(s[e][2], s[e][3]);
                phi[2] = packbf2(s[e + 1][0], s[e + 1][1]);
                phi[3] = packbf2(s[e + 1][2], s[e + 1][3]);
                plo[0] = packlo2(s[e][0], s[e][1], phi[0]);
                plo[1] = packlo2(s[e][2], s[e][3], phi[1]);
                plo[2] = packlo2(s[e + 1][0], s[e + 1][1], phi[2]);
                plo[3] = packlo2(s[e + 1][2], s[e + 1][3], phi[3]);

                uint32_t vh[4][4], vl[4][4];
#pragma unroll
                for (int g = 0; g < 4; g++) {
                    LDSM4(vh[g], vhb + (uint32_t)(g * 16 * AT_ROW + kbp * 16) * 2);
                    LDSM4(vl[g], vlb + (uint32_t)(g * 16 * AT_ROW + kbp * 16) * 2);
                }
#pragma unroll
                for (int g = 0; g < 4; g++)
#pragma unroll
                    for (int half = 0; half < 2; half++) {
                        const int nbd = 2 * g + half, h2 = half * 2;
                        MMA_BF16(o[nbd], phi, vh[g][h2], vh[g][h2 + 1]);
                        MMA_BF16(o[nbd], plo, vh[g][h2], vh[g][h2 + 1]);
                        MMA_BF16(o[nbd], phi, vl[g][h2], vl[g][h2 + 1]);
                    }
            }
        }
        __syncthreads();
    }

    const float inv0 = 1.0f / l0, inv1 = 1.0f / l1;
    const size_t grow0 = (size_t)b * TSEQ + r0g;
    const size_t grow1 = grow0 + 8;
    const int colb = h * DHEAD + (lane & 3) * 2;
#pragma unroll
    for (int nbd = 0; nbd < 8; nbd++) {
        const int col = colb + nbd * 8;
        float f00 = o[nbd][0] * inv0, f01 = o[nbd][1] * inv0;
        float f10 = o[nbd][2] * inv1, f11 = o[nbd][3] * inv1;
        uint32_t h0 = packbf2(f00, f01), l0p = packlo2(f00, f01, h0);
        uint32_t h1 = packbf2(f10, f11), l1p = packlo2(f10, f11, h1);
        *(uint32_t*)(Oh + grow0 * DEMBD + col) = h0;
        *(uint32_t*)(Ol + grow0 * DEMBD + col) = l0p;
        *(uint32_t*)(Oh + grow1 * DEMBD + col) = h1;
        *(uint32_t*)(Ol + grow1 * DEMBD + col) = l1p;
    }
}

// ---------------------------------------------------------------------------
extern "C" void kernel_launch(void* const* d_in, const int* in_sizes, int n_in,
                              void* d_out, int out_size) {
    const float* x  = (const float*)d_in[0];
    const float* W1 = (const float*)d_in[1];
    const float* b1 = (const float*)d_in[2];
    const float* W2 = (const float*)d_in[3];
    const float* b2 = (const float*)d_in[4];
    float* out = (float*)d_out;

    __nv_bfloat16 *A1h, *A1l, *A2h, *A2l, *W1h, *W1l, *W2h, *W2l;
    __nv_bfloat16 *Qh, *Ql, *Kh, *Kl, *Vh, *Vl;
    cudaGetSymbolAddress((void**)&A1h, g_A1hi);
    cudaGetSymbolAddress((void**)&A1l, g_A1lo);
    cudaGetSymbolAddress((void**)&A2h, g_A2hi);
    cudaGetSymbolAddress((void**)&A2l, g_A2lo);
    cudaGetSymbolAddress((void**)&W1h, g_W1Thi);
    cudaGetSymbolAddress((void**)&W1l, g_W1Tlo);
    cudaGetSymbolAddress((void**)&W2h, g_W2Thi);
    cudaGetSymbolAddress((void**)&W2l, g_W2Tlo);
    cudaGetSymbolAddress((void**)&Qh, g_Qhi);
    cudaGetSymbolAddress((void**)&Ql, g_Qlo);
    cudaGetSymbolAddress((void**)&Kh, g_Khi);
    cudaGetSymbolAddress((void**)&Kl, g_Klo);
    cudaGetSymbolAddress((void**)&Vh, g_Vthi);
    cudaGetSymbolAddress((void**)&Vl, g_Vtlo);

    cudaFuncSetAttribute(gemm_bf16_mma, cudaFuncAttributeMaxDynamicSharedMemorySize, GEMM_SMEM);
    cudaFuncSetAttribute(gemm1_qkv,    cudaFuncAttributeMaxDynamicSharedMemorySize, GEMM_SMEM);
    cudaFuncSetAttribute(attn_tc,      cudaFuncAttributeMaxDynamicSharedMemorySize, ATTN_SMEM);

    // 0) input conversions
    {
        int n4 = MROWS * DEMBD / 4;
        split_f32<<<(n4 + 255) / 256, 256>>>(x, A1h, A1l, n4);
        transpose_split<<<dim3(KQV_N / 32, DEMBD / 32), dim3(32, 8)>>>(W1, W1h, W1l, DEMBD, KQV_N);
        transpose_split<<<dim3(DEMBD / 32, DEMBD / 32), dim3(32, 8)>>>(W2, W2h, W2l, DEMBD, DEMBD);
    }
    // 1) kqv = x @ W1 + b1, epilogue writes per-head bf16 hi/lo Q/K/V directly
    gemm1_qkv<<<dim3(KQV_N / 128, MROWS / 128), 256, GEMM_SMEM>>>(
        A1h, A1l, W1h, W1l, b1, Qh, Ql, Kh, Kl, Vh, Vl);
    // 2) causal attention (tensor cores), writes A2 hi/lo directly
    attn_tc<<<dim3(TSEQ / 128, NHEADS, BS), 256, ATTN_SMEM>>>(
        Qh, Ql, Kh, Kl, Vh, Vl, A2h, A2l);
    // 3) out = att @ W2 + b2  (tensor cores)
    gemm_bf16_mma<<<dim3(DEMBD / 128, MROWS / 128), 256, GEMM_SMEM>>>(
        A2h, A2l, W2h, W2l, b2, out, MROWS, DEMBD, DEMBD);
}

// round 9
// speedup vs baseline: 2.8984x; 1.0924x over previous
#include <cuda_runtime.h>
#include <cuda_bf16.h>
#include <math.h>
#include <stdint.h>

// Problem constants
#define BS      2
#define TSEQ    2048
#define DEMBD   1024
#define NHEADS  16
#define DHEAD   64
#define MROWS   (BS * TSEQ)      // 4096
#define KQV_N   (3 * DEMBD)      // 3072
#define BH      (BS * NHEADS)    // 32

// ---------------------------------------------------------------------------
// Scratch (__device__ globals; allocation-free rule)
// ---------------------------------------------------------------------------
__device__ __nv_bfloat16 g_A1hi[MROWS * DEMBD];
__device__ __nv_bfloat16 g_A1lo[MROWS * DEMBD];
__device__ __nv_bfloat16 g_A2hi[MROWS * DEMBD];   // written by attention
__device__ __nv_bfloat16 g_A2lo[MROWS * DEMBD];
__device__ __nv_bfloat16 g_W1Thi[KQV_N * DEMBD];
__device__ __nv_bfloat16 g_W1Tlo[KQV_N * DEMBD];
__device__ __nv_bfloat16 g_W2Thi[DEMBD * DEMBD];
__device__ __nv_bfloat16 g_W2Tlo[DEMBD * DEMBD];

// Attention operands, per-head layouts (bf16 hi/lo) — written by GEMM1 epilogue
__device__ __nv_bfloat16 g_Qhi[BH * TSEQ * DHEAD];  // [bh][t][d], pre-scaled
__device__ __nv_bfloat16 g_Qlo[BH * TSEQ * DHEAD];
__device__ __nv_bfloat16 g_Khi[BH * TSEQ * DHEAD];  // [bh][t][d]
__device__ __nv_bfloat16 g_Klo[BH * TSEQ * DHEAD];
__device__ __nv_bfloat16 g_Vthi[BH * DHEAD * TSEQ]; // [bh][d][t]  (transposed)
__device__ __nv_bfloat16 g_Vtlo[BH * DHEAD * TSEQ];

// ---------------------------------------------------------------------------
// PTX helpers (baseline ISA only)
// ---------------------------------------------------------------------------
__device__ __forceinline__ uint32_t smem_u32(const void* p) {
    uint32_t a;
    asm("{ .reg .u64 t; cvta.to.shared.u64 t, %1; cvt.u32.u64 %0, t; }" : "=r"(a) : "l"(p));
    return a;
}
__device__ __forceinline__ void cp16(uint32_t dst, const void* src) {
    asm volatile("cp.async.cg.shared.global [%0], [%1], 16;"
                 :: "r"(dst), "l"(__cvta_generic_to_global(src)));
}
__device__ __forceinline__ void cp_commit() { asm volatile("cp.async.commit_group;" ::: "memory"); }

#define LDSM4(r, addr) \
    asm volatile("ldmatrix.sync.aligned.m8n8.x4.shared.b16 {%0,%1,%2,%3}, [%4];" \
        : "=r"((r)[0]), "=r"((r)[1]), "=r"((r)[2]), "=r"((r)[3]) : "r"(addr))

#define MMA_BF16(d, a, b0, b1) \
    asm volatile("mma.sync.aligned.m16n8k16.row.col.f32.bf16.bf16.f32 " \
        "{%0,%1,%2,%3}, {%4,%5,%6,%7}, {%8,%9}, {%0,%1,%2,%3};" \
        : "+f"((d)[0]), "+f"((d)[1]), "+f"((d)[2]), "+f"((d)[3]) \
        : "r"((a)[0]), "r"((a)[1]), "r"((a)[2]), "r"((a)[3]), "r"(b0), "r"(b1))

// pack two fp32 into bf16x2: low half <- lo, high half <- hi
__device__ __forceinline__ uint32_t packbf2(float lo, float hi) {
    uint32_t r;
    asm("cvt.rn.bf16x2.f32 %0, %1, %2;" : "=r"(r) : "f"(hi), "f"(lo));
    return r;
}
// residual (lo-part) pack given the hi-pack
__device__ __forceinline__ uint32_t packlo2(float lo, float hi, uint32_t hp) {
    __nv_bfloat162 hv = *reinterpret_cast<__nv_bfloat162*>(&hp);
    return packbf2(lo - __bfloat162float(hv.x), hi - __bfloat162float(hv.y));
}

// ---------------------------------------------------------------------------
// fp32 -> bf16 hi/lo split (elementwise, float4)  [x -> A1]
// ---------------------------------------------------------------------------
__global__ void split_f32(const float* __restrict__ in, __nv_bfloat16* __restrict__ hi,
                          __nv_bfloat16* __restrict__ lo, int n4) {
    int i = blockIdx.x * blockDim.x + threadIdx.x;
    if (i >= n4) return;
    float4 v = ((const float4*)in)[i];
    uint32_t h0 = packbf2(v.x, v.y), h1 = packbf2(v.z, v.w);
    uint32_t l0 = packlo2(v.x, v.y, h0), l1 = packlo2(v.z, v.w, h1);
    ((uint32_t*)hi)[i * 2 + 0] = h0;
    ((uint32_t*)hi)[i * 2 + 1] = h1;
    ((uint32_t*)lo)[i * 2 + 0] = l0;
    ((uint32_t*)lo)[i * 2 + 1] = l1;
}

// ---------------------------------------------------------------------------
// W[K][N] fp32 -> W^T[N][K] bf16 hi/lo (tiled transpose)
// ---------------------------------------------------------------------------
__global__ void transpose_split(const float* __restrict__ W, __nv_bfloat16* __restrict__ hiT,
                                __nv_bfloat16* __restrict__ loT, int K, int N) {
    __shared__ float t[32][33];
    int n = blockIdx.x * 32 + threadIdx.x;
    int k0 = blockIdx.y * 32;
#pragma unroll
    for (int i = 0; i < 32; i += 8)
        t[threadIdx.y + i][threadIdx.x] = W[(size_t)(k0 + threadIdx.y + i) * N + n];
    __syncthreads();
    int kk = k0 + threadIdx.x;
#pragma unroll
    for (int i = 0; i < 32; i += 8) {
        int nn = blockIdx.x * 32 + threadIdx.y + i;
        float v = t[threadIdx.x][threadIdx.y + i];
        __nv_bfloat16 h = __float2bfloat16(v);
        __nv_bfloat16 l = __float2bfloat16(v - __bfloat162float(h));
        hiT[(size_t)nn * K + kk] = h;
        loT[(size_t)nn * K + kk] = l;
    }
}

// ---------------------------------------------------------------------------
// GEMM tiling: 128x128 CTA tile, BK=32 slabs, xor-swizzled smem (64B rows,
// 16B chunk ^= (row&6)>>1), 3-stage cp.async pipeline, 1 sync per slab.
// ---------------------------------------------------------------------------
#define BK        32
#define TILE_B    8192                 // 128 rows x 64 B (swizzled, no pad)
#define STAGE_B   (4 * TILE_B)         // Ah, Al, Bh, Bl = 32 KB
#define GEMM_SMEM (3 * STAGE_B)        // 96 KB -> 2 CTAs/SM

__device__ __forceinline__ uint32_t swz16(int row, int ch) {
    return (uint32_t)(row * 64 + ((ch ^ ((row & 6) >> 1)) << 4));
}

__device__ __forceinline__ void load_tile(uint32_t tb, const __nv_bfloat16* sp, int K, int tid) {
#pragma unroll
    for (int i = 0; i < 2; i++) {
        int q = tid + i * 256;             // 512 16B-chunks per tile
        int row = q >> 2, c16 = q & 3;
        cp16(tb + swz16(row, c16), sp + (size_t)row * K + c16 * 8);
    }
}

__device__ __forceinline__ void load_stage(uint32_t st, const __nv_bfloat16* Ah0,
                                           const __nv_bfloat16* Al0, const __nv_bfloat16* Bh0,
                                           const __nv_bfloat16* Bl0, int k0, int K, int tid) {
    load_tile(st + 0 * TILE_B, Ah0 + k0, K, tid);
    load_tile(st + 1 * TILE_B, Al0 + k0, K, tid);
    load_tile(st + 2 * TILE_B, Bh0 + k0, K, tid);
    load_tile(st + 3 * TILE_B, Bl0 + k0, K, tid);
    cp_commit();
}

// Mainloop shared by both GEMM kernels. Ends with one __syncthreads()
// (so epilogues may immediately reuse smem).
__device__ __forceinline__ void gemm_mainloop(
    uint32_t sbase, const __nv_bfloat16* Ah0, const __nv_bfloat16* Al0,
    const __nv_bfloat16* Bh0, const __nv_bfloat16* Bl0, int K, int tid,
    int wm, int wn, int lane, float acc[4][4][4]) {

    const int NSLAB = K / BK;
    const int rowA = wm + (lane & 15);
    const int chA  = lane >> 4;                         // 0..1
    const int rowB = wn + (lane & 7) + ((lane >> 4) << 3);
    const int chB  = (lane >> 3) & 1;                   // 0..1
    const uint32_t aRow = (uint32_t)rowA * 64;
    const uint32_t bRow = (uint32_t)rowB * 64;
    const int aSwz = (rowA & 6) >> 1;
    const int bSwz = (rowB & 6) >> 1;

    // prologue: slabs 0,1 -> stages 0,1
    load_stage(sbase + 0 * STAGE_B, Ah0, Al0, Bh0, Bl0, 0, K, tid);
    load_stage(sbase + 1 * STAGE_B, Ah0, Al0, Bh0, Bl0, BK, K, tid);

    for (int s = 0; s < NSLAB; s++) {
        if (s + 1 < NSLAB) {
            asm volatile("cp.async.wait_group 1;" ::: "memory");
        } else {
            asm volatile("cp.async.wait_group 0;" ::: "memory");
        }
        __syncthreads();
        if (s + 2 < NSLAB)
            load_stage(sbase + ((s + 2) % 3) * STAGE_B, Ah0, Al0, Bh0, Bl0,
                       (s + 2) * BK, K, tid);

        const uint32_t st = sbase + (s % 3) * STAGE_B;
#pragma unroll
        for (int kk = 0; kk < BK; kk += 16) {
            const int kc = kk >> 3;                     // 0 or 2
            uint32_t bh[2][4], bl[2][4];
#pragma unroll
            for (int g = 0; g < 2; g++) {
                const uint32_t ba = st + bRow + (uint32_t)(g * 1024)
                                  + (uint32_t)(((kc | chB) ^ bSwz) << 4);
                LDSM4(bh[g], ba + 2 * TILE_B);
                LDSM4(bl[g], ba + 3 * TILE_B);
            }
#pragma unroll
            for (int mb = 0; mb < 4; mb++) {
                const uint32_t aa = st + aRow + (uint32_t)(mb * 1024)
                                  + (uint32_t)(((kc | chA) ^ aSwz) << 4);
                uint32_t ah[4], al[4];
                LDSM4(ah, aa + 0 * TILE_B);
                LDSM4(al, aa + 1 * TILE_B);
#pragma unroll
                for (int nb = 0; nb < 4; nb++) {
                    const int g = nb >> 1, h2 = (nb & 1) * 2;
                    MMA_BF16(acc[mb][nb], ah, bh[g][h2], bh[g][h2 + 1]);
                    MMA_BF16(acc[mb][nb], ah, bl[g][h2], bl[g][h2 + 1]);
                    MMA_BF16(acc[mb][nb], al, bh[g][h2], bh[g][h2 + 1]);
                }
            }
        }
    }
    __syncthreads();   // epilogues may reuse smem
}

// ---------------------------------------------------------------------------
// GEMM2: generic fp32-output GEMM + bias (att @ W2 + b2 -> out)
// ---------------------------------------------------------------------------
__global__ __launch_bounds__(256, 2)
void gemm_bf16_mma(const __nv_bfloat16* __restrict__ Ah, const __nv_bfloat16* __restrict__ Al,
                   const __nv_bfloat16* __restrict__ Bh, const __nv_bfloat16* __restrict__ Bl,
                   const float* __restrict__ bias, float* __restrict__ C,
                   int M, int N, int K) {
    extern __shared__ char smem[];
    const uint32_t sbase = smem_u32(smem);

    const int tid  = threadIdx.x;
    const int wid  = tid >> 5;
    const int lane = tid & 31;
    const int m0 = blockIdx.y * 128;
    const int n0 = blockIdx.x * 128;
    const int wm = (wid & 1) * 64;
    const int wn = (wid >> 1) * 32;

    float acc[4][4][4];
#pragma unroll
    for (int mb = 0; mb < 4; mb++)
#pragma unroll
        for (int nb = 0; nb < 4; nb++)
#pragma unroll
            for (int r = 0; r < 4; r++) acc[mb][nb][r] = 0.0f;

    gemm_mainloop(sbase, Ah + (size_t)m0 * K, Al + (size_t)m0 * K,
                  Bh + (size_t)n0 * K, Bl + (size_t)n0 * K, K, tid, wm, wn, lane, acc);

    const int rBase = m0 + wm + (lane >> 2);
    const int cBase = n0 + wn + (lane & 3) * 2;
#pragma unroll
    for (int mb = 0; mb < 4; mb++) {
#pragma unroll
        for (int nb = 0; nb < 4; nb++) {
            const int col = cBase + nb * 8;
            const float bx = __ldg(bias + col);
            const float by = __ldg(bias + col + 1);
            float* p0 = C + (size_t)(rBase + mb * 16) * N + col;
            float* p1 = C + (size_t)(rBase + mb * 16 + 8) * N + col;
            *(float2*)p0 = make_float2(acc[mb][nb][0] + bx, acc[mb][nb][1] + by);
            *(float2*)p1 = make_float2(acc[mb][nb][2] + bx, acc[mb][nb][3] + by);
        }
    }
}

// ---------------------------------------------------------------------------
// GEMM1 with fused QKV epilogue: x @ W1 + b1, written directly as per-head
// bf16 hi/lo attention operands (Q scaled; V transposed via smem staging).
// ---------------------------------------------------------------------------
#define VP 132   // fp32 smem pitch for V transpose staging (128 + 4 pad)

__global__ __launch_bounds__(256, 2)
void gemm1_qkv(const __nv_bfloat16* __restrict__ Ah, const __nv_bfloat16* __restrict__ Al,
               const __nv_bfloat16* __restrict__ Bh, const __nv_bfloat16* __restrict__ Bl,
               const float* __restrict__ bias,
               __nv_bfloat16* __restrict__ Qh, __nv_bfloat16* __restrict__ Ql,
               __nv_bfloat16* __restrict__ Kh, __nv_bfloat16* __restrict__ Kl,
               __nv_bfloat16* __restrict__ Vh, __nv_bfloat16* __restrict__ Vl) {
    extern __shared__ char smem[];
    const uint32_t sbase = smem_u32(smem);
    const int K = DEMBD;

    const int tid  = threadIdx.x;
    const int wid  = tid >> 5;
    const int lane = tid & 31;
    const int m0 = blockIdx.y * 128;
    const int n0 = blockIdx.x * 128;
    const int wm = (wid & 1) * 64;
    const int wn = (wid >> 1) * 32;

    float acc[4][4][4];
#pragma unroll
    for (int mb = 0; mb < 4; mb++)
#pragma unroll
        for (int nb = 0; nb < 4; nb++)
#pragma unroll
            for (int r = 0; r < 4; r++) acc[mb][nb][r] = 0.0f;

    gemm_mainloop(sbase, Ah + (size_t)m0 * K, Al + (size_t)m0 * K,
                  Bh + (size_t)n0 * K, Bl + (size_t)n0 * K, K, tid, wm, wn, lane, acc);

    const int part = n0 >> 10;              // 0 = K, 1 = Q, 2 = V
    const int b    = m0 >> 11;              // batch
    const int t0   = m0 & 2047;             // t of tile row 0
    const int cp0  = n0 & 1023;             // col offset within part

    if (part < 2) {
        // ---- K / Q: direct per-head [bh][t][64] bf16 hi/lo stores ----
        __nv_bfloat16* Dh = (part == 0) ? Kh : Qh;
        __nv_bfloat16* Dl = (part == 0) ? Kl : Ql;
        const float qscale = (part == 1) ? 0.125f : 1.0f;
        const int rLoc = wm + (lane >> 2);
        const int cLoc = wn + (lane & 3) * 2;
#pragma unroll
        for (int mb = 0; mb < 4; mb++) {
#pragma unroll
            for (int nb = 0; nb < 4; nb++) {
                const int c = cLoc + nb * 8;              // 0..127 local
                const int cpart = cp0 + c;                // 0..1023 within part
                const int h = cpart >> 6, d = cpart & 63;
                const float bx = __ldg(bias + n0 + c);
                const float by = __ldg(bias + n0 + c + 1);
                float f0 = (acc[mb][nb][0] + bx) * qscale;
                float f1 = (acc[mb][nb][1] + by) * qscale;
                float f2 = (acc[mb][nb][2] + bx) * qscale;
                float f3 = (acc[mb][nb][3] + by) * qscale;
                const size_t base = ((size_t)(b * NHEADS + h) * TSEQ);
                const int tA = t0 + rLoc + mb * 16;
                const int tB = tA + 8;
                uint32_t h0 = packbf2(f0, f1), l0 = packlo2(f0, f1, h0);
                uint32_t h1 = packbf2(f2, f3), l1 = packlo2(f2, f3, h1);
                *(uint32_t*)(Dh + (base + tA) * DHEAD + d) = h0;
                *(uint32_t*)(Dl + (base + tA) * DHEAD + d) = l0;
                *(uint32_t*)(Dh + (base + tB) * DHEAD + d) = h1;
                *(uint32_t*)(Dl + (base + tB) * DHEAD + d) = l1;
            }
        }
    } else {
        // ---- V: stage (bias-added fp32) into smem as [col][row], then write
        //      transposed per-head [bh][d][t] bf16 hi/lo, coalesced over t ----
        float* sv = (float*)smem;
        const int rLoc = wm + (lane >> 2);
        const int cLoc = wn + (lane & 3) * 2;
#pragma unroll
        for (int mb = 0; mb < 4; mb++) {
#pragma unroll
            for (int nb = 0; nb < 4; nb++) {
                const int c = cLoc + nb * 8;
                const float bx = __ldg(bias + n0 + c);
                const float by = __ldg(bias + n0 + c + 1);
                const int rA = rLoc + mb * 16, rB = rA + 8;
                sv[(c + 0) * VP + rA] = acc[mb][nb][0] + bx;
                sv[(c + 1) * VP + rA] = acc[mb][nb][1] + by;
                sv[(c + 0) * VP + rB] = acc[mb][nb][2] + bx;
                sv[(c + 1) * VP + rB] = acc[mb][nb][3] + by;
            }
        }
        __syncthreads();
#pragma unroll
        for (int i = 0; i < 16; i++) {
            const int c = (tid >> 5) + i * 8;            // 0..127 local col
            const int cpart = cp0 + c;
            const int h = cpart >> 6, d = cpart & 63;
            float4 v = *(float4*)&sv[c * VP + lane * 4];
            uint32_t hA = packbf2(v.x, v.y), lA = packlo2(v.x, v.y, hA);
            uint32_t hB = packbf2(v.z, v.w), lB = packlo2(v.z, v.w, hB);
            const size_t dst =
                ((size_t)(b * NHEADS + h) * DHEAD + d) * TSEQ + t0 + lane * 4;
            *(uint2*)(Vh + dst) = make_uint2(hA, hB);
            *(uint2*)(Vl + dst) = make_uint2(lA, lB);
        }
    }
}

// ---------------------------------------------------------------------------
// Tensor-core causal flash attention (bf16 hi/lo, fp32 softmax) — unchanged.
// ---------------------------------------------------------------------------
#define AT_ROW    72                      // 64 + 8 pad halves
#define AT_TILE_B (64 * AT_ROW * 2)       // 9216 B
#define AT_STAGE  (4 * AT_TILE_B)         // Khi,Klo,Vhi,Vlo = 36864 B
#define ATTN_SMEM (2 * AT_STAGE)          // 73728 B

__global__ __launch_bounds__(256)
void attn_tc(const __nv_bfloat16* __restrict__ Qh, const __nv_bfloat16* __restrict__ Ql,
             const __nv_bfloat16* __restrict__ Kh, const __nv_bfloat16* __restrict__ Kl,
             const __nv_bfloat16* __restrict__ Vh, const __nv_bfloat16* __restrict__ Vl,
             __nv_bfloat16* __restrict__ Oh, __nv_bfloat16* __restrict__ Ol) {
    extern __shared__ char smem[];
    const uint32_t sbase = smem_u32(smem);

    const int tid  = threadIdx.x;
    const int wid  = tid >> 5;
    const int lane = tid & 31;
    const int qt = (gridDim.x - 1) - blockIdx.x;       // heavy tiles first
    const int h  = blockIdx.y;
    const int b  = blockIdx.z;
    const int bh = b * NHEADS + h;
    const int nkt = 2 * qt + 2;

    const __nv_bfloat16* Qhp = Qh + ((size_t)bh * TSEQ + qt * 128) * DHEAD;
    const __nv_bfloat16* Qlp = Ql + ((size_t)bh * TSEQ + qt * 128) * DHEAD;
    const __nv_bfloat16* Khp = Kh + (size_t)bh * TSEQ * DHEAD;
    const __nv_bfloat16* Klp = Kl + (size_t)bh * TSEQ * DHEAD;
    const __nv_bfloat16* Vhp = Vh + (size_t)bh * DHEAD * TSEQ;
    const __nv_bfloat16* Vlp = Vl + (size_t)bh * DHEAD * TSEQ;

#pragma unroll
    for (int i = 0; i < 4; i++) {
        int chunk = tid + i * 256;
        int row = chunk >> 3, cb = chunk & 7;
        cp16(sbase + (uint32_t)row * (AT_ROW * 2) + cb * 16, Qhp + (size_t)row * DHEAD + cb * 8);
        cp16(sbase + 2 * AT_TILE_B + (uint32_t)row * (AT_ROW * 2) + cb * 16,
             Qlp + (size_t)row * DHEAD + cb * 8);
    }
    cp_commit();
    asm volatile("cp.async.wait_group 0;" ::: "memory");
    __syncthreads();

    uint32_t qhi[4][4], qlo[4][4];
    {
        const int aOff = (wid * 16 + (lane & 15)) * AT_ROW + (lane >> 4) * 8;
#pragma unroll
        for (int kb = 0; kb < 4; kb++) {
            LDSM4(qhi[kb], sbase + (uint32_t)(aOff + kb * 16) * 2);
            LDSM4(qlo[kb], sbase + 2 * AT_TILE_B + (uint32_t)(aOff + kb * 16) * 2);
        }
    }
    __syncthreads();

    const int bOff = ((lane & 7) + ((lane >> 4) << 3)) * AT_ROW + (((lane >> 3) & 1) << 3);

    float o[8][4];
#pragma unroll
    for (int nb = 0; nb < 8; nb++)
#pragma unroll
        for (int r = 0; r < 4; r++) o[nb][r] = 0.0f;
    float m0 = -INFINITY, m1 = -INFINITY, l0 = 0.0f, l1 = 0.0f;

    const int qrow_lo = qt * 128 + wid * 16;
    const int r0g = qrow_lo + (lane >> 2);
    const int r1g = r0g + 8;

    {
        const uint32_t st = sbase;
#pragma unroll
        for (int i = 0; i < 8; i++) {
            int chunk = tid + i * 256;
            int tile = chunk >> 9, within = chunk & 511;
            int row = within >> 3, cb = within & 7;
            uint32_t dst = st + tile * AT_TILE_B + (uint32_t)row * (AT_ROW * 2) + cb * 16;
            if (tile == 0)      cp16(dst, Khp + (size_t)row * DHEAD + cb * 8);
            else if (tile == 1) cp16(dst, Klp + (size_t)row * DHEAD + cb * 8);
            else if (tile == 2) cp16(dst, Vhp + (size_t)row * TSEQ + cb * 8);
            else                cp16(dst, Vlp + (size_t)row * TSEQ + cb * 8);
        }
        cp_commit();
    }

    for (int kt = 0; kt < nkt; kt++) {
        if (kt + 1 < nkt) {
            const uint32_t st = sbase + ((kt + 1) & 1) * AT_STAGE;
            const int koff = (kt + 1) * 64;
#pragma unroll
            for (int i = 0; i < 8; i++) {
                int chunk = tid + i * 256;
                int tile = chunk >> 9, within = chunk & 511;
                int row = within >> 3, cb = within & 7;
                uint32_t dst = st + tile * AT_TILE_B + (uint32_t)row * (AT_ROW * 2) + cb * 16;
                if (tile == 0)      cp16(dst, Khp + (size_t)(koff + row) * DHEAD + cb * 8);
                else if (tile == 1) cp16(dst, Klp + (size_t)(koff + row) * DHEAD + cb * 8);
                else if (tile == 2) cp16(dst, Vhp + (size_t)row * TSEQ + koff + cb * 8);
                else                cp16(dst, Vlp + (size_t)row * TSEQ + koff + cb * 8);
            }
            cp_commit();
            asm volatile("cp.async.wait_group 1;" ::: "memory");
        } else {
            asm volatile("cp.async.wait_group 0;" ::: "memory");
        }
        __syncthreads();

        if (kt * 64 <= qrow_lo + 15) {
            const uint32_t st = sbase + (kt & 1) * AT_STAGE;
            const uint32_t khb = st + 0 * AT_TILE_B + (uint32_t)bOff * 2;
            const uint32_t klb = st + 1 * AT_TILE_B + (uint32_t)bOff * 2;
            const uint32_t vhb = st + 2 * AT_TILE_B + (uint32_t)bOff * 2;
            const uint32_t vlb = st + 3 * AT_TILE_B + (uint32_t)bOff * 2;

            float s[8][4];
#pragma unroll
            for (int nb = 0; nb < 8; nb++)
#pragma unroll
                for (int r = 0; r < 4; r++) s[nb][r] = 0.0f;

#pragma unroll
            for (int kb = 0; kb < 4; kb++) {
                uint32_t kh[4][4], kl[4][4];
#pragma unroll
                for (int g = 0; g < 4; g++) {
                    LDSM4(kh[g], khb + (uint32_t)(g * 16 * AT_ROW + kb * 16) * 2);
                    LDSM4(kl[g], klb + (uint32_t)(g * 16 * AT_ROW + kb * 16) * 2);
                }
#pragma unroll
                for (int g = 0; g < 4; g++)
#pragma unroll
                    for (int half = 0; half < 2; half++) {
                        const int nb = 2 * g + half, h2 = half * 2;
                        MMA_BF16(s[nb], qhi[kb], kh[g][h2], kh[g][h2 + 1]);
                        MMA_BF16(s[nb], qhi[kb], kl[g][h2], kl[g][h2 + 1]);
                        MMA_BF16(s[nb], qlo[kb], kh[g][h2], kh[g][h2 + 1]);
                    }
            }

            if (kt * 64 + 63 > qrow_lo) {
#pragma unroll
                for (int nb = 0; nb < 8; nb++) {
                    int c = kt * 64 + nb * 8 + (lane & 3) * 2;
                    if (c > r0g)     s[nb][0] = -INFINITY;
                    if (c + 1 > r0g) s[nb][1] = -INFINITY;
                    if (c > r1g)     s[nb][2] = -INFINITY;
                    if (c + 1 > r1g) s[nb][3] = -INFINITY;
                }
            }

            float mx0 = -INFINITY, mx1 = -INFINITY;
#pragma unroll
            for (int nb = 0; nb < 8; nb++) {
                mx0 = fmaxf(mx0, fmaxf(s[nb][0], s[nb][1]));
                mx1 = fmaxf(mx1, fmaxf(s[nb][2], s[nb][3]));
            }
            mx0 = fmaxf(mx0, __shfl_xor_sync(0xffffffffu, mx0, 1));
            mx0 = fmaxf(mx0, __shfl_xor_sync(0xffffffffu, mx0, 2));
            mx1 = fmaxf(mx1, __shfl_xor_sync(0xffffffffu, mx1, 1));
            mx1 = fmaxf(mx1, __shfl_xor_sync(0xffffffffu, mx1, 2));

            float mn0 = fmaxf(m0, mx0), mn1 = fmaxf(m1, mx1);
            float c0 = __expf(m0 - mn0), c1 = __expf(m1 - mn1);
            m0 = mn0; m1 = mn1;

            float rs0 = 0.0f, rs1 = 0.0f;
#pragma unroll
            for (int nb = 0; nb < 8; nb++) {
                s[nb][0] = __expf(s[nb][0] - m0); rs0 += s[nb][0];
                s[nb][1] = __expf(s[nb][1] - m0); rs0 += s[nb][1];
                s[nb][2] = __expf(s[nb][2] - m1); rs1 += s[nb][2];
                s[nb][3] = __expf(s[nb][3] - m1); rs1 += s[nb][3];
            }
            rs0 += __shfl_xor_sync(0xffffffffu, rs0, 1);
            rs0 += __shfl_xor_sync(0xffffffffu, rs0, 2);
            rs1 += __shfl_xor_sync(0xffffffffu, rs1, 1);
            rs1 += __shfl_xor_sync(0xffffffffu, rs1, 2);
            l0 = l0 * c0 + rs0;
            l1 = l1 * c1 + rs1;
#pragma unroll
            for (int nb = 0; nb < 8; nb++) {
                o[nb][0] *= c0; o[nb][1] *= c0;
                o[nb][2] *= c1; o[nb][3] *= c1;
            }

#pragma unroll
            for (int kbp = 0; kbp < 4; kbp++) {
                uint32_t phi[4], plo[4];
                const int e = 2 * kbp;
                phi[0] = packbf2(s[e][0], s[e][1]);
                phi[1] = packbf2(s[e][2], s[e][3]);
                phi[2] = packbf2(s[e + 1][0], s[e + 1][1]);
                phi[3] = packbf2(s[e + 1][2], s[e + 1][3]);
                plo[0] = packlo2(s[e][0], s[e][1], phi[0]);
                plo[1] = packlo2(s[e][2], s[e][3], phi[1]);
                plo[2] = packlo2(s[e + 1][0], s[e + 1][1], phi[2]);
                plo[3] = packlo2(s[e + 1][2], s[e + 1][3], phi[3]);

                uint32_t vh[4][4], vl[4][4];
#pragma unroll
                for (int g = 0; g < 4; g++) {
                    LDSM4(vh[g], vhb + (uint32_t)(g * 16 * AT_ROW + kbp * 16) * 2);
                    LDSM4(vl[g], vlb + (uint32_t)(g * 16 * AT_ROW + kbp * 16) * 2);
                }
#pragma unroll
                for (int g = 0; g < 4; g++)
#pragma unroll
                    for (int half = 0; half < 2; half++) {
                        const int nbd = 2 * g + half, h2 = half * 2;
                        MMA_BF16(o[nbd], phi, vh[g][h2], vh[g][h2 + 1]);
                        MMA_BF16(o[nbd], plo, vh[g][h2], vh[g][h2 + 1]);
                        MMA_BF16(o[nbd], phi, vl[g][h2], vl[g][h2 + 1]);
                    }
            }
        }
        __syncthreads();
    }

    const float inv0 = 1.0f / l0, inv1 = 1.0f / l1;
    const size_t grow0 = (size_t)b * TSEQ + r0g;
    const size_t grow1 = grow0 + 8;
    const int colb = h * DHEAD + (lane & 3) * 2;
#pragma unroll
    for (int nbd = 0; nbd < 8; nbd++) {
        const int col = colb + nbd * 8;
        float f00 = o[nbd][0] * inv0, f01 = o[nbd][1] * inv0;
        float f10 = o[nbd][2] * inv1, f11 = o[nbd][3] * inv1;
        uint32_t h0 = packbf2(f00, f01), l0p = packlo2(f00, f01, h0);
        uint32_t h1 = packbf2(f10, f11), l1p = packlo2(f10, f11, h1);
        *(uint32_t*)(Oh + grow0 * DEMBD + col) = h0;
        *(uint32_t*)(Ol + grow0 * DEMBD + col) = l0p;
        *(uint32_t*)(Oh + grow1 * DEMBD + col) = h1;
        *(uint32_t*)(Ol + grow1 * DEMBD + col) = l1p;
    }
}

// ---------------------------------------------------------------------------
extern "C" void kernel_launch(void* const* d_in, const int* in_sizes, int n_in,
                              void* d_out, int out_size) {
    const float* x  = (const float*)d_in[0];
    const float* W1 = (const float*)d_in[1];
    const float* b1 = (const float*)d_in[2];
    const float* W2 = (const float*)d_in[3];
    const float* b2 = (const float*)d_in[4];
    float* out = (float*)d_out;

    __nv_bfloat16 *A1h, *A1l, *A2h, *A2l, *W1h, *W1l, *W2h, *W2l;
    __nv_bfloat16 *Qh, *Ql, *Kh, *Kl, *Vh, *Vl;
    cudaGetSymbolAddress((void**)&A1h, g_A1hi);
    cudaGetSymbolAddress((void**)&A1l, g_A1lo);
    cudaGetSymbolAddress((void**)&A2h, g_A2hi);
    cudaGetSymbolAddress((void**)&A2l, g_A2lo);
    cudaGetSymbolAddress((void**)&W1h, g_W1Thi);
    cudaGetSymbolAddress((void**)&W1l, g_W1Tlo);
    cudaGetSymbolAddress((void**)&W2h, g_W2Thi);
    cudaGetSymbolAddress((void**)&W2l, g_W2Tlo);
    cudaGetSymbolAddress((void**)&Qh, g_Qhi);
    cudaGetSymbolAddress((void**)&Ql, g_Qlo);
    cudaGetSymbolAddress((void**)&Kh, g_Khi);
    cudaGetSymbolAddress((void**)&Kl, g_Klo);
    cudaGetSymbolAddress((void**)&Vh, g_Vthi);
    cudaGetSymbolAddress((void**)&Vl, g_Vtlo);

    cudaFuncSetAttribute(gemm_bf16_mma, cudaFuncAttributeMaxDynamicSharedMemorySize, GEMM_SMEM);
    cudaFuncSetAttribute(gemm1_qkv,    cudaFuncAttributeMaxDynamicSharedMemorySize, GEMM_SMEM);
    cudaFuncSetAttribute(attn_tc,      cudaFuncAttributeMaxDynamicSharedMemorySize, ATTN_SMEM);

    // 0) input conversions
    {
        int n4 = MROWS * DEMBD / 4;
        split_f32<<<(n4 + 255) / 256, 256>>>(x, A1h, A1l, n4);
        transpose_split<<<dim3(KQV_N / 32, DEMBD / 32), dim3(32, 8)>>>(W1, W1h, W1l, DEMBD, KQV_N);
        transpose_split<<<dim3(DEMBD / 32, DEMBD / 32), dim3(32, 8)>>>(W2, W2h, W2l, DEMBD, DEMBD);
    }
    // 1) kqv = x @ W1 + b1, epilogue writes per-head bf16 hi/lo Q/K/V directly
    gemm1_qkv<<<dim3(KQV_N / 128, MROWS / 128), 256, GEMM_SMEM>>>(
        A1h, A1l, W1h, W1l, b1, Qh, Ql, Kh, Kl, Vh, Vl);
    // 2) causal attention (tensor cores), writes A2 hi/lo directly
    attn_tc<<<dim3(TSEQ / 128, NHEADS, BS), 256, ATTN_SMEM>>>(
        Qh, Ql, Kh, Kl, Vh, Vl, A2h, A2l);
    // 3) out = att @ W2 + b2  (tensor cores)
    gemm_bf16_mma<<<dim3(DEMBD / 128, MROWS / 128), 256, GEMM_SMEM>>>(
        A2h, A2l, W2h, W2l, b2, out, MROWS, DEMBD, DEMBD);
}

// round 12
// speedup vs baseline: 2.9022x; 1.0013x over previous
#include <cuda_runtime.h>
#include <cuda_bf16.h>
#include <math.h>
#include <stdint.h>

// Problem constants
#define BS      2
#define TSEQ    2048
#define DEMBD   1024
#define NHEADS  16
#define DHEAD   64
#define MROWS   (BS * TSEQ)      // 4096
#define KQV_N   (3 * DEMBD)      // 3072
#define BH      (BS * NHEADS)    // 32

// ---------------------------------------------------------------------------
// Scratch (__device__ globals; allocation-free rule)
// ---------------------------------------------------------------------------
__device__ __nv_bfloat16 g_A1hi[MROWS * DEMBD];
__device__ __nv_bfloat16 g_A1lo[MROWS * DEMBD];
__device__ __nv_bfloat16 g_A2hi[MROWS * DEMBD];   // written by attention
__device__ __nv_bfloat16 g_A2lo[MROWS * DEMBD];
__device__ __nv_bfloat16 g_W1Thi[KQV_N * DEMBD];
__device__ __nv_bfloat16 g_W1Tlo[KQV_N * DEMBD];
__device__ __nv_bfloat16 g_W2Thi[DEMBD * DEMBD];
__device__ __nv_bfloat16 g_W2Tlo[DEMBD * DEMBD];

// Attention operands, per-head layouts (bf16 hi/lo) — written by GEMM1 epilogue
__device__ __nv_bfloat16 g_Qhi[BH * TSEQ * DHEAD];  // [bh][t][d], pre-scaled
__device__ __nv_bfloat16 g_Qlo[BH * TSEQ * DHEAD];
__device__ __nv_bfloat16 g_Khi[BH * TSEQ * DHEAD];  // [bh][t][d]
__device__ __nv_bfloat16 g_Klo[BH * TSEQ * DHEAD];
__device__ __nv_bfloat16 g_Vthi[BH * DHEAD * TSEQ]; // [bh][d][t]  (transposed)
__device__ __nv_bfloat16 g_Vtlo[BH * DHEAD * TSEQ];

// ---------------------------------------------------------------------------
// PTX helpers (baseline ISA only)
// ---------------------------------------------------------------------------
__device__ __forceinline__ uint32_t smem_u32(const void* p) {
    uint32_t a;
    asm("{ .reg .u64 t; cvta.to.shared.u64 t, %1; cvt.u32.u64 %0, t; }" : "=r"(a) : "l"(p));
    return a;
}
__device__ __forceinline__ void cp16(uint32_t dst, const void* src) {
    asm volatile("cp.async.cg.shared.global [%0], [%1], 16;"
                 :: "r"(dst), "l"(__cvta_generic_to_global(src)));
}
__device__ __forceinline__ void cp_commit() { asm volatile("cp.async.commit_group;" ::: "memory"); }

#define LDSM4(r, addr) \
    asm volatile("ldmatrix.sync.aligned.m8n8.x4.shared.b16 {%0,%1,%2,%3}, [%4];" \
        : "=r"((r)[0]), "=r"((r)[1]), "=r"((r)[2]), "=r"((r)[3]) : "r"(addr))

#define MMA_BF16(d, a, b0, b1) \
    asm volatile("mma.sync.aligned.m16n8k16.row.col.f32.bf16.bf16.f32 " \
        "{%0,%1,%2,%3}, {%4,%5,%6,%7}, {%8,%9}, {%0,%1,%2,%3};" \
        : "+f"((d)[0]), "+f"((d)[1]), "+f"((d)[2]), "+f"((d)[3]) \
        : "r"((a)[0]), "r"((a)[1]), "r"((a)[2]), "r"((a)[3]), "r"(b0), "r"(b1))

// pack two fp32 into bf16x2: low half <- lo, high half <- hi
__device__ __forceinline__ uint32_t packbf2(float lo, float hi) {
    uint32_t r;
    asm("cvt.rn.bf16x2.f32 %0, %1, %2;" : "=r"(r) : "f"(hi), "f"(lo));
    return r;
}
// residual (lo-part) pack given the hi-pack
__device__ __forceinline__ uint32_t packlo2(float lo, float hi, uint32_t hp) {
    __nv_bfloat162 hv = *reinterpret_cast<__nv_bfloat162*>(&hp);
    return packbf2(lo - __bfloat162float(hv.x), hi - __bfloat162float(hv.y));
}

// ---------------------------------------------------------------------------
// fp32 -> bf16 hi/lo split (elementwise, float4)  [x -> A1]
// ---------------------------------------------------------------------------
__global__ void split_f32(const float* __restrict__ in, __nv_bfloat16* __restrict__ hi,
                          __nv_bfloat16* __restrict__ lo, int n4) {
    int i = blockIdx.x * blockDim.x + threadIdx.x;
    if (i >= n4) return;
    float4 v = ((const float4*)in)[i];
    uint32_t h0 = packbf2(v.x, v.y), h1 = packbf2(v.z, v.w);
    uint32_t l0 = packlo2(v.x, v.y, h0), l1 = packlo2(v.z, v.w, h1);
    ((uint32_t*)hi)[i * 2 + 0] = h0;
    ((uint32_t*)hi)[i * 2 + 1] = h1;
    ((uint32_t*)lo)[i * 2 + 0] = l0;
    ((uint32_t*)lo)[i * 2 + 1] = l1;
}

// ---------------------------------------------------------------------------
// W[K][N] fp32 -> W^T[N][K] bf16 hi/lo (tiled transpose)
// ---------------------------------------------------------------------------
__global__ void transpose_split(const float* __restrict__ W, __nv_bfloat16* __restrict__ hiT,
                                __nv_bfloat16* __restrict__ loT, int K, int N) {
    __shared__ float t[32][33];
    int n = blockIdx.x * 32 + threadIdx.x;
    int k0 = blockIdx.y * 32;
#pragma unroll
    for (int i = 0; i < 32; i += 8)
        t[threadIdx.y + i][threadIdx.x] = W[(size_t)(k0 + threadIdx.y + i) * N + n];
    __syncthreads();
    int kk = k0 + threadIdx.x;
#pragma unroll
    for (int i = 0; i < 32; i += 8) {
        int nn = blockIdx.x * 32 + threadIdx.y + i;
        float v = t[threadIdx.x][threadIdx.y + i];
        __nv_bfloat16 h = __float2bfloat16(v);
        __nv_bfloat16 l = __float2bfloat16(v - __bfloat162float(h));
        hiT[(size_t)nn * K + kk] = h;
        loT[(size_t)nn * K + kk] = l;
    }
}

// ---------------------------------------------------------------------------
// GEMM tiling: 128x128 CTA tile, BK=32 slabs, xor-swizzled smem (64B rows,
// 16B chunk ^= (row&6)>>1), 3-stage cp.async pipeline, 1 sync per slab.
// ---------------------------------------------------------------------------
#define BK        32
#define TILE_B    8192                 // 128 rows x 64 B (swizzled, no pad)
#define STAGE_B   (4 * TILE_B)         // Ah, Al, Bh, Bl = 32 KB
#define GEMM_SMEM (3 * STAGE_B)        // 96 KB -> 2 CTAs/SM

__device__ __forceinline__ uint32_t swz16(int row, int ch) {
    return (uint32_t)(row * 64 + ((ch ^ ((row & 6) >> 1)) << 4));
}

__device__ __forceinline__ void load_tile(uint32_t tb, const __nv_bfloat16* sp, int K, int tid) {
#pragma unroll
    for (int i = 0; i < 2; i++) {
        int q = tid + i * 256;             // 512 16B-chunks per tile
        int row = q >> 2, c16 = q & 3;
        cp16(tb + swz16(row, c16), sp + (size_t)row * K + c16 * 8);
    }
}

__device__ __forceinline__ void load_stage(uint32_t st, const __nv_bfloat16* Ah0,
                                           const __nv_bfloat16* Al0, const __nv_bfloat16* Bh0,
                                           const __nv_bfloat16* Bl0, int k0, int K, int tid) {
    load_tile(st + 0 * TILE_B, Ah0 + k0, K, tid);
    load_tile(st + 1 * TILE_B, Al0 + k0, K, tid);
    load_tile(st + 2 * TILE_B, Bh0 + k0, K, tid);
    load_tile(st + 3 * TILE_B, Bl0 + k0, K, tid);
    cp_commit();
}

// Mainloop shared by both GEMM kernels. Ends with one __syncthreads()
// (so epilogues may immediately reuse smem).
__device__ __forceinline__ void gemm_mainloop(
    uint32_t sbase, const __nv_bfloat16* Ah0, const __nv_bfloat16* Al0,
    const __nv_bfloat16* Bh0, const __nv_bfloat16* Bl0, int K, int tid,
    int wm, int wn, int lane, float acc[4][4][4]) {

    const int NSLAB = K / BK;
    const int rowA = wm + (lane & 15);
    const int chA  = lane >> 4;                         // 0..1
    const int rowB = wn + (lane & 7) + ((lane >> 4) << 3);
    const int chB  = (lane >> 3) & 1;                   // 0..1
    const uint32_t aRow = (uint32_t)rowA * 64;
    const uint32_t bRow = (uint32_t)rowB * 64;
    const int aSwz = (rowA & 6) >> 1;
    const int bSwz = (rowB & 6) >> 1;

    // prologue: slabs 0,1 -> stages 0,1
    load_stage(sbase + 0 * STAGE_B, Ah0, Al0, Bh0, Bl0, 0, K, tid);
    load_stage(sbase + 1 * STAGE_B, Ah0, Al0, Bh0, Bl0, BK, K, tid);

    for (int s = 0; s < NSLAB; s++) {
        if (s + 1 < NSLAB) {
            asm volatile("cp.async.wait_group 1;" ::: "memory");
        } else {
            asm volatile("cp.async.wait_group 0;" ::: "memory");
        }
        __syncthreads();
        if (s + 2 < NSLAB)
            load_stage(sbase + ((s + 2) % 3) * STAGE_B, Ah0, Al0, Bh0, Bl0,
                       (s + 2) * BK, K, tid);

        const uint32_t st = sbase + (s % 3) * STAGE_B;
#pragma unroll
        for (int kk = 0; kk < BK; kk += 16) {
            const int kc = kk >> 3;                     // 0 or 2
            uint32_t bh[2][4], bl[2][4];
#pragma unroll
            for (int g = 0; g < 2; g++) {
                const uint32_t ba = st + bRow + (uint32_t)(g * 1024)
                                  + (uint32_t)(((kc | chB) ^ bSwz) << 4);
                LDSM4(bh[g], ba + 2 * TILE_B);
                LDSM4(bl[g], ba + 3 * TILE_B);
            }
#pragma unroll
            for (int mb = 0; mb < 4; mb++) {
                const uint32_t aa = st + aRow + (uint32_t)(mb * 1024)
                                  + (uint32_t)(((kc | chA) ^ aSwz) << 4);
                uint32_t ah[4], al[4];
                LDSM4(ah, aa + 0 * TILE_B);
                LDSM4(al, aa + 1 * TILE_B);
#pragma unroll
                for (int nb = 0; nb < 4; nb++) {
                    const int g = nb >> 1, h2 = (nb & 1) * 2;
                    MMA_BF16(acc[mb][nb], ah, bh[g][h2], bh[g][h2 + 1]);
                    MMA_BF16(acc[mb][nb], ah, bl[g][h2], bl[g][h2 + 1]);
                    MMA_BF16(acc[mb][nb], al, bh[g][h2], bh[g][h2 + 1]);
                }
            }
        }
    }
    __syncthreads();   // epilogues may reuse smem
}

// ---------------------------------------------------------------------------
// GEMM2: generic fp32-output GEMM + bias (att @ W2 + b2 -> out)
// ---------------------------------------------------------------------------
__global__ __launch_bounds__(256, 2)
void gemm_bf16_mma(const __nv_bfloat16* __restrict__ Ah, const __nv_bfloat16* __restrict__ Al,
                   const __nv_bfloat16* __restrict__ Bh, const __nv_bfloat16* __restrict__ Bl,
                   const float* __restrict__ bias, float* __restrict__ C,
                   int M, int N, int K) {
    extern __shared__ char smem[];
    const uint32_t sbase = smem_u32(smem);

    const int tid  = threadIdx.x;
    const int wid  = tid >> 5;
    const int lane = tid & 31;
    const int m0 = blockIdx.y * 128;
    const int n0 = blockIdx.x * 128;
    const int wm = (wid & 1) * 64;
    const int wn = (wid >> 1) * 32;

    float acc[4][4][4];
#pragma unroll
    for (int mb = 0; mb < 4; mb++)
#pragma unroll
        for (int nb = 0; nb < 4; nb++)
#pragma unroll
            for (int r = 0; r < 4; r++) acc[mb][nb][r] = 0.0f;

    gemm_mainloop(sbase, Ah + (size_t)m0 * K, Al + (size_t)m0 * K,
                  Bh + (size_t)n0 * K, Bl + (size_t)n0 * K, K, tid, wm, wn, lane, acc);

    const int rBase = m0 + wm + (lane >> 2);
    const int cBase = n0 + wn + (lane & 3) * 2;
#pragma unroll
    for (int mb = 0; mb < 4; mb++) {
#pragma unroll
        for (int nb = 0; nb < 4; nb++) {
            const int col = cBase + nb * 8;
            const float bx = __ldg(bias + col);
            const float by = __ldg(bias + col + 1);
            float* p0 = C + (size_t)(rBase + mb * 16) * N + col;
            float* p1 = C + (size_t)(rBase + mb * 16 + 8) * N + col;
            *(float2*)p0 = make_float2(acc[mb][nb][0] + bx, acc[mb][nb][1] + by);
            *(float2*)p1 = make_float2(acc[mb][nb][2] + bx, acc[mb][nb][3] + by);
        }
    }
}

// ---------------------------------------------------------------------------
// GEMM1 with fused QKV epilogue: x @ W1 + b1, written directly as per-head
// bf16 hi/lo attention operands (Q scaled; V transposed via smem staging).
// ---------------------------------------------------------------------------
#define VP 132   // fp32 smem pitch for V transpose staging (128 + 4 pad)

__global__ __launch_bounds__(256, 2)
void gemm1_qkv(const __nv_bfloat16* __restrict__ Ah, const __nv_bfloat16* __restrict__ Al,
               const __nv_bfloat16* __restrict__ Bh, const __nv_bfloat16* __restrict__ Bl,
               const float* __restrict__ bias,
               __nv_bfloat16* __restrict__ Qh, __nv_bfloat16* __restrict__ Ql,
               __nv_bfloat16* __restrict__ Kh, __nv_bfloat16* __restrict__ Kl,
               __nv_bfloat16* __restrict__ Vh, __nv_bfloat16* __restrict__ Vl) {
    extern __shared__ char smem[];
    const uint32_t sbase = smem_u32(smem);
    const int K = DEMBD;

    const int tid  = threadIdx.x;
    const int wid  = tid >> 5;
    const int lane = tid & 31;
    const int m0 = blockIdx.y * 128;
    const int n0 = blockIdx.x * 128;
    const int wm = (wid & 1) * 64;
    const int wn = (wid >> 1) * 32;

    float acc[4][4][4];
#pragma unroll
    for (int mb = 0; mb < 4; mb++)
#pragma unroll
        for (int nb = 0; nb < 4; nb++)
#pragma unroll
            for (int r = 0; r < 4; r++) acc[mb][nb][r] = 0.0f;

    gemm_mainloop(sbase, Ah + (size_t)m0 * K, Al + (size_t)m0 * K,
                  Bh + (size_t)n0 * K, Bl + (size_t)n0 * K, K, tid, wm, wn, lane, acc);

    const int part = n0 >> 10;              // 0 = K, 1 = Q, 2 = V
    const int b    = m0 >> 11;              // batch
    const int t0   = m0 & 2047;             // t of tile row 0
    const int cp0  = n0 & 1023;             // col offset within part

    if (part < 2) {
        // ---- K / Q: direct per-head [bh][t][64] bf16 hi/lo stores ----
        __nv_bfloat16* Dh = (part == 0) ? Kh : Qh;
        __nv_bfloat16* Dl = (part == 0) ? Kl : Ql;
        const float qscale = (part == 1) ? 0.125f : 1.0f;
        const int rLoc = wm + (lane >> 2);
        const int cLoc = wn + (lane & 3) * 2;
#pragma unroll
        for (int mb = 0; mb < 4; mb++) {
#pragma unroll
            for (int nb = 0; nb < 4; nb++) {
                const int c = cLoc + nb * 8;              // 0..127 local
                const int cpart = cp0 + c;                // 0..1023 within part
                const int h = cpart >> 6, d = cpart & 63;
                const float bx = __ldg(bias + n0 + c);
                const float by = __ldg(bias + n0 + c + 1);
                float f0 = (acc[mb][nb][0] + bx) * qscale;
                float f1 = (acc[mb][nb][1] + by) * qscale;
                float f2 = (acc[mb][nb][2] + bx) * qscale;
                float f3 = (acc[mb][nb][3] + by) * qscale;
                const size_t base = ((size_t)(b * NHEADS + h) * TSEQ);
                const int tA = t0 + rLoc + mb * 16;
                const int tB = tA + 8;
                uint32_t h0 = packbf2(f0, f1), l0 = packlo2(f0, f1, h0);
                uint32_t h1 = packbf2(f2, f3), l1 = packlo2(f2, f3, h1);
                *(uint32_t*)(Dh + (base + tA) * DHEAD + d) = h0;
                *(uint32_t*)(Dl + (base + tA) * DHEAD + d) = l0;
                *(uint32_t*)(Dh + (base + tB) * DHEAD + d) = h1;
                *(uint32_t*)(Dl + (base + tB) * DHEAD + d) = l1;
            }
        }
    } else {
        // ---- V: stage (bias-added fp32) into smem as [col][row], then write
        //      transposed per-head [bh][d][t] bf16 hi/lo, coalesced over t ----
        float* sv = (float*)smem;
        const int rLoc = wm + (lane >> 2);
        const int cLoc = wn + (lane & 3) * 2;
#pragma unroll
        for (int mb = 0; mb < 4; mb++) {
#pragma unroll
            for (int nb = 0; nb < 4; nb++) {
                const int c = cLoc + nb * 8;
                const float bx = __ldg(bias + n0 + c);
                const float by = __ldg(bias + n0 + c + 1);
                const int rA = rLoc + mb * 16, rB = rA + 8;
                sv[(c + 0) * VP + rA] = acc[mb][nb][0] + bx;
                sv[(c + 1) * VP + rA] = acc[mb][nb][1] + by;
                sv[(c + 0) * VP + rB] = acc[mb][nb][2] + bx;
                sv[(c + 1) * VP + rB] = acc[mb][nb][3] + by;
            }
        }
        __syncthreads();
#pragma unroll
        for (int i = 0; i < 16; i++) {
            const int c = (tid >> 5) + i * 8;            // 0..127 local col
            const int cpart = cp0 + c;
            const int h = cpart >> 6, d = cpart & 63;
            float4 v = *(float4*)&sv[c * VP + lane * 4];
            uint32_t hA = packbf2(v.x, v.y), lA = packlo2(v.x, v.y, hA);
            uint32_t hB = packbf2(v.z, v.w), lB = packlo2(v.z, v.w, hB);
            const size_t dst =
                ((size_t)(b * NHEADS + h) * DHEAD + d) * TSEQ + t0 + lane * 4;
            *(uint2*)(Vh + dst) = make_uint2(hA, hB);
            *(uint2*)(Vl + dst) = make_uint2(lA, lB);
        }
    }
}

// ---------------------------------------------------------------------------
// Tensor-core causal flash attention (bf16 hi/lo, fp32 softmax).
// R10: xor-swizzled 64x128B tiles + 3-stage pipeline, 1 sync per key tile.
// ---------------------------------------------------------------------------
#define AT_TILE   8192                    // 64 rows x 128 B, swizzled
#define AT_STAGE  (4 * AT_TILE)           // Khi,Klo,Vhi,Vlo = 32 KB
#define ATTN_SMEM (3 * AT_STAGE)          // 96 KB

// swizzled offset within a 64x128B tile (ch in 16B units, 0..7)
__device__ __forceinline__ uint32_t aswz(int row, int ch) {
    return (uint32_t)(row * 128 + ((ch ^ (row & 7)) << 4));
}

__device__ __forceinline__ void at_load_stage(
    uint32_t st, const __nv_bfloat16* Khp, const __nv_bfloat16* Klp,
    const __nv_bfloat16* Vhp, const __nv_bfloat16* Vlp, int koff, int tid) {
#pragma unroll
    for (int i = 0; i < 8; i++) {
        int chunk = tid + i * 256;                 // 2048 chunks
        int tile = chunk >> 9, within = chunk & 511;
        int row = within >> 3, ch = within & 7;
        uint32_t dst = st + tile * AT_TILE + aswz(row, ch);
        if (tile == 0)      cp16(dst, Khp + (size_t)(koff + row) * DHEAD + ch * 8);
        else if (tile == 1) cp16(dst, Klp + (size_t)(koff + row) * DHEAD + ch * 8);
        else if (tile == 2) cp16(dst, Vhp + (size_t)row * TSEQ + koff + ch * 8);
        else                cp16(dst, Vlp + (size_t)row * TSEQ + koff + ch * 8);
    }
    cp_commit();
}

__global__ __launch_bounds__(256)
void attn_tc(const __nv_bfloat16* __restrict__ Qh, const __nv_bfloat16* __restrict__ Ql,
             const __nv_bfloat16* __restrict__ Kh, const __nv_bfloat16* __restrict__ Kl,
             const __nv_bfloat16* __restrict__ Vh, const __nv_bfloat16* __restrict__ Vl,
             __nv_bfloat16* __restrict__ Oh, __nv_bfloat16* __restrict__ Ol) {
    extern __shared__ char smem[];
    const uint32_t sbase = smem_u32(smem);

    const int tid  = threadIdx.x;
    const int wid  = tid >> 5;
    const int lane = tid & 31;
    const int qt = (gridDim.x - 1) - blockIdx.x;       // heavy tiles first
    const int h  = blockIdx.y;
    const int b  = blockIdx.z;
    const int bh = b * NHEADS + h;
    const int nkt = 2 * qt + 2;

    const __nv_bfloat16* Qhp = Qh + ((size_t)bh * TSEQ + qt * 128) * DHEAD;
    const __nv_bfloat16* Qlp = Ql + ((size_t)bh * TSEQ + qt * 128) * DHEAD;
    const __nv_bfloat16* Khp = Kh + (size_t)bh * TSEQ * DHEAD;
    const __nv_bfloat16* Klp = Kl + (size_t)bh * TSEQ * DHEAD;
    const __nv_bfloat16* Vhp = Vh + (size_t)bh * DHEAD * TSEQ;
    const __nv_bfloat16* Vlp = Vl + (size_t)bh * DHEAD * TSEQ;

    // ---- stage Q (128 rows x 128 B, swizzled) into stage-0/1 region ----
#pragma unroll
    for (int i = 0; i < 8; i++) {
        int chunk = tid + i * 256;                 // 2048 chunks
        int sel = chunk >> 10, within = chunk & 1023;
        int row = within >> 3, ch = within & 7;
        uint32_t dst = sbase + sel * 16384 + (uint32_t)row * 128 + ((ch ^ (row & 7)) << 4);
        cp16(dst, (sel ? Qlp : Qhp) + (size_t)row * DHEAD + ch * 8);
    }
    cp_commit();
    asm volatile("cp.async.wait_group 0;" ::: "memory");
    __syncthreads();

    uint32_t qhi[4][4], qlo[4][4];
    {
        const int qrow = wid * 16 + (lane & 15);
        const int qsw = qrow & 7;
        const uint32_t qb = sbase + (uint32_t)qrow * 128;
#pragma unroll
        for (int kb = 0; kb < 4; kb++) {
            const uint32_t off = (uint32_t)(((kb * 2 + (lane >> 4)) ^ qsw) << 4);
            LDSM4(qhi[kb], qb + off);
            LDSM4(qlo[kb], qb + 16384 + off);
        }
    }
    __syncthreads();

    // B-operand per-lane constants
    const int rB0 = (lane & 7) + ((lane >> 4) << 3);   // 0..15
    const int chB = (lane >> 3) & 1;

    float o[8][4];
#pragma unroll
    for (int nb = 0; nb < 8; nb++)
#pragma unroll
        for (int r = 0; r < 4; r++) o[nb][r] = 0.0f;
    float m0 = -INFINITY, m1 = -INFINITY, l0 = 0.0f, l1 = 0.0f;

    const int qrow_lo = qt * 128 + wid * 16;
    const int r0g = qrow_lo + (lane >> 2);
    const int r1g = r0g + 8;

    // ---- prologue: key tiles 0,1 -> stages 0,1 (nkt >= 2 always) ----
    at_load_stage(sbase + 0 * AT_STAGE, Khp, Klp, Vhp, Vlp, 0, tid);
    at_load_stage(sbase + 1 * AT_STAGE, Khp, Klp, Vhp, Vlp, 64, tid);

    for (int kt = 0; kt < nkt; kt++) {
        if (kt + 1 < nkt) {
            asm volatile("cp.async.wait_group 1;" ::: "memory");
        } else {
            asm volatile("cp.async.wait_group 0;" ::: "memory");
        }
        __syncthreads();
        if (kt + 2 < nkt)
            at_load_stage(sbase + ((kt + 2) % 3) * AT_STAGE, Khp, Klp, Vhp, Vlp,
                          (kt + 2) * 64, tid);

        if (kt * 64 <= qrow_lo + 15) {
            const uint32_t st = sbase + (kt % 3) * AT_STAGE;

            // ---- S = Q K^T (hi/lo split) ----
            float s[8][4];
#pragma unroll
            for (int nb = 0; nb < 8; nb++)
#pragma unroll
                for (int r = 0; r < 4; r++) s[nb][r] = 0.0f;

#pragma unroll
            for (int kb = 0; kb < 4; kb++) {
                uint32_t kh[4][4], kl[4][4];
#pragma unroll
                for (int g = 0; g < 4; g++) {
                    const int row = g * 16 + rB0;
                    const uint32_t ba = st + (uint32_t)row * 128
                                      + (uint32_t)(((kb * 2 + chB) ^ (row & 7)) << 4);
                    LDSM4(kh[g], ba);
                    LDSM4(kl[g], ba + AT_TILE);
                }
#pragma unroll
                for (int g = 0; g < 4; g++)
#pragma unroll
                    for (int half = 0; half < 2; half++) {
                        const int nb = 2 * g + half, h2 = half * 2;
                        MMA_BF16(s[nb], qhi[kb], kh[g][h2], kh[g][h2 + 1]);
                        MMA_BF16(s[nb], qhi[kb], kl[g][h2], kl[g][h2 + 1]);
                        MMA_BF16(s[nb], qlo[kb], kh[g][h2], kh[g][h2 + 1]);
                    }
            }

            // ---- causal mask (only needed near diagonal) ----
            if (kt * 64 + 63 > qrow_lo) {
#pragma unroll
                for (int nb = 0; nb < 8; nb++) {
                    int c = kt * 64 + nb * 8 + (lane & 3) * 2;
                    if (c > r0g)     s[nb][0] = -INFINITY;
                    if (c + 1 > r0g) s[nb][1] = -INFINITY;
                    if (c > r1g)     s[nb][2] = -INFINITY;
                    if (c + 1 > r1g) s[nb][3] = -INFINITY;
                }
            }

            // ---- online softmax ----
            float mx0 = -INFINITY, mx1 = -INFINITY;
#pragma unroll
            for (int nb = 0; nb < 8; nb++) {
                mx0 = fmaxf(mx0, fmaxf(s[nb][0], s[nb][1]));
                mx1 = fmaxf(mx1, fmaxf(s[nb][2], s[nb][3]));
            }
            mx0 = fmaxf(mx0, __shfl_xor_sync(0xffffffffu, mx0, 1));
            mx0 = fmaxf(mx0, __shfl_xor_sync(0xffffffffu, mx0, 2));
            mx1 = fmaxf(mx1, __shfl_xor_sync(0xffffffffu, mx1, 1));
            mx1 = fmaxf(mx1, __shfl_xor_sync(0xffffffffu, mx1, 2));

            float mn0 = fmaxf(m0, mx0), mn1 = fmaxf(m1, mx1);
            float c0 = __expf(m0 - mn0), c1 = __expf(m1 - mn1);
            m0 = mn0; m1 = mn1;

            float rs0 = 0.0f, rs1 = 0.0f;
#pragma unroll
            for (int nb = 0; nb < 8; nb++) {
                s[nb][0] = __expf(s[nb][0] - m0); rs0 += s[nb][0];
                s[nb][1] = __expf(s[nb][1] - m0); rs0 += s[nb][1];
                s[nb][2] = __expf(s[nb][2] - m1); rs1 += s[nb][2];
                s[nb][3] = __expf(s[nb][3] - m1); rs1 += s[nb][3];
            }
            rs0 += __shfl_xor_sync(0xffffffffu, rs0, 1);
            rs0 += __shfl_xor_sync(0xffffffffu, rs0, 2);
            rs1 += __shfl_xor_sync(0xffffffffu, rs1, 1);
            rs1 += __shfl_xor_sync(0xffffffffu, rs1, 2);
            l0 = l0 * c0 + rs0;
            l1 = l1 * c1 + rs1;
#pragma unroll
            for (int nb = 0; nb < 8; nb++) {
                o[nb][0] *= c0; o[nb][1] *= c0;
                o[nb][2] *= c1; o[nb][3] *= c1;
            }

            // ---- O += P V  (P converted in-register to A fragments) ----
#pragma unroll
            for (int kbp = 0; kbp < 4; kbp++) {
                uint32_t phi[4], plo[4];
                const int e = 2 * kbp;
                phi[0] = packbf2(s[e][0], s[e][1]);
                phi[1] = packbf2(s[e][2], s[e][3]);
                phi[2] = packbf2(s[e + 1][0], s[e + 1][1]);
                phi[3] = packbf2(s[e + 1][2], s[e + 1][3]);
                plo[0] = packlo2(s[e][0], s[e][1], phi[0]);
                plo[1] = packlo2(s[e][2], s[e][3], phi[1]);
                plo[2] = packlo2(s[e + 1][0], s[e + 1][1], phi[2]);
                plo[3] = packlo2(s[e + 1][2], s[e + 1][3], phi[3]);

                uint32_t vh[4][4], vl[4][4];
#pragma unroll
                for (int g = 0; g < 4; g++) {
                    const int row = g * 16 + rB0;
                    const uint32_t ba = st + 2 * AT_TILE + (uint32_t)row * 128
                                      + (uint32_t)(((kbp * 2 + chB) ^ (row & 7)) << 4);
                    LDSM4(vh[g], ba);
                    LDSM4(vl[g], ba + AT_TILE);
                }
#pragma unroll
                for (int g = 0; g < 4; g++)
#pragma unroll
                    for (int half = 0; half < 2; half++) {
                        const int nbd = 2 * g + half, h2 = half * 2;
                        MMA_BF16(o[nbd], phi, vh[g][h2], vh[g][h2 + 1]);
                        MMA_BF16(o[nbd], plo, vh[g][h2], vh[g][h2 + 1]);
                        MMA_BF16(o[nbd], phi, vl[g][h2], vl[g][h2 + 1]);
                    }
            }
        }
    }

    // ---- epilogue: normalize, split hi/lo, store bf16 pairs ----
    const float inv0 = 1.0f / l0, inv1 = 1.0f / l1;
    const size_t grow0 = (size_t)b * TSEQ + r0g;
    const size_t grow1 = grow0 + 8;
    const int colb = h * DHEAD + (lane & 3) * 2;
#pragma unroll
    for (int nbd = 0; nbd < 8; nbd++) {
        const int col = colb + nbd * 8;
        float f00 = o[nbd][0] * inv0, f01 = o[nbd][1] * inv0;
        float f10 = o[nbd][2] * inv1, f11 = o[nbd][3] * inv1;
        uint32_t h0 = packbf2(f00, f01), l0p = packlo2(f00, f01, h0);
        uint32_t h1 = packbf2(f10, f11), l1p = packlo2(f10, f11, h1);
        *(uint32_t*)(Oh + grow0 * DEMBD + col) = h0;
        *(uint32_t*)(Ol + grow0 * DEMBD + col) = l0p;
        *(uint32_t*)(Oh + grow1 * DEMBD + col) = h1;
        *(uint32_t*)(Ol + grow1 * DEMBD + col) = l1p;
    }
}

// ---------------------------------------------------------------------------
extern "C" void kernel_launch(void* const* d_in, const int* in_sizes, int n_in,
                              void* d_out, int out_size) {
    const float* x  = (const float*)d_in[0];
    const float* W1 = (const float*)d_in[1];
    const float* b1 = (const float*)d_in[2];
    const float* W2 = (const float*)d_in[3];
    const float* b2 = (const float*)d_in[4];
    float* out = (float*)d_out;

    __nv_bfloat16 *A1h, *A1l, *A2h, *A2l, *W1h, *W1l, *W2h, *W2l;
    __nv_bfloat16 *Qh, *Ql, *Kh, *Kl, *Vh, *Vl;
    cudaGetSymbolAddress((void**)&A1h, g_A1hi);
    cudaGetSymbolAddress((void**)&A1l, g_A1lo);
    cudaGetSymbolAddress((void**)&A2h, g_A2hi);
    cudaGetSymbolAddress((void**)&A2l, g_A2lo);
    cudaGetSymbolAddress((void**)&W1h, g_W1Thi);
    cudaGetSymbolAddress((void**)&W1l, g_W1Tlo);
    cudaGetSymbolAddress((void**)&W2h, g_W2Thi);
    cudaGetSymbolAddress((void**)&W2l, g_W2Tlo);
    cudaGetSymbolAddress((void**)&Qh, g_Qhi);
    cudaGetSymbolAddress((void**)&Ql, g_Qlo);
    cudaGetSymbolAddress((void**)&Kh, g_Khi);
    cudaGetSymbolAddress((void**)&Kl, g_Klo);
    cudaGetSymbolAddress((void**)&Vh, g_Vthi);
    cudaGetSymbolAddress((void**)&Vl, g_Vtlo);

    cudaFuncSetAttribute(gemm_bf16_mma, cudaFuncAttributeMaxDynamicSharedMemorySize, GEMM_SMEM);
    cudaFuncSetAttribute(gemm1_qkv,    cudaFuncAttributeMaxDynamicSharedMemorySize, GEMM_SMEM);
    cudaFuncSetAttribute(attn_tc,      cudaFuncAttributeMaxDynamicSharedMemorySize, ATTN_SMEM);

    // 0) input conversions
    {
        int n4 = MROWS * DEMBD / 4;
        split_f32<<<(n4 + 255) / 256, 256>>>(x, A1h, A1l, n4);
        transpose_split<<<dim3(KQV_N / 32, DEMBD / 32), dim3(32, 8)>>>(W1, W1h, W1l, DEMBD, KQV_N);
        transpose_split<<<dim3(DEMBD / 32, DEMBD / 32), dim3(32, 8)>>>(W2, W2h, W2l, DEMBD, DEMBD);
    }
    // 1) kqv = x @ W1 + b1, epilogue writes per-head bf16 hi/lo Q/K/V directly
    gemm1_qkv<<<dim3(KQV_N / 128, MROWS / 128), 256, GEMM_SMEM>>>(
        A1h, A1l, W1h, W1l, b1, Qh, Ql, Kh, Kl, Vh, Vl);
    // 2) causal attention (tensor cores), writes A2 hi/lo directly
    attn_tc<<<dim3(TSEQ / 128, NHEADS, BS), 256, ATTN_SMEM>>>(
        Qh, Ql, Kh, Kl, Vh, Vl, A2h, A2l);
    // 3) out = att @ W2 + b2  (tensor cores)
    gemm_bf16_mma<<<dim3(DEMBD / 128, MROWS / 128), 256, GEMM_SMEM>>>(
        A2h, A2l, W2h, W2l, b2, out, MROWS, DEMBD, DEMBD);
}

// round 13
// speedup vs baseline: 2.9220x; 1.0068x over previous
#include <cuda_runtime.h>
#include <cuda_bf16.h>
#include <math.h>
#include <stdint.h>

// Problem constants
#define BS      2
#define TSEQ    2048
#define DEMBD   1024
#define NHEADS  16
#define DHEAD   64
#define MROWS   (BS * TSEQ)      // 4096
#define KQV_N   (3 * DEMBD)      // 3072
#define BH      (BS * NHEADS)    // 32

// ---------------------------------------------------------------------------
// Scratch (__device__ globals; allocation-free rule)
// ---------------------------------------------------------------------------
__device__ __nv_bfloat16 g_A1hi[MROWS * DEMBD];
__device__ __nv_bfloat16 g_A1lo[MROWS * DEMBD];
__device__ __nv_bfloat16 g_A2hi[MROWS * DEMBD];   // written by attention
__device__ __nv_bfloat16 g_A2lo[MROWS * DEMBD];
__device__ __nv_bfloat16 g_W1Thi[KQV_N * DEMBD];
__device__ __nv_bfloat16 g_W1Tlo[KQV_N * DEMBD];
__device__ __nv_bfloat16 g_W2Thi[DEMBD * DEMBD];
__device__ __nv_bfloat16 g_W2Tlo[DEMBD * DEMBD];

// Attention operands, per-head layouts (bf16 hi/lo) — written by GEMM1 epilogue
__device__ __nv_bfloat16 g_Qhi[BH * TSEQ * DHEAD];  // [bh][t][d], pre-scaled
__device__ __nv_bfloat16 g_Qlo[BH * TSEQ * DHEAD];
__device__ __nv_bfloat16 g_Khi[BH * TSEQ * DHEAD];  // [bh][t][d]
__device__ __nv_bfloat16 g_Klo[BH * TSEQ * DHEAD];
__device__ __nv_bfloat16 g_Vthi[BH * DHEAD * TSEQ]; // [bh][d][t]  (transposed)
__device__ __nv_bfloat16 g_Vtlo[BH * DHEAD * TSEQ];

// ---------------------------------------------------------------------------
// PTX helpers (baseline ISA only)
// ---------------------------------------------------------------------------
__device__ __forceinline__ uint32_t smem_u32(const void* p) {
    uint32_t a;
    asm("{ .reg .u64 t; cvta.to.shared.u64 t, %1; cvt.u32.u64 %0, t; }" : "=r"(a) : "l"(p));
    return a;
}
__device__ __forceinline__ void cp16(uint32_t dst, const void* src) {
    asm volatile("cp.async.cg.shared.global [%0], [%1], 16;"
                 :: "r"(dst), "l"(__cvta_generic_to_global(src)));
}
__device__ __forceinline__ void cp_commit() { asm volatile("cp.async.commit_group;" ::: "memory"); }

#define LDSM4(r, addr) \
    asm volatile("ldmatrix.sync.aligned.m8n8.x4.shared.b16 {%0,%1,%2,%3}, [%4];" \
        : "=r"((r)[0]), "=r"((r)[1]), "=r"((r)[2]), "=r"((r)[3]) : "r"(addr))

#define MMA_BF16(d, a, b0, b1) \
    asm volatile("mma.sync.aligned.m16n8k16.row.col.f32.bf16.bf16.f32 " \
        "{%0,%1,%2,%3}, {%4,%5,%6,%7}, {%8,%9}, {%0,%1,%2,%3};" \
        : "+f"((d)[0]), "+f"((d)[1]), "+f"((d)[2]), "+f"((d)[3]) \
        : "r"((a)[0]), "r"((a)[1]), "r"((a)[2]), "r"((a)[3]), "r"(b0), "r"(b1))

// pack two fp32 into bf16x2: low half <- lo, high half <- hi
__device__ __forceinline__ uint32_t packbf2(float lo, float hi) {
    uint32_t r;
    asm("cvt.rn.bf16x2.f32 %0, %1, %2;" : "=r"(r) : "f"(hi), "f"(lo));
    return r;
}
// residual (lo-part) pack given the hi-pack
__device__ __forceinline__ uint32_t packlo2(float lo, float hi, uint32_t hp) {
    __nv_bfloat162 hv = *reinterpret_cast<__nv_bfloat162*>(&hp);
    return packbf2(lo - __bfloat162float(hv.x), hi - __bfloat162float(hv.y));
}

// ---------------------------------------------------------------------------
// fp32 -> bf16 hi/lo split (elementwise, float4)  [x -> A1]
// ---------------------------------------------------------------------------
__global__ void split_f32(const float* __restrict__ in, __nv_bfloat16* __restrict__ hi,
                          __nv_bfloat16* __restrict__ lo, int n4) {
    int i = blockIdx.x * blockDim.x + threadIdx.x;
    if (i >= n4) return;
    float4 v = ((const float4*)in)[i];
    uint32_t h0 = packbf2(v.x, v.y), h1 = packbf2(v.z, v.w);
    uint32_t l0 = packlo2(v.x, v.y, h0), l1 = packlo2(v.z, v.w, h1);
    ((uint32_t*)hi)[i * 2 + 0] = h0;
    ((uint32_t*)hi)[i * 2 + 1] = h1;
    ((uint32_t*)lo)[i * 2 + 0] = l0;
    ((uint32_t*)lo)[i * 2 + 1] = l1;
}

// ---------------------------------------------------------------------------
// W[K][N] fp32 -> W^T[N][K] bf16 hi/lo (tiled transpose)
// ---------------------------------------------------------------------------
__global__ void transpose_split(const float* __restrict__ W, __nv_bfloat16* __restrict__ hiT,
                                __nv_bfloat16* __restrict__ loT, int K, int N) {
    __shared__ float t[32][33];
    int n = blockIdx.x * 32 + threadIdx.x;
    int k0 = blockIdx.y * 32;
#pragma unroll
    for (int i = 0; i < 32; i += 8)
        t[threadIdx.y + i][threadIdx.x] = W[(size_t)(k0 + threadIdx.y + i) * N + n];
    __syncthreads();
    int kk = k0 + threadIdx.x;
#pragma unroll
    for (int i = 0; i < 32; i += 8) {
        int nn = blockIdx.x * 32 + threadIdx.y + i;
        float v = t[threadIdx.x][threadIdx.y + i];
        __nv_bfloat16 h = __float2bfloat16(v);
        __nv_bfloat16 l = __float2bfloat16(v - __bfloat162float(h));
        hiT[(size_t)nn * K + kk] = h;
        loT[(size_t)nn * K + kk] = l;
    }
}

// ---------------------------------------------------------------------------
// GEMM tiling: 128x128 CTA tile, BK=32 slabs, xor-swizzled smem (64B rows,
// 16B chunk ^= (row&6)>>1), 3-stage cp.async pipeline, 1 sync per slab.
// ---------------------------------------------------------------------------
#define BK        32
#define TILE_B    8192                 // 128 rows x 64 B (swizzled, no pad)
#define STAGE_B   (4 * TILE_B)         // Ah, Al, Bh, Bl = 32 KB
#define GEMM_SMEM (3 * STAGE_B)        // 96 KB -> 2 CTAs/SM

__device__ __forceinline__ uint32_t swz16(int row, int ch) {
    return (uint32_t)(row * 64 + ((ch ^ ((row & 6) >> 1)) << 4));
}

__device__ __forceinline__ void load_tile(uint32_t tb, const __nv_bfloat16* sp, int K, int tid) {
#pragma unroll
    for (int i = 0; i < 2; i++) {
        int q = tid + i * 256;             // 512 16B-chunks per tile
        int row = q >> 2, c16 = q & 3;
        cp16(tb + swz16(row, c16), sp + (size_t)row * K + c16 * 8);
    }
}

__device__ __forceinline__ void load_stage(uint32_t st, const __nv_bfloat16* Ah0,
                                           const __nv_bfloat16* Al0, const __nv_bfloat16* Bh0,
                                           const __nv_bfloat16* Bl0, int k0, int K, int tid) {
    load_tile(st + 0 * TILE_B, Ah0 + k0, K, tid);
    load_tile(st + 1 * TILE_B, Al0 + k0, K, tid);
    load_tile(st + 2 * TILE_B, Bh0 + k0, K, tid);
    load_tile(st + 3 * TILE_B, Bl0 + k0, K, tid);
    cp_commit();
}

// Mainloop shared by both GEMM kernels. Ends with one __syncthreads()
// (so epilogues may immediately reuse smem).
__device__ __forceinline__ void gemm_mainloop(
    uint32_t sbase, const __nv_bfloat16* Ah0, const __nv_bfloat16* Al0,
    const __nv_bfloat16* Bh0, const __nv_bfloat16* Bl0, int K, int tid,
    int wm, int wn, int lane, float acc[4][4][4]) {

    const int NSLAB = K / BK;
    const int rowA = wm + (lane & 15);
    const int chA  = lane >> 4;                         // 0..1
    const int rowB = wn + (lane & 7) + ((lane >> 4) << 3);
    const int chB  = (lane >> 3) & 1;                   // 0..1
    const uint32_t aRow = (uint32_t)rowA * 64;
    const uint32_t bRow = (uint32_t)rowB * 64;
    const int aSwz = (rowA & 6) >> 1;
    const int bSwz = (rowB & 6) >> 1;

    // prologue: slabs 0,1 -> stages 0,1
    load_stage(sbase + 0 * STAGE_B, Ah0, Al0, Bh0, Bl0, 0, K, tid);
    load_stage(sbase + 1 * STAGE_B, Ah0, Al0, Bh0, Bl0, BK, K, tid);

    for (int s = 0; s < NSLAB; s++) {
        if (s + 1 < NSLAB) {
            asm volatile("cp.async.wait_group 1;" ::: "memory");
        } else {
            asm volatile("cp.async.wait_group 0;" ::: "memory");
        }
        __syncthreads();
        if (s + 2 < NSLAB)
            load_stage(sbase + ((s + 2) % 3) * STAGE_B, Ah0, Al0, Bh0, Bl0,
                       (s + 2) * BK, K, tid);

        const uint32_t st = sbase + (s % 3) * STAGE_B;
#pragma unroll
        for (int kk = 0; kk < BK; kk += 16) {
            const int kc = kk >> 3;                     // 0 or 2
            uint32_t bh[2][4], bl[2][4];
#pragma unroll
            for (int g = 0; g < 2; g++) {
                const uint32_t ba = st + bRow + (uint32_t)(g * 1024)
                                  + (uint32_t)(((kc | chB) ^ bSwz) << 4);
                LDSM4(bh[g], ba + 2 * TILE_B);
                LDSM4(bl[g], ba + 3 * TILE_B);
            }
#pragma unroll
            for (int mb = 0; mb < 4; mb++) {
                const uint32_t aa = st + aRow + (uint32_t)(mb * 1024)
                                  + (uint32_t)(((kc | chA) ^ aSwz) << 4);
                uint32_t ah[4], al[4];
                LDSM4(ah, aa + 0 * TILE_B);
                LDSM4(al, aa + 1 * TILE_B);
#pragma unroll
                for (int nb = 0; nb < 4; nb++) {
                    const int g = nb >> 1, h2 = (nb & 1) * 2;
                    MMA_BF16(acc[mb][nb], ah, bh[g][h2], bh[g][h2 + 1]);
                    MMA_BF16(acc[mb][nb], ah, bl[g][h2], bl[g][h2 + 1]);
                    MMA_BF16(acc[mb][nb], al, bh[g][h2], bh[g][h2 + 1]);
                }
            }
        }
    }
    __syncthreads();   // epilogues may reuse smem
}

// ---------------------------------------------------------------------------
// GEMM2: generic fp32-output GEMM + bias (att @ W2 + b2 -> out)
// ---------------------------------------------------------------------------
__global__ __launch_bounds__(256, 2)
void gemm_bf16_mma(const __nv_bfloat16* __restrict__ Ah, const __nv_bfloat16* __restrict__ Al,
                   const __nv_bfloat16* __restrict__ Bh, const __nv_bfloat16* __restrict__ Bl,
                   const float* __restrict__ bias, float* __restrict__ C,
                   int M, int N, int K) {
    extern __shared__ char smem[];
    const uint32_t sbase = smem_u32(smem);

    const int tid  = threadIdx.x;
    const int wid  = tid >> 5;
    const int lane = tid & 31;
    const int m0 = blockIdx.y * 128;
    const int n0 = blockIdx.x * 128;
    const int wm = (wid & 1) * 64;
    const int wn = (wid >> 1) * 32;

    float acc[4][4][4];
#pragma unroll
    for (int mb = 0; mb < 4; mb++)
#pragma unroll
        for (int nb = 0; nb < 4; nb++)
#pragma unroll
            for (int r = 0; r < 4; r++) acc[mb][nb][r] = 0.0f;

    gemm_mainloop(sbase, Ah + (size_t)m0 * K, Al + (size_t)m0 * K,
                  Bh + (size_t)n0 * K, Bl + (size_t)n0 * K, K, tid, wm, wn, lane, acc);

    const int rBase = m0 + wm + (lane >> 2);
    const int cBase = n0 + wn + (lane & 3) * 2;
#pragma unroll
    for (int mb = 0; mb < 4; mb++) {
#pragma unroll
        for (int nb = 0; nb < 4; nb++) {
            const int col = cBase + nb * 8;
            const float bx = __ldg(bias + col);
            const float by = __ldg(bias + col + 1);
            float* p0 = C + (size_t)(rBase + mb * 16) * N + col;
            float* p1 = C + (size_t)(rBase + mb * 16 + 8) * N + col;
            *(float2*)p0 = make_float2(acc[mb][nb][0] + bx, acc[mb][nb][1] + by);
            *(float2*)p1 = make_float2(acc[mb][nb][2] + bx, acc[mb][nb][3] + by);
        }
    }
}

// ---------------------------------------------------------------------------
// GEMM1 with fused QKV epilogue: x @ W1 + b1, written directly as per-head
// bf16 hi/lo attention operands (Q scaled; V transposed via smem staging).
// ---------------------------------------------------------------------------
#define VP 132   // fp32 smem pitch for V transpose staging (128 + 4 pad)

__global__ __launch_bounds__(256, 2)
void gemm1_qkv(const __nv_bfloat16* __restrict__ Ah, const __nv_bfloat16* __restrict__ Al,
               const __nv_bfloat16* __restrict__ Bh, const __nv_bfloat16* __restrict__ Bl,
               const float* __restrict__ bias,
               __nv_bfloat16* __restrict__ Qh, __nv_bfloat16* __restrict__ Ql,
               __nv_bfloat16* __restrict__ Kh, __nv_bfloat16* __restrict__ Kl,
               __nv_bfloat16* __restrict__ Vh, __nv_bfloat16* __restrict__ Vl) {
    extern __shared__ char smem[];
    const uint32_t sbase = smem_u32(smem);
    const int K = DEMBD;

    const int tid  = threadIdx.x;
    const int wid  = tid >> 5;
    const int lane = tid & 31;
    const int m0 = blockIdx.y * 128;
    const int n0 = blockIdx.x * 128;
    const int wm = (wid & 1) * 64;
    const int wn = (wid >> 1) * 32;

    float acc[4][4][4];
#pragma unroll
    for (int mb = 0; mb < 4; mb++)
#pragma unroll
        for (int nb = 0; nb < 4; nb++)
#pragma unroll
            for (int r = 0; r < 4; r++) acc[mb][nb][r] = 0.0f;

    gemm_mainloop(sbase, Ah + (size_t)m0 * K, Al + (size_t)m0 * K,
                  Bh + (size_t)n0 * K, Bl + (size_t)n0 * K, K, tid, wm, wn, lane, acc);

    const int part = n0 >> 10;              // 0 = K, 1 = Q, 2 = V
    const int b    = m0 >> 11;              // batch
    const int t0   = m0 & 2047;             // t of tile row 0
    const int cp0  = n0 & 1023;             // col offset within part

    if (part < 2) {
        // ---- K / Q: direct per-head [bh][t][64] bf16 hi/lo stores ----
        __nv_bfloat16* Dh = (part == 0) ? Kh : Qh;
        __nv_bfloat16* Dl = (part == 0) ? Kl : Ql;
        const float qscale = (part == 1) ? 0.125f : 1.0f;
        const int rLoc = wm + (lane >> 2);
        const int cLoc = wn + (lane & 3) * 2;
#pragma unroll
        for (int mb = 0; mb < 4; mb++) {
#pragma unroll
            for (int nb = 0; nb < 4; nb++) {
                const int c = cLoc + nb * 8;              // 0..127 local
                const int cpart = cp0 + c;                // 0..1023 within part
                const int h = cpart >> 6, d = cpart & 63;
                const float bx = __ldg(bias + n0 + c);
                const float by = __ldg(bias + n0 + c + 1);
                float f0 = (acc[mb][nb][0] + bx) * qscale;
                float f1 = (acc[mb][nb][1] + by) * qscale;
                float f2 = (acc[mb][nb][2] + bx) * qscale;
                float f3 = (acc[mb][nb][3] + by) * qscale;
                const size_t base = ((size_t)(b * NHEADS + h) * TSEQ);
                const int tA = t0 + rLoc + mb * 16;
                const int tB = tA + 8;
                uint32_t h0 = packbf2(f0, f1), l0 = packlo2(f0, f1, h0);
                uint32_t h1 = packbf2(f2, f3), l1 = packlo2(f2, f3, h1);
                *(uint32_t*)(Dh + (base + tA) * DHEAD + d) = h0;
                *(uint32_t*)(Dl + (base + tA) * DHEAD + d) = l0;
                *(uint32_t*)(Dh + (base + tB) * DHEAD + d) = h1;
                *(uint32_t*)(Dl + (base + tB) * DHEAD + d) = l1;
            }
        }
    } else {
        // ---- V: stage (bias-added fp32) into smem as [col][row], then write
        //      transposed per-head [bh][d][t] bf16 hi/lo, coalesced over t ----
        float* sv = (float*)smem;
        const int rLoc = wm + (lane >> 2);
        const int cLoc = wn + (lane & 3) * 2;
#pragma unroll
        for (int mb = 0; mb < 4; mb++) {
#pragma unroll
            for (int nb = 0; nb < 4; nb++) {
                const int c = cLoc + nb * 8;
                const float bx = __ldg(bias + n0 + c);
                const float by = __ldg(bias + n0 + c + 1);
                const int rA = rLoc + mb * 16, rB = rA + 8;
                sv[(c + 0) * VP + rA] = acc[mb][nb][0] + bx;
                sv[(c + 1) * VP + rA] = acc[mb][nb][1] + by;
                sv[(c + 0) * VP + rB] = acc[mb][nb][2] + bx;
                sv[(c + 1) * VP + rB] = acc[mb][nb][3] + by;
            }
        }
        __syncthreads();
#pragma unroll
        for (int i = 0; i < 16; i++) {
            const int c = (tid >> 5) + i * 8;            // 0..127 local col
            const int cpart = cp0 + c;
            const int h = cpart >> 6, d = cpart & 63;
            float4 v = *(float4*)&sv[c * VP + lane * 4];
            uint32_t hA = packbf2(v.x, v.y), lA = packlo2(v.x, v.y, hA);
            uint32_t hB = packbf2(v.z, v.w), lB = packlo2(v.z, v.w, hB);
            const size_t dst =
                ((size_t)(b * NHEADS + h) * DHEAD + d) * TSEQ + t0 + lane * 4;
            *(uint2*)(Vh + dst) = make_uint2(hA, hB);
            *(uint2*)(Vl + dst) = make_uint2(lA, lB);
        }
    }
}

// ---------------------------------------------------------------------------
// Tensor-core causal flash attention (bf16 hi/lo, fp32 softmax).
// R13: 2 CTAs/SM (reg cap 128). Persistent Q in smem (32 KB, fragments
// re-loaded per k-step), 2-stage K/V pipeline (2 x 32 KB). 96 KB total.
// ---------------------------------------------------------------------------
#define AT_TILE   8192                    // 64 rows x 128 B, swizzled
#define AT_STAGE  (4 * AT_TILE)           // Khi,Klo,Vhi,Vlo = 32 KB
#define AT_QSZ    32768                   // Q hi (16 KB) + Q lo (16 KB)
#define ATTN_SMEM (AT_QSZ + 2 * AT_STAGE) // 96 KB -> 2 CTAs/SM

// swizzled offset within a 64x128B tile (ch in 16B units, 0..7)
__device__ __forceinline__ uint32_t aswz(int row, int ch) {
    return (uint32_t)(row * 128 + ((ch ^ (row & 7)) << 4));
}

__device__ __forceinline__ void at_load_stage(
    uint32_t st, const __nv_bfloat16* Khp, const __nv_bfloat16* Klp,
    const __nv_bfloat16* Vhp, const __nv_bfloat16* Vlp, int koff, int tid) {
#pragma unroll
    for (int i = 0; i < 8; i++) {
        int chunk = tid + i * 256;                 // 2048 chunks
        int tile = chunk >> 9, within = chunk & 511;
        int row = within >> 3, ch = within & 7;
        uint32_t dst = st + tile * AT_TILE + aswz(row, ch);
        if (tile == 0)      cp16(dst, Khp + (size_t)(koff + row) * DHEAD + ch * 8);
        else if (tile == 1) cp16(dst, Klp + (size_t)(koff + row) * DHEAD + ch * 8);
        else if (tile == 2) cp16(dst, Vhp + (size_t)row * TSEQ + koff + ch * 8);
        else                cp16(dst, Vlp + (size_t)row * TSEQ + koff + ch * 8);
    }
    cp_commit();
}

__global__ __launch_bounds__(256, 2)
void attn_tc(const __nv_bfloat16* __restrict__ Qh, const __nv_bfloat16* __restrict__ Ql,
             const __nv_bfloat16* __restrict__ Kh, const __nv_bfloat16* __restrict__ Kl,
             const __nv_bfloat16* __restrict__ Vh, const __nv_bfloat16* __restrict__ Vl,
             __nv_bfloat16* __restrict__ Oh, __nv_bfloat16* __restrict__ Ol) {
    extern __shared__ char smem[];
    const uint32_t sbase = smem_u32(smem);
    const uint32_t kvbase = sbase + AT_QSZ;

    const int tid  = threadIdx.x;
    const int wid  = tid >> 5;
    const int lane = tid & 31;
    const int qt = (gridDim.x - 1) - blockIdx.x;       // heavy tiles first
    const int h  = blockIdx.y;
    const int b  = blockIdx.z;
    const int bh = b * NHEADS + h;
    const int nkt = 2 * qt + 2;

    const __nv_bfloat16* Qhp = Qh + ((size_t)bh * TSEQ + qt * 128) * DHEAD;
    const __nv_bfloat16* Qlp = Ql + ((size_t)bh * TSEQ + qt * 128) * DHEAD;
    const __nv_bfloat16* Khp = Kh + (size_t)bh * TSEQ * DHEAD;
    const __nv_bfloat16* Klp = Kl + (size_t)bh * TSEQ * DHEAD;
    const __nv_bfloat16* Vhp = Vh + (size_t)bh * DHEAD * TSEQ;
    const __nv_bfloat16* Vlp = Vl + (size_t)bh * DHEAD * TSEQ;

    // ---- stage Q (128 rows x 128 B, swizzled) into the persistent region ----
#pragma unroll
    for (int i = 0; i < 8; i++) {
        int chunk = tid + i * 256;                 // 2048 chunks
        int sel = chunk >> 10, within = chunk & 1023;
        int row = within >> 3, ch = within & 7;
        uint32_t dst = sbase + sel * 16384 + (uint32_t)row * 128 + ((ch ^ (row & 7)) << 4);
        cp16(dst, (sel ? Qlp : Qhp) + (size_t)row * DHEAD + ch * 8);
    }
    cp_commit();

    // ---- prologue: key tiles 0,1 -> stages 0,1 (nkt >= 2 always) ----
    at_load_stage(kvbase + 0 * AT_STAGE, Khp, Klp, Vhp, Vlp, 0, tid);
    at_load_stage(kvbase + 1 * AT_STAGE, Khp, Klp, Vhp, Vlp, 64, tid);

    // Per-lane Q-fragment addressing (persistent smem)
    const int qrow = wid * 16 + (lane & 15);
    const int qsw  = qrow & 7;
    const uint32_t qb = sbase + (uint32_t)qrow * 128;
    const int qch  = lane >> 4;                        // 0..1

    // B-operand per-lane constants
    const int rB0 = (lane & 7) + ((lane >> 4) << 3);   // 0..15
    const int chB = (lane >> 3) & 1;

    float o[8][4];
#pragma unroll
    for (int nb = 0; nb < 8; nb++)
#pragma unroll
        for (int r = 0; r < 4; r++) o[nb][r] = 0.0f;
    float m0 = -INFINITY, m1 = -INFINITY, l0 = 0.0f, l1 = 0.0f;

    const int qrow_lo = qt * 128 + wid * 16;
    const int r0g = qrow_lo + (lane >> 2);
    const int r1g = r0g + 8;

    for (int kt = 0; kt < nkt; kt++) {
        if (kt + 1 < nkt) {
            asm volatile("cp.async.wait_group 1;" ::: "memory");
        } else {
            asm volatile("cp.async.wait_group 0;" ::: "memory");
        }
        __syncthreads();

        const uint32_t st = kvbase + (kt & 1) * AT_STAGE;

        if (kt * 64 <= qrow_lo + 15) {
            // ---- S = Q K^T (hi/lo split; low fragment liveness) ----
            float s[8][4];
#pragma unroll
            for (int nb = 0; nb < 8; nb++)
#pragma unroll
                for (int r = 0; r < 4; r++) s[nb][r] = 0.0f;

#pragma unroll
            for (int kb = 0; kb < 4; kb++) {
                uint32_t qh[4], ql[4];
                const uint32_t qoff = (uint32_t)(((kb * 2 + qch) ^ qsw) << 4);
                LDSM4(qh, qb + qoff);
                LDSM4(ql, qb + 16384 + qoff);
#pragma unroll
                for (int g = 0; g < 4; g++) {
                    const int row = g * 16 + rB0;
                    const uint32_t ba = st + (uint32_t)row * 128
                                      + (uint32_t)(((kb * 2 + chB) ^ (row & 7)) << 4);
                    uint32_t kh[4], kl[4];
                    LDSM4(kh, ba);
                    LDSM4(kl, ba + AT_TILE);
#pragma unroll
                    for (int half = 0; half < 2; half++) {
                        const int nb = 2 * g + half, h2 = half * 2;
                        MMA_BF16(s[nb], qh, kh[h2], kh[h2 + 1]);
                        MMA_BF16(s[nb], qh, kl[h2], kl[h2 + 1]);
                        MMA_BF16(s[nb], ql, kh[h2], kh[h2 + 1]);
                    }
                }
            }

            // ---- causal mask (only needed near diagonal) ----
            if (kt * 64 + 63 > qrow_lo) {
#pragma unroll
                for (int nb = 0; nb < 8; nb++) {
                    int c = kt * 64 + nb * 8 + (lane & 3) * 2;
                    if (c > r0g)     s[nb][0] = -INFINITY;
                    if (c + 1 > r0g) s[nb][1] = -INFINITY;
                    if (c > r1g)     s[nb][2] = -INFINITY;
                    if (c + 1 > r1g) s[nb][3] = -INFINITY;
                }
            }

            // ---- online softmax ----
            float mx0 = -INFINITY, mx1 = -INFINITY;
#pragma unroll
            for (int nb = 0; nb < 8; nb++) {
                mx0 = fmaxf(mx0, fmaxf(s[nb][0], s[nb][1]));
                mx1 = fmaxf(mx1, fmaxf(s[nb][2], s[nb][3]));
            }
            mx0 = fmaxf(mx0, __shfl_xor_sync(0xffffffffu, mx0, 1));
            mx0 = fmaxf(mx0, __shfl_xor_sync(0xffffffffu, mx0, 2));
            mx1 = fmaxf(mx1, __shfl_xor_sync(0xffffffffu, mx1, 1));
            mx1 = fmaxf(mx1, __shfl_xor_sync(0xffffffffu, mx1, 2));

            float mn0 = fmaxf(m0, mx0), mn1 = fmaxf(m1, mx1);
            float c0 = __expf(m0 - mn0), c1 = __expf(m1 - mn1);
            m0 = mn0; m1 = mn1;

            float rs0 = 0.0f, rs1 = 0.0f;
#pragma unroll
            for (int nb = 0; nb < 8; nb++) {
                s[nb][0] = __expf(s[nb][0] - m0); rs0 += s[nb][0];
                s[nb][1] = __expf(s[nb][1] - m0); rs0 += s[nb][1];
                s[nb][2] = __expf(s[nb][2] - m1); rs1 += s[nb][2];
                s[nb][3] = __expf(s[nb][3] - m1); rs1 += s[nb][3];
            }
            rs0 += __shfl_xor_sync(0xffffffffu, rs0, 1);
            rs0 += __shfl_xor_sync(0xffffffffu, rs0, 2);
            rs1 += __shfl_xor_sync(0xffffffffu, rs1, 1);
            rs1 += __shfl_xor_sync(0xffffffffu, rs1, 2);
            l0 = l0 * c0 + rs0;
            l1 = l1 * c1 + rs1;
#pragma unroll
            for (int nb = 0; nb < 8; nb++) {
                o[nb][0] *= c0; o[nb][1] *= c0;
                o[nb][2] *= c1; o[nb][3] *= c1;
            }

            // ---- O += P V  (P converted in-register to A fragments) ----
#pragma unroll
            for (int kbp = 0; kbp < 4; kbp++) {
                uint32_t phi[4], plo[4];
                const int e = 2 * kbp;
                phi[0] = packbf2(s[e][0], s[e][1]);
                phi[1] = packbf2(s[e][2], s[e][3]);
                phi[2] = packbf2(s[e + 1][0], s[e + 1][1]);
                phi[3] = packbf2(s[e + 1][2], s[e + 1][3]);
                plo[0] = packlo2(s[e][0], s[e][1], phi[0]);
                plo[1] = packlo2(s[e][2], s[e][3], phi[1]);
                plo[2] = packlo2(s[e + 1][0], s[e + 1][1], phi[2]);
                plo[3] = packlo2(s[e + 1][2], s[e + 1][3], phi[3]);

#pragma unroll
                for (int g = 0; g < 4; g++) {
                    const int row = g * 16 + rB0;
                    const uint32_t ba = st + 2 * AT_TILE + (uint32_t)row * 128
                                      + (uint32_t)(((kbp * 2 + chB) ^ (row & 7)) << 4);
                    uint32_t vh[4], vl[4];
                    LDSM4(vh, ba);
                    LDSM4(vl, ba + AT_TILE);
#pragma unroll
                    for (int half = 0; half < 2; half++) {
                        const int nbd = 2 * g + half, h2 = half * 2;
                        MMA_BF16(o[nbd], phi, vh[h2], vh[h2 + 1]);
                        MMA_BF16(o[nbd], plo, vh[h2], vh[h2 + 1]);
                        MMA_BF16(o[nbd], phi, vl[h2], vl[h2 + 1]);
                    }
                }
            }
        }

        // WAR guard: all warps done reading stage (kt&1) before reloading it
        __syncthreads();
        if (kt + 2 < nkt)
            at_load_stage(kvbase + (kt & 1) * AT_STAGE, Khp, Klp, Vhp, Vlp,
                          (kt + 2) * 64, tid);
    }

    // ---- epilogue: normalize, split hi/lo, store bf16 pairs ----
    const float inv0 = 1.0f / l0, inv1 = 1.0f / l1;
    const size_t grow0 = (size_t)b * TSEQ + r0g;
    const size_t grow1 = grow0 + 8;
    const int colb = h * DHEAD + (lane & 3) * 2;
#pragma unroll
    for (int nbd = 0; nbd < 8; nbd++) {
        const int col = colb + nbd * 8;
        float f00 = o[nbd][0] * inv0, f01 = o[nbd][1] * inv0;
        float f10 = o[nbd][2] * inv1, f11 = o[nbd][3] * inv1;
        uint32_t h0 = packbf2(f00, f01), l0p = packlo2(f00, f01, h0);
        uint32_t h1 = packbf2(f10, f11), l1p = packlo2(f10, f11, h1);
        *(uint32_t*)(Oh + grow0 * DEMBD + col) = h0;
        *(uint32_t*)(Ol + grow0 * DEMBD + col) = l0p;
        *(uint32_t*)(Oh + grow1 * DEMBD + col) = h1;
        *(uint32_t*)(Ol + grow1 * DEMBD + col) = l1p;
    }
}

// ---------------------------------------------------------------------------
extern "C" void kernel_launch(void* const* d_in, const int* in_sizes, int n_in,
                              void* d_out, int out_size) {
    const float* x  = (const float*)d_in[0];
    const float* W1 = (const float*)d_in[1];
    const float* b1 = (const float*)d_in[2];
    const float* W2 = (const float*)d_in[3];
    const float* b2 = (const float*)d_in[4];
    float* out = (float*)d_out;

    __nv_bfloat16 *A1h, *A1l, *A2h, *A2l, *W1h, *W1l, *W2h, *W2l;
    __nv_bfloat16 *Qh, *Ql, *Kh, *Kl, *Vh, *Vl;
    cudaGetSymbolAddress((void**)&A1h, g_A1hi);
    cudaGetSymbolAddress((void**)&A1l, g_A1lo);
    cudaGetSymbolAddress((void**)&A2h, g_A2hi);
    cudaGetSymbolAddress((void**)&A2l, g_A2lo);
    cudaGetSymbolAddress((void**)&W1h, g_W1Thi);
    cudaGetSymbolAddress((void**)&W1l, g_W1Tlo);
    cudaGetSymbolAddress((void**)&W2h, g_W2Thi);
    cudaGetSymbolAddress((void**)&W2l, g_W2Tlo);
    cudaGetSymbolAddress((void**)&Qh, g_Qhi);
    cudaGetSymbolAddress((void**)&Ql, g_Qlo);
    cudaGetSymbolAddress((void**)&Kh, g_Khi);
    cudaGetSymbolAddress((void**)&Kl, g_Klo);
    cudaGetSymbolAddress((void**)&Vh, g_Vthi);
    cudaGetSymbolAddress((void**)&Vl, g_Vtlo);

    cudaFuncSetAttribute(gemm_bf16_mma, cudaFuncAttributeMaxDynamicSharedMemorySize, GEMM_SMEM);
    cudaFuncSetAttribute(gemm1_qkv,    cudaFuncAttributeMaxDynamicSharedMemorySize, GEMM_SMEM);
    cudaFuncSetAttribute(attn_tc,      cudaFuncAttributeMaxDynamicSharedMemorySize, ATTN_SMEM);

    // 0) input conversions
    {
        int n4 = MROWS * DEMBD / 4;
        split_f32<<<(n4 + 255) / 256, 256>>>(x, A1h, A1l, n4);
        transpose_split<<<dim3(KQV_N / 32, DEMBD / 32), dim3(32, 8)>>>(W1, W1h, W1l, DEMBD, KQV_N);
        transpose_split<<<dim3(DEMBD / 32, DEMBD / 32), dim3(32, 8)>>>(W2, W2h, W2l, DEMBD, DEMBD);
    }
    // 1) kqv = x @ W1 + b1, epilogue writes per-head bf16 hi/lo Q/K/V directly
    gemm1_qkv<<<dim3(KQV_N / 128, MROWS / 128), 256, GEMM_SMEM>>>(
        A1h, A1l, W1h, W1l, b1, Qh, Ql, Kh, Kl, Vh, Vl);
    // 2) causal attention (tensor cores), writes A2 hi/lo directly
    attn_tc<<<dim3(TSEQ / 128, NHEADS, BS), 256, ATTN_SMEM>>>(
        Qh, Ql, Kh, Kl, Vh, Vl, A2h, A2l);
    // 3) out = att @ W2 + b2  (tensor cores)
    gemm_bf16_mma<<<dim3(DEMBD / 128, MROWS / 128), 256, GEMM_SMEM>>>(
        A2h, A2l, W2h, W2l, b2, out, MROWS, DEMBD, DEMBD);
}

// round 15
// speedup vs baseline: 4.0586x; 1.3890x over previous
#include <cuda_runtime.h>
#include <cuda_fp16.h>
#include <math.h>
#include <stdint.h>

// Problem constants
#define BS      2
#define TSEQ    2048
#define DEMBD   1024
#define NHEADS  16
#define DHEAD   64
#define MROWS   (BS * TSEQ)      // 4096
#define KQV_N   (3 * DEMBD)      // 3072
#define BH      (BS * NHEADS)    // 32

// ---------------------------------------------------------------------------
// Scratch (__device__ globals; allocation-free rule)
// ---------------------------------------------------------------------------
__device__ __half g_A1hi[MROWS * DEMBD];
__device__ __half g_A1lo[MROWS * DEMBD];
__device__ __half g_A2hi[MROWS * DEMBD];    // written by attention
__device__ __half g_A2lo[MROWS * DEMBD];
__device__ __half g_W1T[KQV_N * DEMBD];     // W1^T single fp16
__device__ __half g_W2T[DEMBD * DEMBD];     // W2^T single fp16

// Attention operands, per-head layouts — written by GEMM1 epilogue
__device__ __half g_Qhi[BH * TSEQ * DHEAD];  // [bh][t][d]  (UNscaled; hi part)
__device__ __half g_Qlo[BH * TSEQ * DHEAD];
__device__ __half g_K  [BH * TSEQ * DHEAD];  // [bh][t][d]  single fp16
__device__ __half g_Vt [BH * DHEAD * TSEQ];  // [bh][d][t]  single fp16 (transposed)

// ---------------------------------------------------------------------------
// PTX helpers (baseline ISA only)
// ---------------------------------------------------------------------------
__device__ __forceinline__ uint32_t smem_u32(const void* p) {
    uint32_t a;
    asm("{ .reg .u64 t; cvta.to.shared.u64 t, %1; cvt.u32.u64 %0, t; }" : "=r"(a) : "l"(p));
    return a;
}
__device__ __forceinline__ void cp16(uint32_t dst, const void* src) {
    asm volatile("cp.async.cg.shared.global [%0], [%1], 16;"
                 :: "r"(dst), "l"(__cvta_generic_to_global(src)));
}
__device__ __forceinline__ void cp_commit() { asm volatile("cp.async.commit_group;" ::: "memory"); }

#define LDSM4(r, addr) \
    asm volatile("ldmatrix.sync.aligned.m8n8.x4.shared.b16 {%0,%1,%2,%3}, [%4];" \
        : "=r"((r)[0]), "=r"((r)[1]), "=r"((r)[2]), "=r"((r)[3]) : "r"(addr))

#define MMA_F16(d, a, b0, b1) \
    asm volatile("mma.sync.aligned.m16n8k16.row.col.f32.f16.f16.f32 " \
        "{%0,%1,%2,%3}, {%4,%5,%6,%7}, {%8,%9}, {%0,%1,%2,%3};" \
        : "+f"((d)[0]), "+f"((d)[1]), "+f"((d)[2]), "+f"((d)[3]) \
        : "r"((a)[0]), "r"((a)[1]), "r"((a)[2]), "r"((a)[3]), "r"(b0), "r"(b1))

// pack two fp32 into f16x2: low half <- lo, high half <- hi
__device__ __forceinline__ uint32_t packh2(float lo, float hi) {
    uint32_t r;
    asm("cvt.rn.f16x2.f32 %0, %1, %2;" : "=r"(r) : "f"(hi), "f"(lo));
    return r;
}
// residual (lo-part) pack given the hi-pack
__device__ __forceinline__ uint32_t packloh2(float lo, float hi, uint32_t hp) {
    __half2 hv = *reinterpret_cast<__half2*>(&hp);
    float2 f = __half22float2(hv);
    return packh2(lo - f.x, hi - f.y);
}

// ---------------------------------------------------------------------------
// fp32 -> fp16 hi/lo split (elementwise, float4)  [x -> A1]
// ---------------------------------------------------------------------------
__global__ void split_f32(const float* __restrict__ in, __half* __restrict__ hi,
                          __half* __restrict__ lo, int n4) {
    int i = blockIdx.x * blockDim.x + threadIdx.x;
    if (i >= n4) return;
    float4 v = ((const float4*)in)[i];
    uint32_t h0 = packh2(v.x, v.y), h1 = packh2(v.z, v.w);
    uint32_t l0 = packloh2(v.x, v.y, h0), l1 = packloh2(v.z, v.w, h1);
    ((uint32_t*)hi)[i * 2 + 0] = h0;
    ((uint32_t*)hi)[i * 2 + 1] = h1;
    ((uint32_t*)lo)[i * 2 + 0] = l0;
    ((uint32_t*)lo)[i * 2 + 1] = l1;
}

// ---------------------------------------------------------------------------
// W[K][N] fp32 -> W^T[N][K] single fp16 (tiled transpose)
// ---------------------------------------------------------------------------
__global__ void transpose_h(const float* __restrict__ W, __half* __restrict__ hT,
                            int K, int N) {
    __shared__ float t[32][33];
    int n = blockIdx.x * 32 + threadIdx.x;
    int k0 = blockIdx.y * 32;
#pragma unroll
    for (int i = 0; i < 32; i += 8)
        t[threadIdx.y + i][threadIdx.x] = W[(size_t)(k0 + threadIdx.y + i) * N + n];
    __syncthreads();
    int kk = k0 + threadIdx.x;
#pragma unroll
    for (int i = 0; i < 32; i += 8) {
        int nn = blockIdx.x * 32 + threadIdx.y + i;
        hT[(size_t)nn * K + kk] = __float2half(t[threadIdx.x][threadIdx.y + i]);
    }
}

// ---------------------------------------------------------------------------
// GEMM tiling: 128x128 CTA tile, BK=32 slabs, xor-swizzled smem (64B rows),
// 3 tiles/stage (Ah, Al, B-single), 3-stage cp.async pipeline.
// ---------------------------------------------------------------------------
#define BK        32
#define TILE_B    8192                 // 128 rows x 64 B (swizzled, no pad)
#define STAGE_B   (3 * TILE_B)         // Ah, Al, B = 24 KB
#define GEMM_SMEM (3 * STAGE_B)        // 72 KB -> 2 CTAs/SM

__device__ __forceinline__ uint32_t swz16(int row, int ch) {
    return (uint32_t)(row * 64 + ((ch ^ ((row & 6) >> 1)) << 4));
}

__device__ __forceinline__ void load_stage(uint32_t st, const __half* Ah0,
                                           const __half* Al0, const __half* B0,
                                           int k0, int K, int tid) {
#pragma unroll
    for (int i = 0; i < 6; i++) {
        int q = tid + i * 256;               // 1536 chunks (3 tiles x 512)
        int tile = q >> 9, w = q & 511;
        int row = w >> 2, c16 = w & 3;
        const __half* sp = (tile == 0) ? Ah0 : (tile == 1) ? Al0 : B0;
        cp16(st + tile * TILE_B + swz16(row, c16), sp + (size_t)(k0 + 0) + (size_t)row * K + c16 * 8);
    }
    cp_commit();
}

// Mainloop shared by both GEMM kernels. Ends with one __syncthreads().
__device__ __forceinline__ void gemm_mainloop(
    uint32_t sbase, const __half* Ah0, const __half* Al0, const __half* B0,
    int K, int tid, int wm, int wn, int lane, float acc[4][4][4]) {

    const int NSLAB = K / BK;
    const int rowA = wm + (lane & 15);
    const int chA  = lane >> 4;
    const int rowB = wn + (lane & 7) + ((lane >> 4) << 3);
    const int chB  = (lane >> 3) & 1;
    const uint32_t aRow = (uint32_t)rowA * 64;
    const uint32_t bRow = (uint32_t)rowB * 64;
    const int aSwz = (rowA & 6) >> 1;
    const int bSwz = (rowB & 6) >> 1;

    load_stage(sbase + 0 * STAGE_B, Ah0, Al0, B0, 0, K, tid);
    load_stage(sbase + 1 * STAGE_B, Ah0, Al0, B0, BK, K, tid);

    for (int s = 0; s < NSLAB; s++) {
        if (s + 1 < NSLAB) {
            asm volatile("cp.async.wait_group 1;" ::: "memory");
        } else {
            asm volatile("cp.async.wait_group 0;" ::: "memory");
        }
        __syncthreads();
        if (s + 2 < NSLAB)
            load_stage(sbase + ((s + 2) % 3) * STAGE_B, Ah0, Al0, B0, (s + 2) * BK, K, tid);

        const uint32_t st = sbase + (s % 3) * STAGE_B;
#pragma unroll
        for (int kk = 0; kk < BK; kk += 16) {
            const int kc = kk >> 3;                     // 0 or 2
            uint32_t bf[2][4];
#pragma unroll
            for (int g = 0; g < 2; g++) {
                const uint32_t ba = st + 2 * TILE_B + bRow + (uint32_t)(g * 1024)
                                  + (uint32_t)(((kc | chB) ^ bSwz) << 4);
                LDSM4(bf[g], ba);
            }
#pragma unroll
            for (int mb = 0; mb < 4; mb++) {
                const uint32_t aa = st + aRow + (uint32_t)(mb * 1024)
                                  + (uint32_t)(((kc | chA) ^ aSwz) << 4);
                uint32_t ah[4], al[4];
                LDSM4(ah, aa + 0 * TILE_B);
                LDSM4(al, aa + 1 * TILE_B);
#pragma unroll
                for (int nb = 0; nb < 4; nb++) {
                    const int g = nb >> 1, h2 = (nb & 1) * 2;
                    MMA_F16(acc[mb][nb], ah, bf[g][h2], bf[g][h2 + 1]);
                    MMA_F16(acc[mb][nb], al, bf[g][h2], bf[g][h2 + 1]);
                }
            }
        }
    }
    __syncthreads();   // epilogues may reuse smem
}

// ---------------------------------------------------------------------------
// GEMM2: generic fp32-output GEMM + bias (att @ W2 + b2 -> out)
// ---------------------------------------------------------------------------
__global__ __launch_bounds__(256, 2)
void gemm_f16_mma(const __half* __restrict__ Ah, const __half* __restrict__ Al,
                  const __half* __restrict__ B,
                  const float* __restrict__ bias, float* __restrict__ C,
                  int M, int N, int K) {
    extern __shared__ char smem[];
    const uint32_t sbase = smem_u32(smem);

    const int tid  = threadIdx.x;
    const int wid  = tid >> 5;
    const int lane = tid & 31;
    const int m0 = blockIdx.y * 128;
    const int n0 = blockIdx.x * 128;
    const int wm = (wid & 1) * 64;
    const int wn = (wid >> 1) * 32;

    float acc[4][4][4];
#pragma unroll
    for (int mb = 0; mb < 4; mb++)
#pragma unroll
        for (int nb = 0; nb < 4; nb++)
#pragma unroll
            for (int r = 0; r < 4; r++) acc[mb][nb][r] = 0.0f;

    gemm_mainloop(sbase, Ah + (size_t)m0 * K, Al + (size_t)m0 * K,
                  B + (size_t)n0 * K, K, tid, wm, wn, lane, acc);

    const int rBase = m0 + wm + (lane >> 2);
    const int cBase = n0 + wn + (lane & 3) * 2;
#pragma unroll
    for (int mb = 0; mb < 4; mb++) {
#pragma unroll
        for (int nb = 0; nb < 4; nb++) {
            const int col = cBase + nb * 8;
            const float bx = __ldg(bias + col);
            const float by = __ldg(bias + col + 1);
            float* p0 = C + (size_t)(rBase + mb * 16) * N + col;
            float* p1 = C + (size_t)(rBase + mb * 16 + 8) * N + col;
            *(float2*)p0 = make_float2(acc[mb][nb][0] + bx, acc[mb][nb][1] + by);
            *(float2*)p1 = make_float2(acc[mb][nb][2] + bx, acc[mb][nb][3] + by);
        }
    }
}

// ---------------------------------------------------------------------------
// GEMM1 with fused QKV epilogue: x @ W1 + b1 -> per-head attention operands.
// K part: single fp16. Q part: fp16 hi/lo (UNscaled). V: single fp16, transposed.
// ---------------------------------------------------------------------------
#define VP 132   // fp32 smem pitch for V transpose staging (128 + 4 pad)

__global__ __launch_bounds__(256, 2)
void gemm1_qkv(const __half* __restrict__ Ah, const __half* __restrict__ Al,
               const __half* __restrict__ B,
               const float* __restrict__ bias,
               __half* __restrict__ Qh, __half* __restrict__ Ql,
               __half* __restrict__ Kp, __half* __restrict__ Vp) {
    extern __shared__ char smem[];
    const uint32_t sbase = smem_u32(smem);
    const int K = DEMBD;

    const int tid  = threadIdx.x;
    const int wid  = tid >> 5;
    const int lane = tid & 31;
    const int m0 = blockIdx.y * 128;
    const int n0 = blockIdx.x * 128;
    const int wm = (wid & 1) * 64;
    const int wn = (wid >> 1) * 32;

    float acc[4][4][4];
#pragma unroll
    for (int mb = 0; mb < 4; mb++)
#pragma unroll
        for (int nb = 0; nb < 4; nb++)
#pragma unroll
            for (int r = 0; r < 4; r++) acc[mb][nb][r] = 0.0f;

    gemm_mainloop(sbase, Ah + (size_t)m0 * K, Al + (size_t)m0 * K,
                  B + (size_t)n0 * K, K, tid, wm, wn, lane, acc);

    const int part = n0 >> 10;              // 0 = K, 1 = Q, 2 = V
    const int b    = m0 >> 11;              // batch
    const int t0   = m0 & 2047;             // t of tile row 0
    const int cp0  = n0 & 1023;             // col offset within part

    const int rLoc = wm + (lane >> 2);
    const int cLoc = wn + (lane & 3) * 2;

    if (part == 0) {
        // ---- K: single fp16 [bh][t][64] ----
#pragma unroll
        for (int mb = 0; mb < 4; mb++) {
#pragma unroll
            for (int nb = 0; nb < 4; nb++) {
                const int c = cLoc + nb * 8;
                const int cpart = cp0 + c;
                const int h = cpart >> 6, d = cpart & 63;
                const float bx = __ldg(bias + n0 + c);
                const float by = __ldg(bias + n0 + c + 1);
                const size_t base = ((size_t)(b * NHEADS + h) * TSEQ);
                const int tA = t0 + rLoc + mb * 16, tB = tA + 8;
                uint32_t h0 = packh2(acc[mb][nb][0] + bx, acc[mb][nb][1] + by);
                uint32_t h1 = packh2(acc[mb][nb][2] + bx, acc[mb][nb][3] + by);
                *(uint32_t*)(Kp + (base + tA) * DHEAD + d) = h0;
                *(uint32_t*)(Kp + (base + tB) * DHEAD + d) = h1;
            }
        }
    } else if (part == 1) {
        // ---- Q: fp16 hi/lo [bh][t][64] (no prescale) ----
#pragma unroll
        for (int mb = 0; mb < 4; mb++) {
#pragma unroll
            for (int nb = 0; nb < 4; nb++) {
                const int c = cLoc + nb * 8;
                const int cpart = cp0 + c;
                const int h = cpart >> 6, d = cpart & 63;
                const float bx = __ldg(bias + n0 + c);
                const float by = __ldg(bias + n0 + c + 1);
                float f0 = acc[mb][nb][0] + bx, f1 = acc[mb][nb][1] + by;
                float f2 = acc[mb][nb][2] + bx, f3 = acc[mb][nb][3] + by;
                const size_t base = ((size_t)(b * NHEADS + h) * TSEQ);
                const int tA = t0 + rLoc + mb * 16, tB = tA + 8;
                uint32_t h0 = packh2(f0, f1), l0 = packloh2(f0, f1, h0);
                uint32_t h1 = packh2(f2, f3), l1 = packloh2(f2, f3, h1);
                *(uint32_t*)(Qh + (base + tA) * DHEAD + d) = h0;
                *(uint32_t*)(Ql + (base + tA) * DHEAD + d) = l0;
                *(uint32_t*)(Qh + (base + tB) * DHEAD + d) = h1;
                *(uint32_t*)(Ql + (base + tB) * DHEAD + d) = l1;
            }
        }
    } else {
        // ---- V: stage fp32 [col][row] in smem, write [bh][d][t] single fp16 ----
        float* sv = (float*)smem;
#pragma unroll
        for (int mb = 0; mb < 4; mb++) {
#pragma unroll
            for (int nb = 0; nb < 4; nb++) {
                const int c = cLoc + nb * 8;
                const float bx = __ldg(bias + n0 + c);
                const float by = __ldg(bias + n0 + c + 1);
                const int rA = rLoc + mb * 16, rB = rA + 8;
                sv[(c + 0) * VP + rA] = acc[mb][nb][0] + bx;
                sv[(c + 1) * VP + rA] = acc[mb][nb][1] + by;
                sv[(c + 0) * VP + rB] = acc[mb][nb][2] + bx;
                sv[(c + 1) * VP + rB] = acc[mb][nb][3] + by;
            }
        }
        __syncthreads();
#pragma unroll
        for (int i = 0; i < 16; i++) {
            const int c = (tid >> 5) + i * 8;
            const int cpart = cp0 + c;
            const int h = cpart >> 6, d = cpart & 63;
            float4 v = *(float4*)&sv[c * VP + lane * 4];
            uint32_t hA = packh2(v.x, v.y), hB = packh2(v.z, v.w);
            const size_t dst =
                ((size_t)(b * NHEADS + h) * DHEAD + d) * TSEQ + t0 + lane * 4;
            *(uint2*)(Vp + dst) = make_uint2(hA, hB);
        }
    }
}

// ---------------------------------------------------------------------------
// Tensor-core causal flash attention (fp16; Q split hi/lo, K/V single).
// Persistent Q (32 KB) + 3-stage K/V pipeline (3 x 16 KB) = 80 KB, 2 CTAs/SM.
// S scaled by 0.125 post-MMA.
// ---------------------------------------------------------------------------
#define AT_TILE   8192                    // 64 rows x 128 B, swizzled
#define AT_STAGE  (2 * AT_TILE)           // K, V = 16 KB
#define AT_QSZ    32768                   // Q hi (16 KB) + Q lo (16 KB)
#define ATTN_SMEM (AT_QSZ + 3 * AT_STAGE) // 81920 B -> 2 CTAs/SM

__device__ __forceinline__ uint32_t aswz(int row, int ch) {
    return (uint32_t)(row * 128 + ((ch ^ (row & 7)) << 4));
}

__device__ __forceinline__ void at_load_stage(
    uint32_t st, const __half* Kp, const __half* Vp, int koff, int tid) {
#pragma unroll
    for (int i = 0; i < 4; i++) {
        int chunk = tid + i * 256;                 // 1024 chunks
        int tile = chunk >> 9, w = chunk & 511;
        int row = w >> 3, ch = w & 7;
        uint32_t dst = st + tile * AT_TILE + aswz(row, ch);
        if (tile == 0) cp16(dst, Kp + (size_t)(koff + row) * DHEAD + ch * 8);
        else           cp16(dst, Vp + (size_t)row * TSEQ + koff + ch * 8);
    }
    cp_commit();
}

__global__ __launch_bounds__(256, 2)
void attn_tc(const __half* __restrict__ Qh, const __half* __restrict__ Ql,
             const __half* __restrict__ Kg, const __half* __restrict__ Vg,
             __half* __restrict__ Oh, __half* __restrict__ Ol) {
    extern __shared__ char smem[];
    const uint32_t sbase = smem_u32(smem);
    const uint32_t kvbase = sbase + AT_QSZ;

    const int tid  = threadIdx.x;
    const int wid  = tid >> 5;
    const int lane = tid & 31;
    const int qt = (gridDim.x - 1) - blockIdx.x;       // heavy tiles first
    const int h  = blockIdx.y;
    const int b  = blockIdx.z;
    const int bh = b * NHEADS + h;
    const int nkt = 2 * qt + 2;

    const __half* Qhp = Qh + ((size_t)bh * TSEQ + qt * 128) * DHEAD;
    const __half* Qlp = Ql + ((size_t)bh * TSEQ + qt * 128) * DHEAD;
    const __half* Kp  = Kg + (size_t)bh * TSEQ * DHEAD;
    const __half* Vp  = Vg + (size_t)bh * DHEAD * TSEQ;

    // ---- stage Q (hi+lo, 128 rows x 128 B each, swizzled) ----
#pragma unroll
    for (int i = 0; i < 8; i++) {
        int chunk = tid + i * 256;                 // 2048 chunks
        int sel = chunk >> 10, w = chunk & 1023;
        int row = w >> 3, ch = w & 7;
        uint32_t dst = sbase + sel * 16384 + (uint32_t)row * 128 + ((ch ^ (row & 7)) << 4);
        cp16(dst, (sel ? Qlp : Qhp) + (size_t)row * DHEAD + ch * 8);
    }
    cp_commit();

    // ---- prologue: key tiles 0,1 -> stages 0,1 ----
    at_load_stage(kvbase + 0 * AT_STAGE, Kp, Vp, 0, tid);
    at_load_stage(kvbase + 1 * AT_STAGE, Kp, Vp, 64, tid);

    // Per-lane Q-fragment addressing (persistent smem)
    const int qrow = wid * 16 + (lane & 15);
    const int qsw  = qrow & 7;
    const uint32_t qb = sbase + (uint32_t)qrow * 128;
    const int qch  = lane >> 4;

    // B-operand per-lane constants
    const int rB0 = (lane & 7) + ((lane >> 4) << 3);
    const int chB = (lane >> 3) & 1;

    float o[8][4];
#pragma unroll
    for (int nb = 0; nb < 8; nb++)
#pragma unroll
        for (int r = 0; r < 4; r++) o[nb][r] = 0.0f;
    float m0 = -INFINITY, m1 = -INFINITY, l0 = 0.0f, l1 = 0.0f;

    const int qrow_lo = qt * 128 + wid * 16;
    const int r0g = qrow_lo + (lane >> 2);
    const int r1g = r0g + 8;

    for (int kt = 0; kt < nkt; kt++) {
        if (kt + 1 < nkt) {
            asm volatile("cp.async.wait_group 1;" ::: "memory");
        } else {
            asm volatile("cp.async.wait_group 0;" ::: "memory");
        }
        __syncthreads();
        if (kt + 2 < nkt)
            at_load_stage(kvbase + ((kt + 2) % 3) * AT_STAGE, Kp, Vp, (kt + 2) * 64, tid);

        if (kt * 64 <= qrow_lo + 15) {
            const uint32_t st = kvbase + (kt % 3) * AT_STAGE;

            // ---- S = Q K^T (A split, B single: 2 MMAs/product) ----
            float s[8][4];
#pragma unroll
            for (int nb = 0; nb < 8; nb++)
#pragma unroll
                for (int r = 0; r < 4; r++) s[nb][r] = 0.0f;

#pragma unroll
            for (int kb = 0; kb < 4; kb++) {
                uint32_t qhf[4], qlf[4];
                const uint32_t qoff = (uint32_t)(((kb * 2 + qch) ^ qsw) << 4);
                LDSM4(qhf, qb + qoff);
                LDSM4(qlf, qb + 16384 + qoff);
#pragma unroll
                for (int g = 0; g < 4; g++) {
                    const int row = g * 16 + rB0;
                    const uint32_t ba = st + (uint32_t)row * 128
                                      + (uint32_t)(((kb * 2 + chB) ^ (row & 7)) << 4);
                    uint32_t kf[4];
                    LDSM4(kf, ba);
#pragma unroll
                    for (int half = 0; half < 2; half++) {
                        const int nb = 2 * g + half, h2 = half * 2;
                        MMA_F16(s[nb], qhf, kf[h2], kf[h2 + 1]);
                        MMA_F16(s[nb], qlf, kf[h2], kf[h2 + 1]);
                    }
                }
            }

            // ---- scale (post-MMA) + causal mask ----
#pragma unroll
            for (int nb = 0; nb < 8; nb++)
#pragma unroll
                for (int r = 0; r < 4; r++) s[nb][r] *= 0.125f;

            if (kt * 64 + 63 > qrow_lo) {
#pragma unroll
                for (int nb = 0; nb < 8; nb++) {
                    int c = kt * 64 + nb * 8 + (lane & 3) * 2;
                    if (c > r0g)     s[nb][0] = -INFINITY;
                    if (c + 1 > r0g) s[nb][1] = -INFINITY;
                    if (c > r1g)     s[nb][2] = -INFINITY;
                    if (c + 1 > r1g) s[nb][3] = -INFINITY;
                }
            }

            // ---- online softmax ----
            float mx0 = -INFINITY, mx1 = -INFINITY;
#pragma unroll
            for (int nb = 0; nb < 8; nb++) {
                mx0 = fmaxf(mx0, fmaxf(s[nb][0], s[nb][1]));
                mx1 = fmaxf(mx1, fmaxf(s[nb][2], s[nb][3]));
            }
            mx0 = fmaxf(mx0, __shfl_xor_sync(0xffffffffu, mx0, 1));
            mx0 = fmaxf(mx0, __shfl_xor_sync(0xffffffffu, mx0, 2));
            mx1 = fmaxf(mx1, __shfl_xor_sync(0xffffffffu, mx1, 1));
            mx1 = fmaxf(mx1, __shfl_xor_sync(0xffffffffu, mx1, 2));

            float mn0 = fmaxf(m0, mx0), mn1 = fmaxf(m1, mx1);
            float c0 = __expf(m0 - mn0), c1 = __expf(m1 - mn1);
            m0 = mn0; m1 = mn1;

            float rs0 = 0.0f, rs1 = 0.0f;
#pragma unroll
            for (int nb = 0; nb < 8; nb++) {
                s[nb][0] = __expf(s[nb][0] - m0); rs0 += s[nb][0];
                s[nb][1] = __expf(s[nb][1] - m0); rs0 += s[nb][1];
                s[nb][2] = __expf(s[nb][2] - m1); rs1 += s[nb][2];
                s[nb][3] = __expf(s[nb][3] - m1); rs1 += s[nb][3];
            }
            rs0 += __shfl_xor_sync(0xffffffffu, rs0, 1);
            rs0 += __shfl_xor_sync(0xffffffffu, rs0, 2);
            rs1 += __shfl_xor_sync(0xffffffffu, rs1, 1);
            rs1 += __shfl_xor_sync(0xffffffffu, rs1, 2);
            l0 = l0 * c0 + rs0;
            l1 = l1 * c1 + rs1;
#pragma unroll
            for (int nb = 0; nb < 8; nb++) {
                o[nb][0] *= c0; o[nb][1] *= c0;
                o[nb][2] *= c1; o[nb][3] *= c1;
            }

            // ---- O += P V  (P split in-register; V single) ----
#pragma unroll
            for (int kbp = 0; kbp < 4; kbp++) {
                uint32_t phi[4], plo[4];
                const int e = 2 * kbp;
                phi[0] = packh2(s[e][0], s[e][1]);
                phi[1] = packh2(s[e][2], s[e][3]);
                phi[2] = packh2(s[e + 1][0], s[e + 1][1]);
                phi[3] = packh2(s[e + 1][2], s[e + 1][3]);
                plo[0] = packloh2(s[e][0], s[e][1], phi[0]);
                plo[1] = packloh2(s[e][2], s[e][3], phi[1]);
                plo[2] = packloh2(s[e + 1][0], s[e + 1][1], phi[2]);
                plo[3] = packloh2(s[e + 1][2], s[e + 1][3], phi[3]);

#pragma unroll
                for (int g = 0; g < 4; g++) {
                    const int row = g * 16 + rB0;
                    const uint32_t ba = st + AT_TILE + (uint32_t)row * 128
                                      + (uint32_t)(((kbp * 2 + chB) ^ (row & 7)) << 4);
                    uint32_t vf[4];
                    LDSM4(vf, ba);
#pragma unroll
                    for (int half = 0; half < 2; half++) {
                        const int nbd = 2 * g + half, h2 = half * 2;
                        MMA_F16(o[nbd], phi, vf[h2], vf[h2 + 1]);
                        MMA_F16(o[nbd], plo, vf[h2], vf[h2 + 1]);
                    }
                }
            }
        }
    }

    // ---- epilogue: normalize, split hi/lo, store fp16 pairs ----
    const float inv0 = 1.0f / l0, inv1 = 1.0f / l1;
    const size_t grow0 = (size_t)b * TSEQ + r0g;
    const size_t grow1 = grow0 + 8;
    const int colb = h * DHEAD + (lane & 3) * 2;
#pragma unroll
    for (int nbd = 0; nbd < 8; nbd++) {
        const int col = colb + nbd * 8;
        float f00 = o[nbd][0] * inv0, f01 = o[nbd][1] * inv0;
        float f10 = o[nbd][2] * inv1, f11 = o[nbd][3] * inv1;
        uint32_t h0 = packh2(f00, f01), l0p = packloh2(f00, f01, h0);
        uint32_t h1 = packh2(f10, f11), l1p = packloh2(f10, f11, h1);
        *(uint32_t*)(Oh + grow0 * DEMBD + col) = h0;
        *(uint32_t*)(Ol + grow0 * DEMBD + col) = l0p;
        *(uint32_t*)(Oh + grow1 * DEMBD + col) = h1;
        *(uint32_t*)(Ol + grow1 * DEMBD + col) = l1p;
    }
}

// ---------------------------------------------------------------------------
extern "C" void kernel_launch(void* const* d_in, const int* in_sizes, int n_in,
                              void* d_out, int out_size) {
    const float* x  = (const float*)d_in[0];
    const float* W1 = (const float*)d_in[1];
    const float* b1 = (const float*)d_in[2];
    const float* W2 = (const float*)d_in[3];
    const float* b2 = (const float*)d_in[4];
    float* out = (float*)d_out;

    __half *A1h, *A1l, *A2h, *A2l, *W1T, *W2T, *Qh, *Ql, *Kp, *Vp;
    cudaGetSymbolAddress((void**)&A1h, g_A1hi);
    cudaGetSymbolAddress((void**)&A1l, g_A1lo);
    cudaGetSymbolAddress((void**)&A2h, g_A2hi);
    cudaGetSymbolAddress((void**)&A2l, g_A2lo);
    cudaGetSymbolAddress((void**)&W1T, g_W1T);
    cudaGetSymbolAddress((void**)&W2T, g_W2T);
    cudaGetSymbolAddress((void**)&Qh, g_Qhi);
    cudaGetSymbolAddress((void**)&Ql, g_Qlo);
    cudaGetSymbolAddress((void**)&Kp, g_K);
    cudaGetSymbolAddress((void**)&Vp, g_Vt);

    cudaFuncSetAttribute(gemm_f16_mma, cudaFuncAttributeMaxDynamicSharedMemorySize, GEMM_SMEM);
    cudaFuncSetAttribute(gemm1_qkv,   cudaFuncAttributeMaxDynamicSharedMemorySize, GEMM_SMEM);
    cudaFuncSetAttribute(attn_tc,     cudaFuncAttributeMaxDynamicSharedMemorySize, ATTN_SMEM);

    // 0) input conversions
    {
        int n4 = MROWS * DEMBD / 4;
        split_f32<<<(n4 + 255) / 256, 256>>>(x, A1h, A1l, n4);
        transpose_h<<<dim3(KQV_N / 32, DEMBD / 32), dim3(32, 8)>>>(W1, W1T, DEMBD, KQV_N);
        transpose_h<<<dim3(DEMBD / 32, DEMBD / 32), dim3(32, 8)>>>(W2, W2T, DEMBD, DEMBD);
    }
    // 1) kqv = x @ W1 + b1, epilogue writes per-head Q(hi/lo) / K / V directly
    gemm1_qkv<<<dim3(KQV_N / 128, MROWS / 128), 256, GEMM_SMEM>>>(
        A1h, A1l, W1T, b1, Qh, Ql, Kp, Vp);
    // 2) causal attention (tensor cores), writes A2 hi/lo directly
    attn_tc<<<dim3(TSEQ / 128, NHEADS, BS), 256, ATTN_SMEM>>>(
        Qh, Ql, Kp, Vp, A2h, A2l);
    // 3) out = att @ W2 + b2  (tensor cores)
    gemm_f16_mma<<<dim3(DEMBD / 128, MROWS / 128), 256, GEMM_SMEM>>>(
        A2h, A2l, W2T, b2, out, MROWS, DEMBD, DEMBD);
}